// round 1
// baseline (speedup 1.0000x reference)
#include <cuda_runtime.h>
#include <cstdint>
#include <math.h>

// ---------------------------------------------------------------------------
// Swin Transformer 3D block, B200 baseline (fp32, FFMA)
//   B=2, D=16, H=112, W=112, C=96, WS=(2,7,7), N=98, HEADS=3, HEAD_DIM=32
//   windows: 2048/batch, B_=4096, nW=2048, M (tokens) = 401408
// ---------------------------------------------------------------------------

#define NTOK   401408          // total tokens = 4096*98 = 2*16*112*112
#define CDIM   96
#define NWIN   4096
#define NW_PB  2048            // windows per batch (mask count)
#define NTOKW  98              // tokens per window
#define HEADS  3
#define HDIM   32
#define SCALE  0.17677669529663687f   // 32^-0.5
#define HID    384

// ---------------- scratch (device globals; no runtime allocation) ----------
__device__ float g_xw  [(size_t)NTOK * CDIM];   // LN1+shift+windowed x ; later: proj output
__device__ float g_qkv [(size_t)NTOK * 288];    // qkv
__device__ float g_attn[(size_t)NTOK * CDIM];   // attention output ; later: LN2 output
__device__ float g_xres[(size_t)NTOK * CDIM];   // x + attn residual
__device__ float g_h   [(size_t)NTOK * HID];    // MLP hidden
__device__ float g_rpb [HEADS * NTOKW * NTOKW]; // expanded relative position bias

// ---------------------------------------------------------------------------
// K0: expand relative-position-bias table -> (3, 98, 98)
// ---------------------------------------------------------------------------
__global__ void rpb_precompute(const float* __restrict__ table) {
    int idx = blockIdx.x * 256 + threadIdx.x;
    if (idx >= HEADS * NTOKW * NTOKW) return;
    int h = idx / (NTOKW * NTOKW);
    int r = idx % (NTOKW * NTOKW);
    int i = r / NTOKW, j = r % NTOKW;
    int zdi = i / 49, zhi = (i / 7) % 7, zwi = i % 7;
    int zdj = j / 49, zhj = (j / 7) % 7, zwj = j % 7;
    int ridx = (zdi - zdj + 1) * 169 + (zhi - zhj + 6) * 13 + (zwi - zwj + 6);
    g_rpb[idx] = table[ridx * 3 + h];
}

// ---------------------------------------------------------------------------
// K1: LN1 + cyclic shift + window partition.  One warp per token.
//     grid: NTOK/4 blocks of 128 threads (4 warps)  -> exact
// ---------------------------------------------------------------------------
__global__ void ln1_shift_win(const float* __restrict__ x,
                              const float* __restrict__ g,
                              const float* __restrict__ b) {
    int t    = blockIdx.x * 4 + (threadIdx.x >> 5);
    int lane = threadIdx.x & 31;
    int win = t / NTOKW, n = t % NTOKW;
    int bb  = win >> 11;
    int rem = win & 2047;
    int wd = rem >> 8, wh = (rem >> 4) & 15, ww = rem & 15;
    int zd = n / 49, r2 = n % 49, zh = r2 / 7, zw = r2 % 7;
    int sd = (wd * 2 + zd + 1) & 15;                 // roll(-1) : src = (dst+1)%16
    int sh = wh * 7 + zh + 3; if (sh >= 112) sh -= 112;
    int sw = ww * 7 + zw + 3; if (sw >= 112) sw -= 112;
    const float* px = x + ((((size_t)bb * 16 + sd) * 112 + sh) * 112 + sw) * CDIM;
    float v0 = px[lane], v1 = px[lane + 32], v2 = px[lane + 64];
    float s  = v0 + v1 + v2;
    float ss = v0 * v0 + v1 * v1 + v2 * v2;
    #pragma unroll
    for (int o = 16; o; o >>= 1) {
        s  += __shfl_xor_sync(0xFFFFFFFFu, s, o);
        ss += __shfl_xor_sync(0xFFFFFFFFu, ss, o);
    }
    float mu   = s * (1.0f / 96.0f);
    float var  = ss * (1.0f / 96.0f) - mu * mu;
    float rstd = rsqrtf(var + 1e-5f);
    float* po = g_xw + (size_t)t * CDIM;
    po[lane]      = (v0 - mu) * rstd * g[lane]      + b[lane];
    po[lane + 32] = (v1 - mu) * rstd * g[lane + 32] + b[lane + 32];
    po[lane + 64] = (v2 - mu) * rstd * g[lane + 64] + b[lane + 64];
}

// ---------------------------------------------------------------------------
// Generic SGEMM:  C[m,n] = sum_k A[m,k] * B[n,k] (+bias[n]) (+gelu) (+res)
//   A: (M,K) row-major, B: (N,K) row-major (i.e. computing A @ B^T)
//   BM=64, BK=16, TM=4.  BN/TN template so N=96/288 (48,3) and N=384 (64,4)
//   divide exactly — no bounds checks anywhere.
//   EPI: 0 = bias, 1 = bias+gelu(exact), 2 = bias + res[m*N+n]
// ---------------------------------------------------------------------------
template<int BN, int TN, int EPI>
__global__ __launch_bounds__(256)
void sgemm_kernel(const float* __restrict__ A, const float* __restrict__ B,
                  const float* __restrict__ bias, const float* __restrict__ res,
                  float* __restrict__ C, int M, int N, int K) {
    constexpr int BM = 64, BK = 16, TM = 4;
    constexpr int APAD = 4, BPAD = 4;
    __shared__ float As[BK][BM + APAD];
    __shared__ float Bs[BK][BN + BPAD];
    int tid = threadIdx.x;
    int tx = tid % (BN / TN);          // 16
    int ty = tid / (BN / TN);          // 16
    int m0 = blockIdx.y * BM;
    int n0 = blockIdx.x * BN;

    float acc[TM][TN];
    #pragma unroll
    for (int i = 0; i < TM; i++)
        #pragma unroll
        for (int j = 0; j < TN; j++) acc[i][j] = 0.0f;

    for (int k0 = 0; k0 < K; k0 += BK) {
        __syncthreads();
        {   // A tile: 64x16, float4 along K, transposed into As[k][m]
            int r = tid >> 2;
            int c = (tid & 3) * 4;
            float4 av = *(const float4*)&A[(size_t)(m0 + r) * K + k0 + c];
            As[c + 0][r] = av.x; As[c + 1][r] = av.y;
            As[c + 2][r] = av.z; As[c + 3][r] = av.w;
        }
        #pragma unroll
        for (int idx = tid; idx < BN * BK; idx += 256) {
            int n = idx / BK, kk = idx % BK;
            Bs[kk][n] = B[(size_t)(n0 + n) * K + k0 + kk];
        }
        __syncthreads();
        #pragma unroll
        for (int kk = 0; kk < BK; kk++) {
            float a[TM], bb[TN];
            float4 a4 = *(const float4*)&As[kk][ty * TM];
            a[0] = a4.x; a[1] = a4.y; a[2] = a4.z; a[3] = a4.w;
            #pragma unroll
            for (int j = 0; j < TN; j++) bb[j] = Bs[kk][tx * TN + j];
            #pragma unroll
            for (int ii = 0; ii < TM; ii++)
                #pragma unroll
                for (int j = 0; j < TN; j++)
                    acc[ii][j] = fmaf(a[ii], bb[j], acc[ii][j]);
        }
    }
    #pragma unroll
    for (int ii = 0; ii < TM; ii++) {
        int m = m0 + ty * TM + ii;
        #pragma unroll
        for (int j = 0; j < TN; j++) {
            int n = n0 + tx * TN + j;
            float v = acc[ii][j] + bias[n];
            if (EPI == 1) v = 0.5f * v * (1.0f + erff(v * 0.70710678118654752f));
            if (EPI == 2) v += res[(size_t)m * N + n];
            C[(size_t)m * N + n] = v;
        }
    }
}

// ---------------------------------------------------------------------------
// K3: attention per (window, head).  128 threads.
//   smem: q,k,v (98x32 each) + S (98x101 padded)  = ~77.2 KB dynamic
// ---------------------------------------------------------------------------
#define SPAD 101
__global__ __launch_bounds__(128)
void attn_kernel(const float* __restrict__ mask) {
    int wh   = blockIdx.x;
    int win  = wh / HEADS, head = wh % HEADS;
    int mw   = win & (NW_PB - 1);
    extern __shared__ float sm[];
    float* q = sm;
    float* k = q + NTOKW * HDIM;
    float* v = k + NTOKW * HDIM;
    float* S = v + NTOKW * HDIM;
    int tid = threadIdx.x;

    const float* base = g_qkv + (size_t)win * NTOKW * 288 + head * HDIM;
    for (int idx = tid; idx < NTOKW * HDIM; idx += 128) {
        int n = idx >> 5, d = idx & 31;
        const float* p = base + (size_t)n * 288 + d;
        q[idx] = p[0] * SCALE;
        k[idx] = p[96];
        v[idx] = p[192];
    }
    const float* rp = g_rpb + head * NTOKW * NTOKW;
    const float* mp = mask + (size_t)mw * NTOKW * NTOKW;
    for (int idx = tid; idx < NTOKW * NTOKW; idx += 128) {
        int i = idx / NTOKW, j = idx % NTOKW;
        S[i * SPAD + j] = rp[idx] + mp[idx];
    }
    __syncthreads();

    int warp = tid >> 5, lane = tid & 31;
    int i = warp * 32 + lane;

    if (i < NTOKW) {
        float4 qr[8];
        #pragma unroll
        for (int t = 0; t < 8; t++) qr[t] = *(const float4*)&q[i * HDIM + t * 4];
        for (int j = 0; j < NTOKW; j++) {
            const float4* kj = (const float4*)&k[j * HDIM];
            float acc = 0.0f;
            #pragma unroll
            for (int t = 0; t < 8; t++) {
                float4 kv = kj[t];
                acc = fmaf(qr[t].x, kv.x, acc);
                acc = fmaf(qr[t].y, kv.y, acc);
                acc = fmaf(qr[t].z, kv.z, acc);
                acc = fmaf(qr[t].w, kv.w, acc);
            }
            S[i * SPAD + j] += acc;
        }
    }
    __syncthreads();

    // softmax per row, warp-strided rows, lanes over columns
    for (int r = warp; r < NTOKW; r += 4) {
        float m = -1e30f;
        for (int j = lane; j < NTOKW; j += 32) m = fmaxf(m, S[r * SPAD + j]);
        #pragma unroll
        for (int o = 16; o; o >>= 1) m = fmaxf(m, __shfl_xor_sync(0xFFFFFFFFu, m, o));
        float s = 0.0f;
        for (int j = lane; j < NTOKW; j += 32) {
            float e = __expf(S[r * SPAD + j] - m);
            S[r * SPAD + j] = e;
            s += e;
        }
        #pragma unroll
        for (int o = 16; o; o >>= 1) s += __shfl_xor_sync(0xFFFFFFFFu, s, o);
        float inv = 1.0f / s;
        for (int j = lane; j < NTOKW; j += 32) S[r * SPAD + j] *= inv;
    }
    __syncthreads();

    if (i < NTOKW) {
        float acc[HDIM];
        #pragma unroll
        for (int t = 0; t < HDIM; t++) acc[t] = 0.0f;
        for (int j = 0; j < NTOKW; j++) {
            float p = S[i * SPAD + j];
            const float4* vj = (const float4*)&v[j * HDIM];
            #pragma unroll
            for (int t = 0; t < 8; t++) {
                float4 vv = vj[t];
                acc[4 * t + 0] = fmaf(p, vv.x, acc[4 * t + 0]);
                acc[4 * t + 1] = fmaf(p, vv.y, acc[4 * t + 1]);
                acc[4 * t + 2] = fmaf(p, vv.z, acc[4 * t + 2]);
                acc[4 * t + 3] = fmaf(p, vv.w, acc[4 * t + 3]);
            }
        }
        float* op = g_attn + ((size_t)win * NTOKW + i) * CDIM + head * HDIM;
        #pragma unroll
        for (int t = 0; t < 8; t++)
            *(float4*)&op[4 * t] = make_float4(acc[4*t], acc[4*t+1], acc[4*t+2], acc[4*t+3]);
    }
}

// ---------------------------------------------------------------------------
// K5: window-reverse + reverse shift + attn residual:  g_xres = x + gather(proj)
//     proj output lives in g_xw.  One thread per element (exact grid).
// ---------------------------------------------------------------------------
__global__ void residual_gather(const float* __restrict__ x) {
    int idx = blockIdx.x * 256 + threadIdx.x;
    int c = idx % CDIM;
    int t = idx / CDIM;
    int w = t % 112; int r = t / 112;
    int h = r % 112; r /= 112;
    int d = r % 16;  int bb = r / 16;
    int sd = d - 1; if (sd < 0) sd += 16;
    int sh = h - 3; if (sh < 0) sh += 112;
    int sw = w - 3; if (sw < 0) sw += 112;
    int win = ((bb * 8 + (sd >> 1)) * 16 + sh / 7) * 16 + sw / 7;
    int n   = ((sd & 1) * 7 + sh % 7) * 7 + sw % 7;
    g_xres[idx] = x[idx] + g_xw[((size_t)win * NTOKW + n) * CDIM + c];
}

// ---------------------------------------------------------------------------
// K6: LN2 (per-token), g_xres -> g_attn (reused).  One warp per token.
// ---------------------------------------------------------------------------
__global__ void ln2_kernel(const float* __restrict__ g, const float* __restrict__ b) {
    int t    = blockIdx.x * 4 + (threadIdx.x >> 5);
    int lane = threadIdx.x & 31;
    const float* px = g_xres + (size_t)t * CDIM;
    float v0 = px[lane], v1 = px[lane + 32], v2 = px[lane + 64];
    float s  = v0 + v1 + v2;
    float ss = v0 * v0 + v1 * v1 + v2 * v2;
    #pragma unroll
    for (int o = 16; o; o >>= 1) {
        s  += __shfl_xor_sync(0xFFFFFFFFu, s, o);
        ss += __shfl_xor_sync(0xFFFFFFFFu, ss, o);
    }
    float mu   = s * (1.0f / 96.0f);
    float var  = ss * (1.0f / 96.0f) - mu * mu;
    float rstd = rsqrtf(var + 1e-5f);
    float* po = g_attn + (size_t)t * CDIM;
    po[lane]      = (v0 - mu) * rstd * g[lane]      + b[lane];
    po[lane + 32] = (v1 - mu) * rstd * g[lane + 32] + b[lane + 32];
    po[lane + 64] = (v2 - mu) * rstd * g[lane + 64] + b[lane + 64];
}

// ---------------------------------------------------------------------------
extern "C" void kernel_launch(void* const* d_in, const int* in_sizes, int n_in,
                              void* d_out, int out_size) {
    const float* x         = (const float*)d_in[0];
    const float* attn_mask = (const float*)d_in[1];
    const float* g1        = (const float*)d_in[2];
    const float* b1        = (const float*)d_in[3];
    const float* qkv_w     = (const float*)d_in[4];
    const float* qkv_b     = (const float*)d_in[5];
    const float* rpb_table = (const float*)d_in[6];
    const float* proj_w    = (const float*)d_in[7];
    const float* proj_b    = (const float*)d_in[8];
    const float* g2        = (const float*)d_in[9];
    const float* b2        = (const float*)d_in[10];
    const float* fc1_w     = (const float*)d_in[11];
    const float* fc1_b     = (const float*)d_in[12];
    const float* fc2_w     = (const float*)d_in[13];
    const float* fc2_b     = (const float*)d_in[14];
    float* out = (float*)d_out;

    float *p_xw, *p_qkv, *p_attn, *p_xres, *p_h;
    cudaGetSymbolAddress((void**)&p_xw,   g_xw);
    cudaGetSymbolAddress((void**)&p_qkv,  g_qkv);
    cudaGetSymbolAddress((void**)&p_attn, g_attn);
    cudaGetSymbolAddress((void**)&p_xres, g_xres);
    cudaGetSymbolAddress((void**)&p_h,    g_h);

    size_t attn_smem = (size_t)(3 * NTOKW * HDIM + NTOKW * SPAD) * sizeof(float);
    cudaFuncSetAttribute(attn_kernel, cudaFuncAttributeMaxDynamicSharedMemorySize,
                         (int)attn_smem);

    // K0: rpb expand
    rpb_precompute<<<(HEADS * NTOKW * NTOKW + 255) / 256, 256>>>(rpb_table);

    // K1: LN1 + shift + window partition
    ln1_shift_win<<<NTOK / 4, 128>>>(x, g1, b1);

    // K2: QKV gemm  (M=401408, N=288, K=96)
    sgemm_kernel<48, 3, 0><<<dim3(288 / 48, NTOK / 64), 256>>>(
        p_xw, qkv_w, qkv_b, nullptr, p_qkv, NTOK, 288, 96);

    // K3: attention
    attn_kernel<<<NWIN * HEADS, 128, attn_smem>>>(attn_mask);

    // K4: proj gemm  (M, 96, 96)  -> g_xw (reused)
    sgemm_kernel<48, 3, 0><<<dim3(96 / 48, NTOK / 64), 256>>>(
        p_attn, proj_w, proj_b, nullptr, p_xw, NTOK, 96, 96);

    // K5: window reverse + reverse shift + residual
    residual_gather<<<(NTOK * CDIM) / 256, 256>>>(x);

    // K6: LN2 -> g_attn (reused)
    ln2_kernel<<<NTOK / 4, 128>>>(g2, b2);

    // K7: fc1 + GELU  (M, 384, 96)
    sgemm_kernel<64, 4, 1><<<dim3(HID / 64, NTOK / 64), 256>>>(
        p_attn, fc1_w, fc1_b, nullptr, p_h, NTOK, HID, 96);

    // K8: fc2 + residual  (M, 96, 384)  -> d_out
    sgemm_kernel<48, 3, 2><<<dim3(96 / 48, NTOK / 64), 256>>>(
        p_h, fc2_w, fc2_b, p_xres, out, NTOK, 96, HID);
}

// round 4
// speedup vs baseline: 1.3267x; 1.3267x over previous
#include <cuda_runtime.h>
#include <cstdint>
#include <math.h>

// ---------------------------------------------------------------------------
// Swin Transformer 3D block — round 3: tf32 mma.sync GEMMs (re-bench of R2
// theory after infra failure) + fused residual/LN2 kernel.
//   B=2, D=16, H=112, W=112, C=96, WS=(2,7,7), N=98, HEADS=3, HEAD_DIM=32
// ---------------------------------------------------------------------------

#define NTOK   401408
#define CDIM   96
#define NWIN   4096
#define NW_PB  2048
#define NTOKW  98
#define HEADS  3
#define HDIM   32
#define SCALE  0.17677669529663687f
#define HID    384

__device__ float g_xw  [(size_t)NTOK * CDIM];
__device__ float g_qkv [(size_t)NTOK * 288];
__device__ float g_attn[(size_t)NTOK * CDIM];
__device__ float g_xres[(size_t)NTOK * CDIM];
__device__ float g_h   [(size_t)NTOK * HID];
__device__ float g_rpb [HEADS * NTOKW * NTOKW];

// ---------------------------------------------------------------------------
__global__ void rpb_precompute(const float* __restrict__ table) {
    int idx = blockIdx.x * 256 + threadIdx.x;
    if (idx >= HEADS * NTOKW * NTOKW) return;
    int h = idx / (NTOKW * NTOKW);
    int r = idx % (NTOKW * NTOKW);
    int i = r / NTOKW, j = r % NTOKW;
    int zdi = i / 49, zhi = (i / 7) % 7, zwi = i % 7;
    int zdj = j / 49, zhj = (j / 7) % 7, zwj = j % 7;
    int ridx = (zdi - zdj + 1) * 169 + (zhi - zhj + 6) * 13 + (zwi - zwj + 6);
    g_rpb[idx] = table[ridx * 3 + h];
}

// ---------------------------------------------------------------------------
// LN1 + cyclic shift + window partition.  One warp per token.
// ---------------------------------------------------------------------------
__global__ void ln1_shift_win(const float* __restrict__ x,
                              const float* __restrict__ g,
                              const float* __restrict__ b) {
    int t    = blockIdx.x * 4 + (threadIdx.x >> 5);
    int lane = threadIdx.x & 31;
    int win = t / NTOKW, n = t % NTOKW;
    int bb  = win >> 11;
    int rem = win & 2047;
    int wd = rem >> 8, wh = (rem >> 4) & 15, ww = rem & 15;
    int zd = n / 49, r2 = n % 49, zh = r2 / 7, zw = r2 % 7;
    int sd = (wd * 2 + zd + 1) & 15;
    int sh = wh * 7 + zh + 3; if (sh >= 112) sh -= 112;
    int sw = ww * 7 + zw + 3; if (sw >= 112) sw -= 112;
    const float* px = x + ((((size_t)bb * 16 + sd) * 112 + sh) * 112 + sw) * CDIM;
    float v0 = px[lane], v1 = px[lane + 32], v2 = px[lane + 64];
    float s  = v0 + v1 + v2;
    float ss = v0 * v0 + v1 * v1 + v2 * v2;
    #pragma unroll
    for (int o = 16; o; o >>= 1) {
        s  += __shfl_xor_sync(0xFFFFFFFFu, s, o);
        ss += __shfl_xor_sync(0xFFFFFFFFu, ss, o);
    }
    float mu   = s * (1.0f / 96.0f);
    float var  = ss * (1.0f / 96.0f) - mu * mu;
    float rstd = rsqrtf(var + 1e-5f);
    float* po = g_xw + (size_t)t * CDIM;
    po[lane]      = (v0 - mu) * rstd * g[lane]      + b[lane];
    po[lane + 32] = (v1 - mu) * rstd * g[lane + 32] + b[lane + 32];
    po[lane + 64] = (v2 - mu) * rstd * g[lane + 64] + b[lane + 64];
}

// ---------------------------------------------------------------------------
// tf32 mma helpers
// ---------------------------------------------------------------------------
__device__ __forceinline__ uint32_t f2tf32(float f) {
    uint32_t r;
    asm("cvt.rna.tf32.f32 %0, %1;" : "=r"(r) : "f"(f));
    return r;
}

__device__ __forceinline__ void mma_tf32(float c[4], const uint32_t a[4], const uint32_t b[2]) {
    asm volatile(
        "mma.sync.aligned.m16n8k8.row.col.f32.tf32.tf32.f32 "
        "{%0,%1,%2,%3}, {%4,%5,%6,%7}, {%8,%9}, {%0,%1,%2,%3};"
        : "+f"(c[0]), "+f"(c[1]), "+f"(c[2]), "+f"(c[3])
        : "r"(a[0]), "r"(a[1]), "r"(a[2]), "r"(a[3]), "r"(b[0]), "r"(b[1]));
}

// ---------------------------------------------------------------------------
// tf32 tensor-core GEMM: C[m,n] = sum_k A[m,k]*B[n,k] (+bias) (+gelu/+res)
//   Block tile 128 x 96, 6 warps (2x3), warp tile 64x32, BK=32.
//   EPI: 0 = bias, 1 = bias+gelu(exact), 2 = bias+res
// ---------------------------------------------------------------------------
#define BK   32
#define LDA  33
template<int EPI>
__global__ __launch_bounds__(192)
void mma_gemm(const float* __restrict__ A, const float* __restrict__ B,
              const float* __restrict__ bias, const float* __restrict__ res,
              float* __restrict__ C, int M, int N, int K) {
    constexpr int BM = 128, BN = 96;
    __shared__ uint32_t As[BM * LDA];
    __shared__ uint32_t Bs[BN * LDA];

    int tid  = threadIdx.x;
    int w    = tid >> 5;
    int lane = tid & 31;
    int g    = lane >> 2;
    int tg   = lane & 3;
    int warpM = w & 1;
    int warpN = w >> 1;
    int m0 = blockIdx.y * BM;
    int n0 = blockIdx.x * BN;

    float acc[4][4][4];
    #pragma unroll
    for (int i = 0; i < 4; i++)
        #pragma unroll
        for (int j = 0; j < 4; j++)
            #pragma unroll
            for (int t = 0; t < 4; t++) acc[i][j][t] = 0.0f;

    for (int k0 = 0; k0 < K; k0 += BK) {
        #pragma unroll 2
        for (int idx = tid; idx < BM * (BK / 4); idx += 192) {
            int r = idx >> 3, kq = (idx & 7) << 2;
            float4 av = *(const float4*)&A[(size_t)(m0 + r) * K + k0 + kq];
            uint32_t* p = &As[r * LDA + kq];
            p[0] = f2tf32(av.x); p[1] = f2tf32(av.y);
            p[2] = f2tf32(av.z); p[3] = f2tf32(av.w);
        }
        #pragma unroll
        for (int idx = tid; idx < BN * (BK / 4); idx += 192) {
            int r = idx >> 3, kq = (idx & 7) << 2;
            float4 bv = *(const float4*)&B[(size_t)(n0 + r) * K + k0 + kq];
            uint32_t* p = &Bs[r * LDA + kq];
            p[0] = f2tf32(bv.x); p[1] = f2tf32(bv.y);
            p[2] = f2tf32(bv.z); p[3] = f2tf32(bv.w);
        }
        __syncthreads();

        #pragma unroll
        for (int ks = 0; ks < BK / 8; ks++) {
            uint32_t afr[4][4];
            #pragma unroll
            for (int mt = 0; mt < 4; mt++) {
                int row = warpM * 64 + mt * 16;
                const uint32_t* ap = &As[(row + g) * LDA + ks * 8 + tg];
                afr[mt][0] = ap[0];
                afr[mt][1] = ap[8 * LDA];
                afr[mt][2] = ap[4];
                afr[mt][3] = ap[8 * LDA + 4];
            }
            uint32_t bfr[4][2];
            #pragma unroll
            for (int nt = 0; nt < 4; nt++) {
                int col = warpN * 32 + nt * 8;
                const uint32_t* bp = &Bs[(col + g) * LDA + ks * 8 + tg];
                bfr[nt][0] = bp[0];
                bfr[nt][1] = bp[4];
            }
            #pragma unroll
            for (int mt = 0; mt < 4; mt++)
                #pragma unroll
                for (int nt = 0; nt < 4; nt++)
                    mma_tf32(acc[mt][nt], afr[mt], bfr[nt]);
        }
        __syncthreads();
    }

    #pragma unroll
    for (int mt = 0; mt < 4; mt++) {
        int r0 = m0 + warpM * 64 + mt * 16 + g;
        #pragma unroll
        for (int nt = 0; nt < 4; nt++) {
            int c0 = n0 + warpN * 32 + nt * 8 + tg * 2;
            float bs0 = bias[c0], bs1 = bias[c0 + 1];
            float v0 = acc[mt][nt][0] + bs0;
            float v1 = acc[mt][nt][1] + bs1;
            float v2 = acc[mt][nt][2] + bs0;
            float v3 = acc[mt][nt][3] + bs1;
            if (EPI == 1) {
                v0 = 0.5f * v0 * (1.0f + erff(v0 * 0.70710678118654752f));
                v1 = 0.5f * v1 * (1.0f + erff(v1 * 0.70710678118654752f));
                v2 = 0.5f * v2 * (1.0f + erff(v2 * 0.70710678118654752f));
                v3 = 0.5f * v3 * (1.0f + erff(v3 * 0.70710678118654752f));
            }
            if (EPI == 2) {
                const float* rp0 = &res[(size_t)r0 * N + c0];
                const float* rp1 = &res[(size_t)(r0 + 8) * N + c0];
                v0 += rp0[0]; v1 += rp0[1];
                v2 += rp1[0]; v3 += rp1[1];
            }
            *(float2*)&C[(size_t)r0 * N + c0]       = make_float2(v0, v1);
            *(float2*)&C[(size_t)(r0 + 8) * N + c0] = make_float2(v2, v3);
        }
    }
}

// ---------------------------------------------------------------------------
// attention per (window, head)
// ---------------------------------------------------------------------------
#define SPAD 101
__global__ __launch_bounds__(128)
void attn_kernel(const float* __restrict__ mask) {
    int wh   = blockIdx.x;
    int win  = wh / HEADS, head = wh % HEADS;
    int mw   = win & (NW_PB - 1);
    extern __shared__ float sm[];
    float* q = sm;
    float* k = q + NTOKW * HDIM;
    float* v = k + NTOKW * HDIM;
    float* S = v + NTOKW * HDIM;
    int tid = threadIdx.x;

    const float* base = g_qkv + (size_t)win * NTOKW * 288 + head * HDIM;
    for (int idx = tid; idx < NTOKW * HDIM; idx += 128) {
        int n = idx >> 5, d = idx & 31;
        const float* p = base + (size_t)n * 288 + d;
        q[idx] = p[0] * SCALE;
        k[idx] = p[96];
        v[idx] = p[192];
    }
    const float* rp = g_rpb + head * NTOKW * NTOKW;
    const float* mp = mask + (size_t)mw * NTOKW * NTOKW;
    for (int idx = tid; idx < NTOKW * NTOKW; idx += 128) {
        int i = idx / NTOKW, j = idx % NTOKW;
        S[i * SPAD + j] = rp[idx] + mp[idx];
    }
    __syncthreads();

    int warp = tid >> 5, lane = tid & 31;
    int i = warp * 32 + lane;

    if (i < NTOKW) {
        float4 qr[8];
        #pragma unroll
        for (int t = 0; t < 8; t++) qr[t] = *(const float4*)&q[i * HDIM + t * 4];
        for (int j = 0; j < NTOKW; j++) {
            const float4* kj = (const float4*)&k[j * HDIM];
            float acc = 0.0f;
            #pragma unroll
            for (int t = 0; t < 8; t++) {
                float4 kv = kj[t];
                acc = fmaf(qr[t].x, kv.x, acc);
                acc = fmaf(qr[t].y, kv.y, acc);
                acc = fmaf(qr[t].z, kv.z, acc);
                acc = fmaf(qr[t].w, kv.w, acc);
            }
            S[i * SPAD + j] += acc;
        }
    }
    __syncthreads();

    for (int r = warp; r < NTOKW; r += 4) {
        float m = -1e30f;
        for (int j = lane; j < NTOKW; j += 32) m = fmaxf(m, S[r * SPAD + j]);
        #pragma unroll
        for (int o = 16; o; o >>= 1) m = fmaxf(m, __shfl_xor_sync(0xFFFFFFFFu, m, o));
        float s = 0.0f;
        for (int j = lane; j < NTOKW; j += 32) {
            float e = __expf(S[r * SPAD + j] - m);
            S[r * SPAD + j] = e;
            s += e;
        }
        #pragma unroll
        for (int o = 16; o; o >>= 1) s += __shfl_xor_sync(0xFFFFFFFFu, s, o);
        float inv = 1.0f / s;
        for (int j = lane; j < NTOKW; j += 32) S[r * SPAD + j] *= inv;
    }
    __syncthreads();

    if (i < NTOKW) {
        float acc[HDIM];
        #pragma unroll
        for (int t = 0; t < HDIM; t++) acc[t] = 0.0f;
        for (int j = 0; j < NTOKW; j++) {
            float p = S[i * SPAD + j];
            const float4* vj = (const float4*)&v[j * HDIM];
            #pragma unroll
            for (int t = 0; t < 8; t++) {
                float4 vv = vj[t];
                acc[4 * t + 0] = fmaf(p, vv.x, acc[4 * t + 0]);
                acc[4 * t + 1] = fmaf(p, vv.y, acc[4 * t + 1]);
                acc[4 * t + 2] = fmaf(p, vv.z, acc[4 * t + 2]);
                acc[4 * t + 3] = fmaf(p, vv.w, acc[4 * t + 3]);
            }
        }
        float* op = g_attn + ((size_t)win * NTOKW + i) * CDIM + head * HDIM;
        #pragma unroll
        for (int t = 0; t < 8; t++)
            *(float4*)&op[4 * t] = make_float4(acc[4*t], acc[4*t+1], acc[4*t+2], acc[4*t+3]);
    }
}

// ---------------------------------------------------------------------------
// Fused: window-reverse + reverse-shift residual (xres = x + gather(proj))
// then LN2 of xres -> g_attn.  One warp per output token.
// ---------------------------------------------------------------------------
__global__ void residual_ln2(const float* __restrict__ x,
                             const float* __restrict__ g,
                             const float* __restrict__ b) {
    int t    = blockIdx.x * 4 + (threadIdx.x >> 5);
    int lane = threadIdx.x & 31;
    // t = ((bb*16 + d)*112 + h)*112 + w
    int w = t % 112; int r = t / 112;
    int h = r % 112; r /= 112;
    int d = r % 16;  int bb = r / 16;
    int sd = d - 1; if (sd < 0) sd += 16;
    int sh = h - 3; if (sh < 0) sh += 112;
    int sw = w - 3; if (sw < 0) sw += 112;
    int win = ((bb * 8 + (sd >> 1)) * 16 + sh / 7) * 16 + sw / 7;
    int n   = ((sd & 1) * 7 + sh % 7) * 7 + sw % 7;
    const float* pp = g_xw + ((size_t)win * NTOKW + n) * CDIM;
    const float* px = x + (size_t)t * CDIM;
    float v0 = px[lane]      + pp[lane];
    float v1 = px[lane + 32] + pp[lane + 32];
    float v2 = px[lane + 64] + pp[lane + 64];
    float* pr = g_xres + (size_t)t * CDIM;
    pr[lane] = v0; pr[lane + 32] = v1; pr[lane + 64] = v2;
    float s  = v0 + v1 + v2;
    float ss = v0 * v0 + v1 * v1 + v2 * v2;
    #pragma unroll
    for (int o = 16; o; o >>= 1) {
        s  += __shfl_xor_sync(0xFFFFFFFFu, s, o);
        ss += __shfl_xor_sync(0xFFFFFFFFu, ss, o);
    }
    float mu   = s * (1.0f / 96.0f);
    float var  = ss * (1.0f / 96.0f) - mu * mu;
    float rstd = rsqrtf(var + 1e-5f);
    float* po = g_attn + (size_t)t * CDIM;
    po[lane]      = (v0 - mu) * rstd * g[lane]      + b[lane];
    po[lane + 32] = (v1 - mu) * rstd * g[lane + 32] + b[lane + 32];
    po[lane + 64] = (v2 - mu) * rstd * g[lane + 64] + b[lane + 64];
}

// ---------------------------------------------------------------------------
extern "C" void kernel_launch(void* const* d_in, const int* in_sizes, int n_in,
                              void* d_out, int out_size) {
    const float* x         = (const float*)d_in[0];
    const float* attn_mask = (const float*)d_in[1];
    const float* g1        = (const float*)d_in[2];
    const float* b1        = (const float*)d_in[3];
    const float* qkv_w     = (const float*)d_in[4];
    const float* qkv_b     = (const float*)d_in[5];
    const float* rpb_table = (const float*)d_in[6];
    const float* proj_w    = (const float*)d_in[7];
    const float* proj_b    = (const float*)d_in[8];
    const float* g2        = (const float*)d_in[9];
    const float* b2        = (const float*)d_in[10];
    const float* fc1_w     = (const float*)d_in[11];
    const float* fc1_b     = (const float*)d_in[12];
    const float* fc2_w     = (const float*)d_in[13];
    const float* fc2_b     = (const float*)d_in[14];
    float* out = (float*)d_out;

    float *p_xw, *p_qkv, *p_attn, *p_xres, *p_h;
    cudaGetSymbolAddress((void**)&p_xw,   g_xw);
    cudaGetSymbolAddress((void**)&p_qkv,  g_qkv);
    cudaGetSymbolAddress((void**)&p_attn, g_attn);
    cudaGetSymbolAddress((void**)&p_xres, g_xres);
    cudaGetSymbolAddress((void**)&p_h,    g_h);

    size_t attn_smem = (size_t)(3 * NTOKW * HDIM + NTOKW * SPAD) * sizeof(float);
    cudaFuncSetAttribute(attn_kernel, cudaFuncAttributeMaxDynamicSharedMemorySize,
                         (int)attn_smem);

    rpb_precompute<<<(HEADS * NTOKW * NTOKW + 255) / 256, 256>>>(rpb_table);
    ln1_shift_win<<<NTOK / 4, 128>>>(x, g1, b1);

    // QKV gemm (M, 288, 96)
    mma_gemm<0><<<dim3(288 / 96, NTOK / 128), 192>>>(
        p_xw, qkv_w, qkv_b, nullptr, p_qkv, NTOK, 288, 96);

    attn_kernel<<<NWIN * HEADS, 128, attn_smem>>>(attn_mask);

    // proj gemm (M, 96, 96)
    mma_gemm<0><<<dim3(1, NTOK / 128), 192>>>(
        p_attn, proj_w, proj_b, nullptr, p_xw, NTOK, 96, 96);

    // fused residual gather + LN2
    residual_ln2<<<NTOK / 4, 128>>>(x, g2, b2);

    // fc1 + gelu (M, 384, 96)
    mma_gemm<1><<<dim3(HID / 96, NTOK / 128), 192>>>(
        p_attn, fc1_w, fc1_b, nullptr, p_h, NTOK, HID, 96);

    // fc2 + residual (M, 96, 384)
    mma_gemm<2><<<dim3(1, NTOK / 128), 192>>>(
        p_h, fc2_w, fc2_b, p_xres, out, NTOK, 96, HID);
}

// round 5
// speedup vs baseline: 2.3787x; 1.7929x over previous
#include <cuda_runtime.h>
#include <cstdint>
#include <math.h>

// ---------------------------------------------------------------------------
// Swin Transformer 3D block — round 5
//   GEMM: tf32 mma.sync, single-pass K (BK=96), cp.async, 2 blocks/SM
//   Attention: 256-thread pair-split, q in regs, 3 blocks/SM
// ---------------------------------------------------------------------------

#define NTOK   401408
#define CDIM   96
#define NWIN   4096
#define NW_PB  2048
#define NTOKW  98
#define HEADS  3
#define HDIM   32
#define SCALE  0.17677669529663687f
#define HID    384

__device__ float g_xw  [(size_t)NTOK * CDIM];
__device__ float g_qkv [(size_t)NTOK * 288];
__device__ float g_attn[(size_t)NTOK * CDIM];
__device__ float g_xres[(size_t)NTOK * CDIM];
__device__ float g_h   [(size_t)NTOK * HID];
__device__ float g_rpb [HEADS * NTOKW * NTOKW];

// ---------------------------------------------------------------------------
__global__ void rpb_precompute(const float* __restrict__ table) {
    int idx = blockIdx.x * 256 + threadIdx.x;
    if (idx >= HEADS * NTOKW * NTOKW) return;
    int h = idx / (NTOKW * NTOKW);
    int r = idx % (NTOKW * NTOKW);
    int i = r / NTOKW, j = r % NTOKW;
    int zdi = i / 49, zhi = (i / 7) % 7, zwi = i % 7;
    int zdj = j / 49, zhj = (j / 7) % 7, zwj = j % 7;
    int ridx = (zdi - zdj + 1) * 169 + (zhi - zhj + 6) * 13 + (zwi - zwj + 6);
    g_rpb[idx] = table[ridx * 3 + h];
}

// ---------------------------------------------------------------------------
__global__ void ln1_shift_win(const float* __restrict__ x,
                              const float* __restrict__ g,
                              const float* __restrict__ b) {
    int t    = blockIdx.x * 4 + (threadIdx.x >> 5);
    int lane = threadIdx.x & 31;
    int win = t / NTOKW, n = t % NTOKW;
    int bb  = win >> 11;
    int rem = win & 2047;
    int wd = rem >> 8, wh = (rem >> 4) & 15, ww = rem & 15;
    int zd = n / 49, r2 = n % 49, zh = r2 / 7, zw = r2 % 7;
    int sd = (wd * 2 + zd + 1) & 15;
    int sh = wh * 7 + zh + 3; if (sh >= 112) sh -= 112;
    int sw = ww * 7 + zw + 3; if (sw >= 112) sw -= 112;
    const float* px = x + ((((size_t)bb * 16 + sd) * 112 + sh) * 112 + sw) * CDIM;
    float v0 = px[lane], v1 = px[lane + 32], v2 = px[lane + 64];
    float s  = v0 + v1 + v2;
    float ss = v0 * v0 + v1 * v1 + v2 * v2;
    #pragma unroll
    for (int o = 16; o; o >>= 1) {
        s  += __shfl_xor_sync(0xFFFFFFFFu, s, o);
        ss += __shfl_xor_sync(0xFFFFFFFFu, ss, o);
    }
    float mu   = s * (1.0f / 96.0f);
    float var  = ss * (1.0f / 96.0f) - mu * mu;
    float rstd = rsqrtf(var + 1e-5f);
    float* po = g_xw + (size_t)t * CDIM;
    po[lane]      = (v0 - mu) * rstd * g[lane]      + b[lane];
    po[lane + 32] = (v1 - mu) * rstd * g[lane + 32] + b[lane + 32];
    po[lane + 64] = (v2 - mu) * rstd * g[lane + 64] + b[lane + 64];
}

// ---------------------------------------------------------------------------
// mma + cp.async helpers
// ---------------------------------------------------------------------------
__device__ __forceinline__ void mma_tf32(float c[4], const uint32_t a[4], const uint32_t b[2]) {
    asm volatile(
        "mma.sync.aligned.m16n8k8.row.col.f32.tf32.tf32.f32 "
        "{%0,%1,%2,%3}, {%4,%5,%6,%7}, {%8,%9}, {%0,%1,%2,%3};"
        : "+f"(c[0]), "+f"(c[1]), "+f"(c[2]), "+f"(c[3])
        : "r"(a[0]), "r"(a[1]), "r"(a[2]), "r"(a[3]), "r"(b[0]), "r"(b[1]));
}

__device__ __forceinline__ void cp_async16(uint32_t smem_addr, const void* gptr) {
    asm volatile("cp.async.ca.shared.global [%0], [%1], 16;"
                 :: "r"(smem_addr), "l"(gptr));
}
__device__ __forceinline__ void cp_async_commit_wait() {
    asm volatile("cp.async.commit_group;\n cp.async.wait_group 0;" ::: "memory");
}

// ---------------------------------------------------------------------------
// tf32 GEMM: C[m,n] = sum_k A[m,k]*B[n,k] (+bias)(+gelu/+res)
//   BM=128, BN=96, BK=96 (whole K chunk per iteration), 256 threads/8 warps,
//   warp tile 64x24 (mt=4 x 16, nt=3 x 8).  K = 96 or 384 (KC = K/96 iters).
//   Raw fp32 into smem via cp.async; HMMA truncates to tf32.
//   EPI: 0=bias, 1=bias+gelu(exact), 2=bias+res
// ---------------------------------------------------------------------------
#define LDK 100
template<int EPI>
__global__ __launch_bounds__(256)
void mma_gemm(const float* __restrict__ A, const float* __restrict__ B,
              const float* __restrict__ bias, const float* __restrict__ res,
              float* __restrict__ C, int M, int N, int K) {
    constexpr int BM = 128, BN = 96, BKC = 96;
    extern __shared__ float smem[];
    float* As = smem;                 // 128 x LDK
    float* Bs = smem + BM * LDK;      //  96 x LDK

    int tid  = threadIdx.x;
    int w    = tid >> 5;
    int lane = tid & 31;
    int g    = lane >> 2;
    int tg   = lane & 3;
    int warpM = w & 1;                // 2
    int warpN = w >> 1;               // 4
    int m0 = blockIdx.y * BM;
    int n0 = blockIdx.x * BN;

    float acc[4][3][4];
    #pragma unroll
    for (int i = 0; i < 4; i++)
        #pragma unroll
        for (int j = 0; j < 3; j++)
            #pragma unroll
            for (int t = 0; t < 4; t++) acc[i][j][t] = 0.0f;

    uint32_t sA = (uint32_t)__cvta_generic_to_shared(As);
    uint32_t sB = (uint32_t)__cvta_generic_to_shared(Bs);

    int KC = K / BKC;
    for (int kc = 0; kc < KC; kc++) {
        int k0 = kc * BKC;
        // A tile: 128 rows x 24 chunks(16B) = 3072 chunks, 12 per thread
        #pragma unroll
        for (int t = 0; t < 12; t++) {
            int idx = tid + t * 256;
            int r = idx / 24, c = idx % 24;
            cp_async16(sA + (r * LDK + c * 4) * 4,
                       &A[(size_t)(m0 + r) * K + k0 + c * 4]);
        }
        // B tile: 96 x 24 = 2304 chunks, 9 per thread
        #pragma unroll
        for (int t = 0; t < 9; t++) {
            int idx = tid + t * 256;
            int r = idx / 24, c = idx % 24;
            cp_async16(sB + (r * LDK + c * 4) * 4,
                       &B[(size_t)(n0 + r) * K + k0 + c * 4]);
        }
        cp_async_commit_wait();
        __syncthreads();

        #pragma unroll
        for (int ks = 0; ks < BKC / 8; ks++) {
            uint32_t afr[4][4];
            #pragma unroll
            for (int mt = 0; mt < 4; mt++) {
                const uint32_t* ap = (const uint32_t*)
                    &As[(warpM * 64 + mt * 16 + g) * LDK + ks * 8 + tg];
                afr[mt][0] = ap[0];
                afr[mt][1] = ap[8 * LDK];
                afr[mt][2] = ap[4];
                afr[mt][3] = ap[8 * LDK + 4];
            }
            uint32_t bfr[3][2];
            #pragma unroll
            for (int nt = 0; nt < 3; nt++) {
                const uint32_t* bp = (const uint32_t*)
                    &Bs[(warpN * 24 + nt * 8 + g) * LDK + ks * 8 + tg];
                bfr[nt][0] = bp[0];
                bfr[nt][1] = bp[4];
            }
            #pragma unroll
            for (int mt = 0; mt < 4; mt++)
                #pragma unroll
                for (int nt = 0; nt < 3; nt++)
                    mma_tf32(acc[mt][nt], afr[mt], bfr[nt]);
        }
        __syncthreads();
    }

    #pragma unroll
    for (int mt = 0; mt < 4; mt++) {
        int r0 = m0 + warpM * 64 + mt * 16 + g;
        #pragma unroll
        for (int nt = 0; nt < 3; nt++) {
            int c0 = n0 + warpN * 24 + nt * 8 + tg * 2;
            float bs0 = bias[c0], bs1 = bias[c0 + 1];
            float v0 = acc[mt][nt][0] + bs0;
            float v1 = acc[mt][nt][1] + bs1;
            float v2 = acc[mt][nt][2] + bs0;
            float v3 = acc[mt][nt][3] + bs1;
            if (EPI == 1) {
                v0 = 0.5f * v0 * (1.0f + erff(v0 * 0.70710678118654752f));
                v1 = 0.5f * v1 * (1.0f + erff(v1 * 0.70710678118654752f));
                v2 = 0.5f * v2 * (1.0f + erff(v2 * 0.70710678118654752f));
                v3 = 0.5f * v3 * (1.0f + erff(v3 * 0.70710678118654752f));
            }
            if (EPI == 2) {
                const float* rp0 = &res[(size_t)r0 * N + c0];
                const float* rp1 = &res[(size_t)(r0 + 8) * N + c0];
                v0 += rp0[0]; v1 += rp0[1];
                v2 += rp1[0]; v3 += rp1[1];
            }
            *(float2*)&C[(size_t)r0 * N + c0]       = make_float2(v0, v1);
            *(float2*)&C[(size_t)(r0 + 8) * N + c0] = make_float2(v2, v3);
        }
    }
}

// ---------------------------------------------------------------------------
// Attention v2: one block per (window, head), 256 threads.
//   smem: k,v (fp32 98x32 each) + S (98x100)  = 62.8 KB -> 3 blocks/SM
//   QK^T: thread pair (row i, half of j-range);  PV: pair (row i, half of d)
// ---------------------------------------------------------------------------
#define SLD 100
__global__ __launch_bounds__(256)
void attn_kernel(const float* __restrict__ mask) {
    int wh   = blockIdx.x;
    int win  = wh / HEADS, head = wh % HEADS;
    int mw   = win & (NW_PB - 1);
    extern __shared__ float sm[];
    float* k = sm;
    float* v = k + NTOKW * HDIM;
    float* S = v + NTOKW * HDIM;
    int tid = threadIdx.x;

    const float* base = g_qkv + (size_t)win * NTOKW * 288 + head * HDIM;
    for (int idx = tid; idx < NTOKW * HDIM; idx += 256) {
        int n = idx >> 5, d = idx & 31;
        const float* p = base + (size_t)n * 288 + d;
        k[idx] = p[96];
        v[idx] = p[192];
    }
    const float* rp = g_rpb + head * NTOKW * NTOKW;
    const float* mp = mask + (size_t)mw * NTOKW * NTOKW;
    for (int idx = tid; idx < NTOKW * NTOKW; idx += 256) {
        int i = idx / NTOKW, j = idx % NTOKW;
        S[i * SLD + j] = rp[idx] + mp[idx];
    }
    __syncthreads();

    int i    = tid >> 1;
    int half = tid & 1;

    // QK^T: row i, j-range [half*49, half*49+49)
    if (i < NTOKW) {
        float4 qr[8];
        const float4* qp = (const float4*)(base + (size_t)i * 288);
        #pragma unroll
        for (int t = 0; t < 8; t++) {
            float4 qv = qp[t];
            qr[t] = make_float4(qv.x * SCALE, qv.y * SCALE, qv.z * SCALE, qv.w * SCALE);
        }
        int j0 = half * 49;
        #pragma unroll 7
        for (int jj = 0; jj < 49; jj++) {
            int j = j0 + jj;
            const float4* kj = (const float4*)&k[j * HDIM];
            float acc = 0.0f;
            #pragma unroll
            for (int t = 0; t < 8; t++) {
                float4 kv = kj[t];
                acc = fmaf(qr[t].x, kv.x, acc);
                acc = fmaf(qr[t].y, kv.y, acc);
                acc = fmaf(qr[t].z, kv.z, acc);
                acc = fmaf(qr[t].w, kv.w, acc);
            }
            S[i * SLD + j] += acc;
        }
    }
    __syncthreads();

    // softmax: 8 warps, warp-per-row strided
    int warp = tid >> 5, lane = tid & 31;
    for (int r = warp; r < NTOKW; r += 8) {
        float m = -1e30f;
        for (int j = lane; j < NTOKW; j += 32) m = fmaxf(m, S[r * SLD + j]);
        #pragma unroll
        for (int o = 16; o; o >>= 1) m = fmaxf(m, __shfl_xor_sync(0xFFFFFFFFu, m, o));
        float s = 0.0f;
        for (int j = lane; j < NTOKW; j += 32) {
            float e = __expf(S[r * SLD + j] - m);
            S[r * SLD + j] = e;
            s += e;
        }
        #pragma unroll
        for (int o = 16; o; o >>= 1) s += __shfl_xor_sync(0xFFFFFFFFu, s, o);
        float inv = 1.0f / s;
        for (int j = lane; j < NTOKW; j += 32) S[r * SLD + j] *= inv;
    }
    __syncthreads();

    // PV: row i, d-range [half*16, half*16+16)
    if (i < NTOKW) {
        int dbase = half * 16;
        float acc[16];
        #pragma unroll
        for (int t = 0; t < 16; t++) acc[t] = 0.0f;
        const float* srow = &S[i * SLD];
        #pragma unroll 7
        for (int j = 0; j < NTOKW; j++) {
            float p = srow[j];
            const float4* vj = (const float4*)&v[j * HDIM + dbase];
            #pragma unroll
            for (int t = 0; t < 4; t++) {
                float4 vv = vj[t];
                acc[4 * t + 0] = fmaf(p, vv.x, acc[4 * t + 0]);
                acc[4 * t + 1] = fmaf(p, vv.y, acc[4 * t + 1]);
                acc[4 * t + 2] = fmaf(p, vv.z, acc[4 * t + 2]);
                acc[4 * t + 3] = fmaf(p, vv.w, acc[4 * t + 3]);
            }
        }
        float* op = g_attn + ((size_t)win * NTOKW + i) * CDIM + head * HDIM + dbase;
        #pragma unroll
        for (int t = 0; t < 4; t++)
            *(float4*)&op[4 * t] = make_float4(acc[4*t], acc[4*t+1], acc[4*t+2], acc[4*t+3]);
    }
}

// ---------------------------------------------------------------------------
// Fused window-reverse + reverse-shift residual + LN2
// ---------------------------------------------------------------------------
__global__ void residual_ln2(const float* __restrict__ x,
                             const float* __restrict__ g,
                             const float* __restrict__ b) {
    int t    = blockIdx.x * 4 + (threadIdx.x >> 5);
    int lane = threadIdx.x & 31;
    int w = t % 112; int r = t / 112;
    int h = r % 112; r /= 112;
    int d = r % 16;  int bb = r / 16;
    int sd = d - 1; if (sd < 0) sd += 16;
    int sh = h - 3; if (sh < 0) sh += 112;
    int sw = w - 3; if (sw < 0) sw += 112;
    int win = ((bb * 8 + (sd >> 1)) * 16 + sh / 7) * 16 + sw / 7;
    int n   = ((sd & 1) * 7 + sh % 7) * 7 + sw % 7;
    const float* pp = g_xw + ((size_t)win * NTOKW + n) * CDIM;
    const float* px = x + (size_t)t * CDIM;
    float v0 = px[lane]      + pp[lane];
    float v1 = px[lane + 32] + pp[lane + 32];
    float v2 = px[lane + 64] + pp[lane + 64];
    float* pr = g_xres + (size_t)t * CDIM;
    pr[lane] = v0; pr[lane + 32] = v1; pr[lane + 64] = v2;
    float s  = v0 + v1 + v2;
    float ss = v0 * v0 + v1 * v1 + v2 * v2;
    #pragma unroll
    for (int o = 16; o; o >>= 1) {
        s  += __shfl_xor_sync(0xFFFFFFFFu, s, o);
        ss += __shfl_xor_sync(0xFFFFFFFFu, ss, o);
    }
    float mu   = s * (1.0f / 96.0f);
    float var  = ss * (1.0f / 96.0f) - mu * mu;
    float rstd = rsqrtf(var + 1e-5f);
    float* po = g_attn + (size_t)t * CDIM;
    po[lane]      = (v0 - mu) * rstd * g[lane]      + b[lane];
    po[lane + 32] = (v1 - mu) * rstd * g[lane + 32] + b[lane + 32];
    po[lane + 64] = (v2 - mu) * rstd * g[lane + 64] + b[lane + 64];
}

// ---------------------------------------------------------------------------
extern "C" void kernel_launch(void* const* d_in, const int* in_sizes, int n_in,
                              void* d_out, int out_size) {
    const float* x         = (const float*)d_in[0];
    const float* attn_mask = (const float*)d_in[1];
    const float* g1        = (const float*)d_in[2];
    const float* b1        = (const float*)d_in[3];
    const float* qkv_w     = (const float*)d_in[4];
    const float* qkv_b     = (const float*)d_in[5];
    const float* rpb_table = (const float*)d_in[6];
    const float* proj_w    = (const float*)d_in[7];
    const float* proj_b    = (const float*)d_in[8];
    const float* g2        = (const float*)d_in[9];
    const float* b2        = (const float*)d_in[10];
    const float* fc1_w     = (const float*)d_in[11];
    const float* fc1_b     = (const float*)d_in[12];
    const float* fc2_w     = (const float*)d_in[13];
    const float* fc2_b     = (const float*)d_in[14];
    float* out = (float*)d_out;

    float *p_xw, *p_qkv, *p_attn, *p_xres, *p_h;
    cudaGetSymbolAddress((void**)&p_xw,   g_xw);
    cudaGetSymbolAddress((void**)&p_qkv,  g_qkv);
    cudaGetSymbolAddress((void**)&p_attn, g_attn);
    cudaGetSymbolAddress((void**)&p_xres, g_xres);
    cudaGetSymbolAddress((void**)&p_h,    g_h);

    const int gemm_smem = (128 + 96) * LDK * 4;            // 89.6 KB
    cudaFuncSetAttribute(mma_gemm<0>, cudaFuncAttributeMaxDynamicSharedMemorySize, gemm_smem);
    cudaFuncSetAttribute(mma_gemm<1>, cudaFuncAttributeMaxDynamicSharedMemorySize, gemm_smem);
    cudaFuncSetAttribute(mma_gemm<2>, cudaFuncAttributeMaxDynamicSharedMemorySize, gemm_smem);

    size_t attn_smem = (size_t)(2 * NTOKW * HDIM + NTOKW * SLD) * sizeof(float);
    cudaFuncSetAttribute(attn_kernel, cudaFuncAttributeMaxDynamicSharedMemorySize,
                         (int)attn_smem);

    rpb_precompute<<<(HEADS * NTOKW * NTOKW + 255) / 256, 256>>>(rpb_table);
    ln1_shift_win<<<NTOK / 4, 128>>>(x, g1, b1);

    // QKV gemm (M, 288, 96)
    mma_gemm<0><<<dim3(288 / 96, NTOK / 128), 256, gemm_smem>>>(
        p_xw, qkv_w, qkv_b, nullptr, p_qkv, NTOK, 288, 96);

    attn_kernel<<<NWIN * HEADS, 256, attn_smem>>>(attn_mask);

    // proj gemm (M, 96, 96)
    mma_gemm<0><<<dim3(1, NTOK / 128), 256, gemm_smem>>>(
        p_attn, proj_w, proj_b, nullptr, p_xw, NTOK, 96, 96);

    residual_ln2<<<NTOK / 4, 128>>>(x, g2, b2);

    // fc1 + gelu (M, 384, 96)
    mma_gemm<1><<<dim3(HID / 96, NTOK / 128), 256, gemm_smem>>>(
        p_attn, fc1_w, fc1_b, nullptr, p_h, NTOK, HID, 96);

    // fc2 + residual (M, 96, 384)
    mma_gemm<2><<<dim3(1, NTOK / 128), 256, gemm_smem>>>(
        p_h, fc2_w, fc2_b, p_xres, out, NTOK, 96, HID);
}

// round 7
// speedup vs baseline: 2.8934x; 1.2164x over previous
#include <cuda_runtime.h>
#include <cuda_bf16.h>
#include <cstdint>
#include <math.h>

// ---------------------------------------------------------------------------
// Swin Transformer 3D block — round 7 (re-bench of round-6 design after
// container flake): bf16 tensor-core GEMMs + bf16 mma attention.
// fp32 residual spine.
// ---------------------------------------------------------------------------

#define NTOK   401408
#define CDIM   96
#define NWIN   4096
#define NW_PB  2048
#define NTOKW  98
#define HEADS  3
#define HDIM   32
#define SCALE  0.17677669529663687f
#define HID    384

typedef __nv_bfloat16 bf16;
typedef __nv_bfloat162 bf162;

// -------------------------- device scratch ---------------------------------
__device__ bf16  g_xwh  [(size_t)NTOK * CDIM];     // ln1 out; later ln2 out
__device__ bf16  g_qkvh [(size_t)NTOK * 288];      // qkv (bf16)
__device__ bf16  g_attnh[(size_t)NTOK * CDIM];     // attention out (bf16)
__device__ bf16  g_h    [(size_t)NTOK * HID];      // mlp hidden (bf16)
__device__ float g_xw   [(size_t)NTOK * CDIM];     // proj out (fp32)
__device__ float g_xres [(size_t)NTOK * CDIM];     // x + attn residual (fp32)
__device__ bf16  g_bias [(size_t)NW_PB * HEADS * NTOKW * NTOKW]; // rpb+mask
__device__ bf16  g_wh   [110592];                  // all weights bf16

// ---------------------------------------------------------------------------
// weight conversion (qkv 27648 | proj 9216 | fc1 36864 | fc2 36864)
// ---------------------------------------------------------------------------
__global__ void conv_weights(const float* __restrict__ qkv_w,
                             const float* __restrict__ proj_w,
                             const float* __restrict__ fc1_w,
                             const float* __restrict__ fc2_w) {
    int idx = blockIdx.x * 256 + threadIdx.x;       // 110592 total, exact
    const float* src; int off;
    if (idx < 27648)       { src = qkv_w;  off = idx; }
    else if (idx < 36864)  { src = proj_w; off = idx - 27648; }
    else if (idx < 73728)  { src = fc1_w;  off = idx - 36864; }
    else                   { src = fc2_w;  off = idx - 73728; }
    g_wh[idx] = __float2bfloat16(src[off]);
}

// ---------------------------------------------------------------------------
// combined rpb + mask bias table, bf16, layout [(mw*3+head)][i*98+j]
// ---------------------------------------------------------------------------
__global__ void bias_precompute(const float* __restrict__ table,
                                const float* __restrict__ mask) {
    size_t u = (size_t)blockIdx.x * 256 + threadIdx.x;   // total 2048*3*4802
    if (u >= (size_t)NW_PB * HEADS * 4802) return;
    int p   = (int)(u % 4802);
    int mwh = (int)(u / 4802);
    int head = mwh % 3, mw = mwh / 3;
    int i = p / 49, j = 2 * (p % 49);
    int zdi = i / 49, zhi = (i / 7) % 7, zwi = i % 7;
    float out[2];
    #pragma unroll
    for (int e = 0; e < 2; e++) {
        int jj = j + e;
        int zdj = jj / 49, zhj = (jj / 7) % 7, zwj = jj % 7;
        int ridx = (zdi - zdj + 1) * 169 + (zhi - zhj + 6) * 13 + (zwi - zwj + 6);
        out[e] = table[ridx * 3 + head] + mask[(size_t)mw * 9604 + i * 98 + jj];
    }
    *(bf162*)&g_bias[(size_t)mwh * 9604 + i * 98 + j] =
        __floats2bfloat162_rn(out[0], out[1]);
}

// ---------------------------------------------------------------------------
// LN1 + cyclic shift + window partition -> bf16.  One warp per token.
// ---------------------------------------------------------------------------
__global__ void ln1_shift_win(const float* __restrict__ x,
                              const float* __restrict__ g,
                              const float* __restrict__ b) {
    int t    = blockIdx.x * 4 + (threadIdx.x >> 5);
    int lane = threadIdx.x & 31;
    int win = t / NTOKW, n = t % NTOKW;
    int bb  = win >> 11;
    int rem = win & 2047;
    int wd = rem >> 8, wh = (rem >> 4) & 15, ww = rem & 15;
    int zd = n / 49, r2 = n % 49, zh = r2 / 7, zw = r2 % 7;
    int sd = (wd * 2 + zd + 1) & 15;
    int sh = wh * 7 + zh + 3; if (sh >= 112) sh -= 112;
    int sw = ww * 7 + zw + 3; if (sw >= 112) sw -= 112;
    const float* px = x + ((((size_t)bb * 16 + sd) * 112 + sh) * 112 + sw) * CDIM;
    float v0 = px[lane], v1 = px[lane + 32], v2 = px[lane + 64];
    float s  = v0 + v1 + v2;
    float ss = v0 * v0 + v1 * v1 + v2 * v2;
    #pragma unroll
    for (int o = 16; o; o >>= 1) {
        s  += __shfl_xor_sync(0xFFFFFFFFu, s, o);
        ss += __shfl_xor_sync(0xFFFFFFFFu, ss, o);
    }
    float mu   = s * (1.0f / 96.0f);
    float var  = ss * (1.0f / 96.0f) - mu * mu;
    float rstd = rsqrtf(var + 1e-5f);
    bf16* po = g_xwh + (size_t)t * CDIM;
    po[lane]      = __float2bfloat16((v0 - mu) * rstd * g[lane]      + b[lane]);
    po[lane + 32] = __float2bfloat16((v1 - mu) * rstd * g[lane + 32] + b[lane + 32]);
    po[lane + 64] = __float2bfloat16((v2 - mu) * rstd * g[lane + 64] + b[lane + 64]);
}

// ---------------------------------------------------------------------------
// mma / cp.async helpers
// ---------------------------------------------------------------------------
__device__ __forceinline__ void mma_bf16(float c[4], const uint32_t a[4],
                                         uint32_t b0, uint32_t b1) {
    asm volatile(
        "mma.sync.aligned.m16n8k16.row.col.f32.bf16.bf16.f32 "
        "{%0,%1,%2,%3}, {%4,%5,%6,%7}, {%8,%9}, {%0,%1,%2,%3};"
        : "+f"(c[0]), "+f"(c[1]), "+f"(c[2]), "+f"(c[3])
        : "r"(a[0]), "r"(a[1]), "r"(a[2]), "r"(a[3]), "r"(b0), "r"(b1));
}
__device__ __forceinline__ void cp_async16(uint32_t smem_addr, const void* gptr) {
    asm volatile("cp.async.ca.shared.global [%0], [%1], 16;"
                 :: "r"(smem_addr), "l"(gptr));
}
__device__ __forceinline__ void cp_async_commit_wait() {
    asm volatile("cp.async.commit_group;\n cp.async.wait_group 0;" ::: "memory");
}

// ---------------------------------------------------------------------------
// bf16 GEMM: C[m,n] = sum_k A[m,k]*B[n,k] (+bias)(+gelu/+res)
//   BM=128, BN=96, BK=96 chunk, 256 thr / 8 warps (2x4), warp tile 64x24.
//   EPI: 0=bias, 1=bias+gelu, 2=bias+res.  OUTB: 1 -> bf16 out, 0 -> fp32.
// ---------------------------------------------------------------------------
#define ALD 104   // smem leading dim (bf16 units)
template<int EPI, int OUTB>
__global__ __launch_bounds__(256)
void mma_gemm(const bf16* __restrict__ A, const bf16* __restrict__ B,
              const float* __restrict__ bias, const float* __restrict__ res,
              void* __restrict__ Cv, int M, int N, int K) {
    constexpr int BM = 128, BKC = 96;
    extern __shared__ bf16 sh[];
    bf16* As = sh;                 // 128 x ALD
    bf16* Bs = sh + BM * ALD;      //  96 x ALD

    int tid  = threadIdx.x;
    int w    = tid >> 5;
    int lane = tid & 31;
    int g    = lane >> 2;
    int tg   = lane & 3;
    int warpM = w & 1;
    int warpN = w >> 1;
    int m0 = blockIdx.y * BM;
    int n0 = blockIdx.x * 96;

    float acc[4][3][4];
    #pragma unroll
    for (int i = 0; i < 4; i++)
        #pragma unroll
        for (int j = 0; j < 3; j++)
            #pragma unroll
            for (int t = 0; t < 4; t++) acc[i][j][t] = 0.0f;

    uint32_t sA = (uint32_t)__cvta_generic_to_shared(As);
    uint32_t sB = (uint32_t)__cvta_generic_to_shared(Bs);

    int KC = K / BKC;
    for (int kc = 0; kc < KC; kc++) {
        int k0 = kc * BKC;
        #pragma unroll
        for (int t = 0; t < 6; t++) {
            int idx = tid + t * 256;
            int r = idx / 12, c = idx % 12;
            cp_async16(sA + (r * ALD + c * 8) * 2,
                       &A[(size_t)(m0 + r) * K + k0 + c * 8]);
        }
        #pragma unroll
        for (int t = 0; t < 5; t++) {
            int idx = tid + t * 256;
            if (idx < 1152) {
                int r = idx / 12, c = idx % 12;
                cp_async16(sB + (r * ALD + c * 8) * 2,
                           &B[(size_t)(n0 + r) * K + k0 + c * 8]);
            }
        }
        cp_async_commit_wait();
        __syncthreads();

        #pragma unroll
        for (int ks = 0; ks < BKC / 16; ks++) {
            uint32_t afr[4][4];
            #pragma unroll
            for (int mt = 0; mt < 4; mt++) {
                const uint32_t* ap = (const uint32_t*)
                    (As + (warpM * 64 + mt * 16 + g) * ALD + ks * 16 + tg * 2);
                afr[mt][0] = ap[0];
                afr[mt][1] = ap[8 * (ALD / 2)];
                afr[mt][2] = ap[4];
                afr[mt][3] = ap[8 * (ALD / 2) + 4];
            }
            #pragma unroll
            for (int nt = 0; nt < 3; nt++) {
                const uint32_t* bp = (const uint32_t*)
                    (Bs + (warpN * 24 + nt * 8 + g) * ALD + ks * 16 + tg * 2);
                uint32_t b0 = bp[0], b1 = bp[4];
                #pragma unroll
                for (int mt = 0; mt < 4; mt++)
                    mma_bf16(acc[mt][nt], afr[mt], b0, b1);
            }
        }
        __syncthreads();
    }

    #pragma unroll
    for (int mt = 0; mt < 4; mt++) {
        int r0 = m0 + warpM * 64 + mt * 16 + g;
        #pragma unroll
        for (int nt = 0; nt < 3; nt++) {
            int c0 = n0 + warpN * 24 + nt * 8 + tg * 2;
            float bs0 = bias[c0], bs1 = bias[c0 + 1];
            float v0 = acc[mt][nt][0] + bs0;
            float v1 = acc[mt][nt][1] + bs1;
            float v2 = acc[mt][nt][2] + bs0;
            float v3 = acc[mt][nt][3] + bs1;
            if (EPI == 1) {
                v0 = 0.5f * v0 * (1.0f + erff(v0 * 0.70710678118654752f));
                v1 = 0.5f * v1 * (1.0f + erff(v1 * 0.70710678118654752f));
                v2 = 0.5f * v2 * (1.0f + erff(v2 * 0.70710678118654752f));
                v3 = 0.5f * v3 * (1.0f + erff(v3 * 0.70710678118654752f));
            }
            if (EPI == 2) {
                const float* rp0 = &res[(size_t)r0 * N + c0];
                const float* rp1 = &res[(size_t)(r0 + 8) * N + c0];
                v0 += rp0[0]; v1 += rp0[1];
                v2 += rp1[0]; v3 += rp1[1];
            }
            if (OUTB) {
                bf16* C = (bf16*)Cv;
                *(bf162*)&C[(size_t)r0 * N + c0]       = __floats2bfloat162_rn(v0, v1);
                *(bf162*)&C[(size_t)(r0 + 8) * N + c0] = __floats2bfloat162_rn(v2, v3);
            } else {
                float* C = (float*)Cv;
                *(float2*)&C[(size_t)r0 * N + c0]       = make_float2(v0, v1);
                *(float2*)&C[(size_t)(r0 + 8) * N + c0] = make_float2(v2, v3);
            }
        }
    }
}

// ---------------------------------------------------------------------------
// Tensor-core attention: one block per (window, head), 256 thr / 8 warps.
//   Q padded 112x32, K padded 104x32, Vt 32x112 (transposed), S/P 112x116 bf16
// ---------------------------------------------------------------------------
#define QLD 36
#define KLD 36
#define VLD 116
#define PLD 116
#define SMEM_ATTN_BF 24480

__global__ __launch_bounds__(256)
void attn_kernel() {
    int wh   = blockIdx.x;
    int win  = wh / HEADS, head = wh % HEADS;
    int mw   = win & (NW_PB - 1);
    extern __shared__ bf16 smh[];
    bf16* Qs = smh;
    bf16* Ks = smh + 4032;
    bf16* Vt = smh + 7776;
    bf16* P  = smh + 11488;
    int tid  = threadIdx.x;
    int w    = tid >> 5;
    int lane = tid & 31;
    int g    = lane >> 2;
    int tg   = lane & 3;
    bf16 Z = __float2bfloat16(0.0f);

    const bf16* qkv = g_qkvh + (size_t)win * NTOKW * 288 + head * HDIM;
    for (int idx = tid; idx < 112 * 32; idx += 256) {
        int n = idx >> 5, d = idx & 31;
        Qs[n * QLD + d] = (n < NTOKW) ? qkv[n * 288 + d] : Z;
    }
    for (int idx = tid; idx < 104 * 32; idx += 256) {
        int n = idx >> 5, d = idx & 31;
        Ks[n * KLD + d] = (n < NTOKW) ? qkv[n * 288 + 96 + d] : Z;
    }
    for (int idx = tid; idx < 112 * 32; idx += 256) {
        int n = idx >> 5, d = idx & 31;
        Vt[d * VLD + n] = (n < NTOKW) ? qkv[n * 288 + 192 + d] : Z;
    }
    {
        const uint32_t* bp = (const uint32_t*)(g_bias + (size_t)(mw * 3 + head) * 9604);
        uint32_t* Pu = (uint32_t*)P;
        for (int u = tid; u < 4802; u += 256) {
            int i = u / 49, c = u % 49;
            Pu[i * (PLD / 2) + c] = bp[u];
        }
        for (int u = tid; u < 98 * 7; u += 256) {
            int i = u / 7, c = 49 + u % 7;
            Pu[i * (PLD / 2) + c] = 0;
        }
    }
    __syncthreads();

    // ---------------- QK^T ----------------
    int row0 = w * 16;
    if (w < 7) {
        #pragma unroll
        for (int h2 = 0; h2 < 2; h2++) {
            int ntbase = h2 * 7;
            int NT = h2 ? 6 : 7;
            float acc[7][4];
            #pragma unroll
            for (int t = 0; t < 7; t++)
                #pragma unroll
                for (int q = 0; q < 4; q++) acc[t][q] = 0.0f;
            #pragma unroll
            for (int ks = 0; ks < 2; ks++) {
                uint32_t afr[4];
                const uint32_t* ap = (const uint32_t*)
                    (Qs + (row0 + g) * QLD + ks * 16 + tg * 2);
                afr[0] = ap[0];
                afr[1] = ap[8 * (QLD / 2)];
                afr[2] = ap[4];
                afr[3] = ap[8 * (QLD / 2) + 4];
                for (int t = 0; t < NT; t++) {
                    int n = (ntbase + t) * 8 + g;
                    const uint32_t* bp = (const uint32_t*)
                        (Ks + n * KLD + ks * 16 + tg * 2);
                    mma_bf16(acc[t], afr, bp[0], bp[4]);
                }
            }
            for (int t = 0; t < NT; t++) {
                int c0 = (ntbase + t) * 8 + tg * 2;
                bf162* p0 = (bf162*)(P + (row0 + g) * PLD + c0);
                bf162* p1 = (bf162*)(P + (row0 + g + 8) * PLD + c0);
                float2 f0 = __bfloat1622float2(*p0);
                float2 f1 = __bfloat1622float2(*p1);
                *p0 = __floats2bfloat162_rn(acc[t][0] * SCALE + f0.x,
                                            acc[t][1] * SCALE + f0.y);
                *p1 = __floats2bfloat162_rn(acc[t][2] * SCALE + f1.x,
                                            acc[t][3] * SCALE + f1.y);
            }
        }
    }
    __syncthreads();

    // ---------------- softmax (rows < 98) ----------------
    for (int r = w; r < NTOKW; r += 8) {
        bf16* prow = P + r * PLD;
        float m = -1e30f;
        for (int j = lane; j < NTOKW; j += 32)
            m = fmaxf(m, __bfloat162float(prow[j]));
        #pragma unroll
        for (int o = 16; o; o >>= 1) m = fmaxf(m, __shfl_xor_sync(0xFFFFFFFFu, m, o));
        float s = 0.0f;
        for (int j = lane; j < NTOKW; j += 32) {
            float e = __expf(__bfloat162float(prow[j]) - m);
            prow[j] = __float2bfloat16(e);
            s += e;
        }
        #pragma unroll
        for (int o = 16; o; o >>= 1) s += __shfl_xor_sync(0xFFFFFFFFu, s, o);
        float inv = 1.0f / s;
        for (int j = lane; j < NTOKW; j += 32)
            prow[j] = __float2bfloat16(__bfloat162float(prow[j]) * inv);
    }
    __syncthreads();

    // ---------------- PV ----------------
    if (w < 7) {
        float acc[4][4];
        #pragma unroll
        for (int t = 0; t < 4; t++)
            #pragma unroll
            for (int q = 0; q < 4; q++) acc[t][q] = 0.0f;
        #pragma unroll
        for (int ks = 0; ks < 7; ks++) {
            uint32_t afr[4];
            const uint32_t* ap = (const uint32_t*)
                (P + (row0 + g) * PLD + ks * 16 + tg * 2);
            afr[0] = ap[0];
            afr[1] = ap[8 * (PLD / 2)];
            afr[2] = ap[4];
            afr[3] = ap[8 * (PLD / 2) + 4];
            #pragma unroll
            for (int nt = 0; nt < 4; nt++) {
                const uint32_t* bp = (const uint32_t*)
                    (Vt + (nt * 8 + g) * VLD + ks * 16 + tg * 2);
                mma_bf16(acc[nt], afr, bp[0], bp[4]);
            }
        }
        int r = row0 + g;
        size_t obase = ((size_t)win * NTOKW + r) * CDIM + head * HDIM;
        #pragma unroll
        for (int nt = 0; nt < 4; nt++) {
            int c0 = nt * 8 + tg * 2;
            if (r < NTOKW)
                *(bf162*)&g_attnh[obase + c0] =
                    __floats2bfloat162_rn(acc[nt][0], acc[nt][1]);
            if (r + 8 < NTOKW)
                *(bf162*)&g_attnh[obase + 8 * CDIM + c0] =
                    __floats2bfloat162_rn(acc[nt][2], acc[nt][3]);
        }
    }
}

// ---------------------------------------------------------------------------
// Fused window-reverse + reverse-shift residual + LN2
// ---------------------------------------------------------------------------
__global__ void residual_ln2(const float* __restrict__ x,
                             const float* __restrict__ g,
                             const float* __restrict__ b) {
    int t    = blockIdx.x * 4 + (threadIdx.x >> 5);
    int lane = threadIdx.x & 31;
    int w = t % 112; int r = t / 112;
    int h = r % 112; r /= 112;
    int d = r % 16;  int bb = r / 16;
    int sd = d - 1; if (sd < 0) sd += 16;
    int sh = h - 3; if (sh < 0) sh += 112;
    int sw = w - 3; if (sw < 0) sw += 112;
    int win = ((bb * 8 + (sd >> 1)) * 16 + sh / 7) * 16 + sw / 7;
    int n   = ((sd & 1) * 7 + sh % 7) * 7 + sw % 7;
    const float* pp = g_xw + ((size_t)win * NTOKW + n) * CDIM;
    const float* px = x + (size_t)t * CDIM;
    float v0 = px[lane]      + pp[lane];
    float v1 = px[lane + 32] + pp[lane + 32];
    float v2 = px[lane + 64] + pp[lane + 64];
    float* pr = g_xres + (size_t)t * CDIM;
    pr[lane] = v0; pr[lane + 32] = v1; pr[lane + 64] = v2;
    float s  = v0 + v1 + v2;
    float ss = v0 * v0 + v1 * v1 + v2 * v2;
    #pragma unroll
    for (int o = 16; o; o >>= 1) {
        s  += __shfl_xor_sync(0xFFFFFFFFu, s, o);
        ss += __shfl_xor_sync(0xFFFFFFFFu, ss, o);
    }
    float mu   = s * (1.0f / 96.0f);
    float var  = ss * (1.0f / 96.0f) - mu * mu;
    float rstd = rsqrtf(var + 1e-5f);
    bf16* po = g_xwh + (size_t)t * CDIM;
    po[lane]      = __float2bfloat16((v0 - mu) * rstd * g[lane]      + b[lane]);
    po[lane + 32] = __float2bfloat16((v1 - mu) * rstd * g[lane + 32] + b[lane + 32]);
    po[lane + 64] = __float2bfloat16((v2 - mu) * rstd * g[lane + 64] + b[lane + 64]);
}

// ---------------------------------------------------------------------------
extern "C" void kernel_launch(void* const* d_in, const int* in_sizes, int n_in,
                              void* d_out, int out_size) {
    const float* x         = (const float*)d_in[0];
    const float* attn_mask = (const float*)d_in[1];
    const float* g1        = (const float*)d_in[2];
    const float* b1        = (const float*)d_in[3];
    const float* qkv_w     = (const float*)d_in[4];
    const float* qkv_b     = (const float*)d_in[5];
    const float* rpb_table = (const float*)d_in[6];
    const float* proj_w    = (const float*)d_in[7];
    const float* proj_b    = (const float*)d_in[8];
    const float* g2        = (const float*)d_in[9];
    const float* b2        = (const float*)d_in[10];
    const float* fc1_w     = (const float*)d_in[11];
    const float* fc1_b     = (const float*)d_in[12];
    const float* fc2_w     = (const float*)d_in[13];
    const float* fc2_b     = (const float*)d_in[14];
    float* out = (float*)d_out;

    bf16 *p_xwh, *p_qkvh, *p_attnh, *p_h, *p_wh;
    float *p_xw, *p_xres;
    cudaGetSymbolAddress((void**)&p_xwh,   g_xwh);
    cudaGetSymbolAddress((void**)&p_qkvh,  g_qkvh);
    cudaGetSymbolAddress((void**)&p_attnh, g_attnh);
    cudaGetSymbolAddress((void**)&p_h,     g_h);
    cudaGetSymbolAddress((void**)&p_wh,    g_wh);
    cudaGetSymbolAddress((void**)&p_xw,    g_xw);
    cudaGetSymbolAddress((void**)&p_xres,  g_xres);

    const int gemm_smem = (128 + 96) * ALD * 2;      // 46.6 KB
    cudaFuncSetAttribute(mma_gemm<0,1>, cudaFuncAttributeMaxDynamicSharedMemorySize, gemm_smem);
    cudaFuncSetAttribute(mma_gemm<0,0>, cudaFuncAttributeMaxDynamicSharedMemorySize, gemm_smem);
    cudaFuncSetAttribute(mma_gemm<1,1>, cudaFuncAttributeMaxDynamicSharedMemorySize, gemm_smem);
    cudaFuncSetAttribute(mma_gemm<2,0>, cudaFuncAttributeMaxDynamicSharedMemorySize, gemm_smem);
    const int attn_smem = SMEM_ATTN_BF * 2;          // 48.96 KB
    cudaFuncSetAttribute(attn_kernel, cudaFuncAttributeMaxDynamicSharedMemorySize, attn_smem);

    conv_weights<<<432, 256>>>(qkv_w, proj_w, fc1_w, fc2_w);

    size_t nbias = (size_t)NW_PB * HEADS * 4802;
    bias_precompute<<<(unsigned)((nbias + 255) / 256), 256>>>(rpb_table, attn_mask);

    ln1_shift_win<<<NTOK / 4, 128>>>(x, g1, b1);

    // QKV gemm (M, 288, 96) -> bf16
    mma_gemm<0,1><<<dim3(288 / 96, NTOK / 128), 256, gemm_smem>>>(
        p_xwh, p_wh, qkv_b, nullptr, p_qkvh, NTOK, 288, 96);

    attn_kernel<<<NWIN * HEADS, 256, attn_smem>>>();

    // proj gemm (M, 96, 96) -> fp32 g_xw
    mma_gemm<0,0><<<dim3(1, NTOK / 128), 256, gemm_smem>>>(
        p_attnh, p_wh + 27648, proj_b, nullptr, p_xw, NTOK, 96, 96);

    residual_ln2<<<NTOK / 4, 128>>>(x, g2, b2);

    // fc1 + gelu (M, 384, 96) -> bf16 h
    mma_gemm<1,1><<<dim3(HID / 96, NTOK / 128), 256, gemm_smem>>>(
        p_xwh, p_wh + 36864, fc1_b, nullptr, p_h, NTOK, HID, 96);

    // fc2 + residual (M, 96, 384) -> fp32 d_out
    mma_gemm<2,0><<<dim3(1, NTOK / 128), 256, gemm_smem>>>(
        p_h, p_wh + 73728, fc2_b, p_xres, out, NTOK, 96, HID);
}

// round 10
// speedup vs baseline: 2.9132x; 1.0068x over previous
#include <cuda_runtime.h>
#include <cuda_bf16.h>
#include <cstdint>
#include <math.h>

// ---------------------------------------------------------------------------
// Swin Transformer 3D block — round 10 (third bench attempt of the GEMM-v3
// build; two prior runs died to container flake): pipelined bf16 GEMM
// (2-stage cp.async, 2 blocks/SM) + bf16 mma attention.  fp32 residual spine.
// ---------------------------------------------------------------------------

#define NTOK   401408
#define CDIM   96
#define NWIN   4096
#define NW_PB  2048
#define NTOKW  98
#define HEADS  3
#define HDIM   32
#define SCALE  0.17677669529663687f
#define HID    384

typedef __nv_bfloat16 bf16;
typedef __nv_bfloat162 bf162;

// -------------------------- device scratch ---------------------------------
__device__ bf16  g_xwh  [(size_t)NTOK * CDIM];
__device__ bf16  g_qkvh [(size_t)NTOK * 288];
__device__ bf16  g_attnh[(size_t)NTOK * CDIM];
__device__ bf16  g_h    [(size_t)NTOK * HID];
__device__ float g_xw   [(size_t)NTOK * CDIM];
__device__ float g_xres [(size_t)NTOK * CDIM];
__device__ bf16  g_bias [(size_t)NW_PB * HEADS * NTOKW * NTOKW];
__device__ bf16  g_wh   [110592];

// ---------------------------------------------------------------------------
__global__ void conv_weights(const float* __restrict__ qkv_w,
                             const float* __restrict__ proj_w,
                             const float* __restrict__ fc1_w,
                             const float* __restrict__ fc2_w) {
    int idx = blockIdx.x * 256 + threadIdx.x;       // 110592 total, exact
    const float* src; int off;
    if (idx < 27648)       { src = qkv_w;  off = idx; }
    else if (idx < 36864)  { src = proj_w; off = idx - 27648; }
    else if (idx < 73728)  { src = fc1_w;  off = idx - 36864; }
    else                   { src = fc2_w;  off = idx - 73728; }
    g_wh[idx] = __float2bfloat16(src[off]);
}

// ---------------------------------------------------------------------------
__global__ void bias_precompute(const float* __restrict__ table,
                                const float* __restrict__ mask) {
    size_t u = (size_t)blockIdx.x * 256 + threadIdx.x;   // total 2048*3*4802
    if (u >= (size_t)NW_PB * HEADS * 4802) return;
    int p   = (int)(u % 4802);
    int mwh = (int)(u / 4802);
    int head = mwh % 3, mw = mwh / 3;
    int i = p / 49, j = 2 * (p % 49);
    int zdi = i / 49, zhi = (i / 7) % 7, zwi = i % 7;
    float out[2];
    #pragma unroll
    for (int e = 0; e < 2; e++) {
        int jj = j + e;
        int zdj = jj / 49, zhj = (jj / 7) % 7, zwj = jj % 7;
        int ridx = (zdi - zdj + 1) * 169 + (zhi - zhj + 6) * 13 + (zwi - zwj + 6);
        out[e] = table[ridx * 3 + head] + mask[(size_t)mw * 9604 + i * 98 + jj];
    }
    *(bf162*)&g_bias[(size_t)mwh * 9604 + i * 98 + j] =
        __floats2bfloat162_rn(out[0], out[1]);
}

// ---------------------------------------------------------------------------
__global__ void ln1_shift_win(const float* __restrict__ x,
                              const float* __restrict__ g,
                              const float* __restrict__ b) {
    int t    = blockIdx.x * 4 + (threadIdx.x >> 5);
    int lane = threadIdx.x & 31;
    int win = t / NTOKW, n = t % NTOKW;
    int bb  = win >> 11;
    int rem = win & 2047;
    int wd = rem >> 8, wh = (rem >> 4) & 15, ww = rem & 15;
    int zd = n / 49, r2 = n % 49, zh = r2 / 7, zw = r2 % 7;
    int sd = (wd * 2 + zd + 1) & 15;
    int sh = wh * 7 + zh + 3; if (sh >= 112) sh -= 112;
    int sw = ww * 7 + zw + 3; if (sw >= 112) sw -= 112;
    const float* px = x + ((((size_t)bb * 16 + sd) * 112 + sh) * 112 + sw) * CDIM;
    float v0 = px[lane], v1 = px[lane + 32], v2 = px[lane + 64];
    float s  = v0 + v1 + v2;
    float ss = v0 * v0 + v1 * v1 + v2 * v2;
    #pragma unroll
    for (int o = 16; o; o >>= 1) {
        s  += __shfl_xor_sync(0xFFFFFFFFu, s, o);
        ss += __shfl_xor_sync(0xFFFFFFFFu, ss, o);
    }
    float mu   = s * (1.0f / 96.0f);
    float var  = ss * (1.0f / 96.0f) - mu * mu;
    float rstd = rsqrtf(var + 1e-5f);
    bf16* po = g_xwh + (size_t)t * CDIM;
    po[lane]      = __float2bfloat16((v0 - mu) * rstd * g[lane]      + b[lane]);
    po[lane + 32] = __float2bfloat16((v1 - mu) * rstd * g[lane + 32] + b[lane + 32]);
    po[lane + 64] = __float2bfloat16((v2 - mu) * rstd * g[lane + 64] + b[lane + 64]);
}

// ---------------------------------------------------------------------------
__device__ __forceinline__ void mma_bf16(float c[4], const uint32_t a[4],
                                         uint32_t b0, uint32_t b1) {
    asm volatile(
        "mma.sync.aligned.m16n8k16.row.col.f32.bf16.bf16.f32 "
        "{%0,%1,%2,%3}, {%4,%5,%6,%7}, {%8,%9}, {%0,%1,%2,%3};"
        : "+f"(c[0]), "+f"(c[1]), "+f"(c[2]), "+f"(c[3])
        : "r"(a[0]), "r"(a[1]), "r"(a[2]), "r"(a[3]), "r"(b0), "r"(b1));
}
__device__ __forceinline__ void cp_async16(uint32_t smem_addr, const void* gptr) {
    asm volatile("cp.async.ca.shared.global [%0], [%1], 16;"
                 :: "r"(smem_addr), "l"(gptr));
}
__device__ __forceinline__ void cp_commit() {
    asm volatile("cp.async.commit_group;" ::: "memory");
}
template<int N>
__device__ __forceinline__ void cp_wait() {
    asm volatile("cp.async.wait_group %0;" :: "n"(N) : "memory");
}

// ---------------------------------------------------------------------------
// GEMM v3: BM=64, BN=96, BK=32, 2-stage cp.async pipeline, 256 thr / 8 warps
//   warp tile 32x24 (warpM=w&1, warpN=w>>1).  2 blocks/SM.
//   EPI: 0=bias, 1=bias+gelu, 2=bias+res.  OUTB: 1 -> bf16 out, 0 -> fp32.
// ---------------------------------------------------------------------------
#define GLD  40                 // smem leading dim (bf16), 32 + 8 pad
#define STG  ((64 + 96) * GLD)  // bf16 units per stage = 6400

template<int EPI, int OUTB>
__global__ __launch_bounds__(256, 2)
void mma_gemm(const bf16* __restrict__ A, const bf16* __restrict__ B,
              const float* __restrict__ bias, const float* __restrict__ res,
              void* __restrict__ Cv, int M, int N, int K) {
    __shared__ bf16 sh[2 * STG];          // 25.6 KB

    int tid  = threadIdx.x;
    int w    = tid >> 5;
    int lane = tid & 31;
    int g    = lane >> 2;
    int tg   = lane & 3;
    int warpM = w & 1;
    int warpN = w >> 1;
    int m0 = blockIdx.y * 64;
    int n0 = blockIdx.x * 96;

    int ar = tid >> 2, ac = tid & 3;
    int br0 = tid >> 2, bc0 = tid & 3;
    int bi1 = 256 + tid;
    int br1 = bi1 >> 2, bc1 = bi1 & 3;

    uint32_t sbase = (uint32_t)__cvta_generic_to_shared(sh);

    float acc[2][3][4];
    #pragma unroll
    for (int i = 0; i < 2; i++)
        #pragma unroll
        for (int j = 0; j < 3; j++)
            #pragma unroll
            for (int t = 0; t < 4; t++) acc[i][j][t] = 0.0f;

    int KC = K >> 5;

    {
        cp_async16(sbase + (ar * GLD + ac * 8) * 2,
                   &A[(size_t)(m0 + ar) * K + ac * 8]);
        cp_async16(sbase + ((64 + br0) * GLD + bc0 * 8) * 2,
                   &B[(size_t)(n0 + br0) * K + bc0 * 8]);
        if (tid < 128)
            cp_async16(sbase + ((64 + br1) * GLD + bc1 * 8) * 2,
                       &B[(size_t)(n0 + br1) * K + bc1 * 8]);
        cp_commit();
    }

    for (int kc = 0; kc < KC; kc++) {
        if (kc + 1 < KC) {
            int k0 = (kc + 1) << 5;
            uint32_t sb = sbase + ((kc + 1) & 1) * STG * 2;
            cp_async16(sb + (ar * GLD + ac * 8) * 2,
                       &A[(size_t)(m0 + ar) * K + k0 + ac * 8]);
            cp_async16(sb + ((64 + br0) * GLD + bc0 * 8) * 2,
                       &B[(size_t)(n0 + br0) * K + k0 + bc0 * 8]);
            if (tid < 128)
                cp_async16(sb + ((64 + br1) * GLD + bc1 * 8) * 2,
                           &B[(size_t)(n0 + br1) * K + k0 + bc1 * 8]);
            cp_commit();
            cp_wait<1>();
        } else {
            cp_wait<0>();
        }
        __syncthreads();

        const bf16* As = sh + (kc & 1) * STG;
        const bf16* Bs = As + 64 * GLD;

        #pragma unroll
        for (int ks = 0; ks < 2; ks++) {
            uint32_t afr[2][4];
            #pragma unroll
            for (int mt = 0; mt < 2; mt++) {
                const uint32_t* ap = (const uint32_t*)
                    (As + (warpM * 32 + mt * 16 + g) * GLD + ks * 16 + tg * 2);
                afr[mt][0] = ap[0];
                afr[mt][1] = ap[8 * (GLD / 2)];
                afr[mt][2] = ap[4];
                afr[mt][3] = ap[8 * (GLD / 2) + 4];
            }
            #pragma unroll
            for (int nt = 0; nt < 3; nt++) {
                const uint32_t* bp = (const uint32_t*)
                    (Bs + (warpN * 24 + nt * 8 + g) * GLD + ks * 16 + tg * 2);
                uint32_t b0 = bp[0], b1 = bp[4];
                #pragma unroll
                for (int mt = 0; mt < 2; mt++)
                    mma_bf16(acc[mt][nt], afr[mt], b0, b1);
            }
        }
        __syncthreads();
    }

    #pragma unroll
    for (int mt = 0; mt < 2; mt++) {
        int r0 = m0 + warpM * 32 + mt * 16 + g;
        #pragma unroll
        for (int nt = 0; nt < 3; nt++) {
            int c0 = n0 + warpN * 24 + nt * 8 + tg * 2;
            float bs0 = bias[c0], bs1 = bias[c0 + 1];
            float v0 = acc[mt][nt][0] + bs0;
            float v1 = acc[mt][nt][1] + bs1;
            float v2 = acc[mt][nt][2] + bs0;
            float v3 = acc[mt][nt][3] + bs1;
            if (EPI == 1) {
                v0 = 0.5f * v0 * (1.0f + erff(v0 * 0.70710678118654752f));
                v1 = 0.5f * v1 * (1.0f + erff(v1 * 0.70710678118654752f));
                v2 = 0.5f * v2 * (1.0f + erff(v2 * 0.70710678118654752f));
                v3 = 0.5f * v3 * (1.0f + erff(v3 * 0.70710678118654752f));
            }
            if (EPI == 2) {
                const float* rp0 = &res[(size_t)r0 * N + c0];
                const float* rp1 = &res[(size_t)(r0 + 8) * N + c0];
                v0 += rp0[0]; v1 += rp0[1];
                v2 += rp1[0]; v3 += rp1[1];
            }
            if (OUTB) {
                bf16* C = (bf16*)Cv;
                *(bf162*)&C[(size_t)r0 * N + c0]       = __floats2bfloat162_rn(v0, v1);
                *(bf162*)&C[(size_t)(r0 + 8) * N + c0] = __floats2bfloat162_rn(v2, v3);
            } else {
                float* C = (float*)Cv;
                *(float2*)&C[(size_t)r0 * N + c0]       = make_float2(v0, v1);
                *(float2*)&C[(size_t)(r0 + 8) * N + c0] = make_float2(v2, v3);
            }
        }
    }
}

// ---------------------------------------------------------------------------
// Tensor-core attention (unchanged)
// ---------------------------------------------------------------------------
#define QLD 36
#define KLD 36
#define VLD 116
#define PLD 116
#define SMEM_ATTN_BF 24480

__global__ __launch_bounds__(256)
void attn_kernel() {
    int wh   = blockIdx.x;
    int win  = wh / HEADS, head = wh % HEADS;
    int mw   = win & (NW_PB - 1);
    extern __shared__ bf16 smh[];
    bf16* Qs = smh;
    bf16* Ks = smh + 4032;
    bf16* Vt = smh + 7776;
    bf16* P  = smh + 11488;
    int tid  = threadIdx.x;
    int w    = tid >> 5;
    int lane = tid & 31;
    int g    = lane >> 2;
    int tg   = lane & 3;
    bf16 Z = __float2bfloat16(0.0f);

    const bf16* qkv = g_qkvh + (size_t)win * NTOKW * 288 + head * HDIM;
    for (int idx = tid; idx < 112 * 32; idx += 256) {
        int n = idx >> 5, d = idx & 31;
        Qs[n * QLD + d] = (n < NTOKW) ? qkv[n * 288 + d] : Z;
    }
    for (int idx = tid; idx < 104 * 32; idx += 256) {
        int n = idx >> 5, d = idx & 31;
        Ks[n * KLD + d] = (n < NTOKW) ? qkv[n * 288 + 96 + d] : Z;
    }
    for (int idx = tid; idx < 112 * 32; idx += 256) {
        int n = idx >> 5, d = idx & 31;
        Vt[d * VLD + n] = (n < NTOKW) ? qkv[n * 288 + 192 + d] : Z;
    }
    {
        const uint32_t* bp = (const uint32_t*)(g_bias + (size_t)(mw * 3 + head) * 9604);
        uint32_t* Pu = (uint32_t*)P;
        for (int u = tid; u < 4802; u += 256) {
            int i = u / 49, c = u % 49;
            Pu[i * (PLD / 2) + c] = bp[u];
        }
        for (int u = tid; u < 98 * 7; u += 256) {
            int i = u / 7, c = 49 + u % 7;
            Pu[i * (PLD / 2) + c] = 0;
        }
    }
    __syncthreads();

    int row0 = w * 16;
    if (w < 7) {
        #pragma unroll
        for (int h2 = 0; h2 < 2; h2++) {
            int ntbase = h2 * 7;
            int NT = h2 ? 6 : 7;
            float acc[7][4];
            #pragma unroll
            for (int t = 0; t < 7; t++)
                #pragma unroll
                for (int q = 0; q < 4; q++) acc[t][q] = 0.0f;
            #pragma unroll
            for (int ks = 0; ks < 2; ks++) {
                uint32_t afr[4];
                const uint32_t* ap = (const uint32_t*)
                    (Qs + (row0 + g) * QLD + ks * 16 + tg * 2);
                afr[0] = ap[0];
                afr[1] = ap[8 * (QLD / 2)];
                afr[2] = ap[4];
                afr[3] = ap[8 * (QLD / 2) + 4];
                for (int t = 0; t < NT; t++) {
                    int n = (ntbase + t) * 8 + g;
                    const uint32_t* bp = (const uint32_t*)
                        (Ks + n * KLD + ks * 16 + tg * 2);
                    mma_bf16(acc[t], afr, bp[0], bp[4]);
                }
            }
            for (int t = 0; t < NT; t++) {
                int c0 = (ntbase + t) * 8 + tg * 2;
                bf162* p0 = (bf162*)(P + (row0 + g) * PLD + c0);
                bf162* p1 = (bf162*)(P + (row0 + g + 8) * PLD + c0);
                float2 f0 = __bfloat1622float2(*p0);
                float2 f1 = __bfloat1622float2(*p1);
                *p0 = __floats2bfloat162_rn(acc[t][0] * SCALE + f0.x,
                                            acc[t][1] * SCALE + f0.y);
                *p1 = __floats2bfloat162_rn(acc[t][2] * SCALE + f1.x,
                                            acc[t][3] * SCALE + f1.y);
            }
        }
    }
    __syncthreads();

    for (int r = w; r < NTOKW; r += 8) {
        bf16* prow = P + r * PLD;
        float m = -1e30f;
        for (int j = lane; j < NTOKW; j += 32)
            m = fmaxf(m, __bfloat162float(prow[j]));
        #pragma unroll
        for (int o = 16; o; o >>= 1) m = fmaxf(m, __shfl_xor_sync(0xFFFFFFFFu, m, o));
        float s = 0.0f;
        for (int j = lane; j < NTOKW; j += 32) {
            float e = __expf(__bfloat162float(prow[j]) - m);
            prow[j] = __float2bfloat16(e);
            s += e;
        }
        #pragma unroll
        for (int o = 16; o; o >>= 1) s += __shfl_xor_sync(0xFFFFFFFFu, s, o);
        float inv = 1.0f / s;
        for (int j = lane; j < NTOKW; j += 32)
            prow[j] = __float2bfloat16(__bfloat162float(prow[j]) * inv);
    }
    __syncthreads();

    if (w < 7) {
        float acc[4][4];
        #pragma unroll
        for (int t = 0; t < 4; t++)
            #pragma unroll
            for (int q = 0; q < 4; q++) acc[t][q] = 0.0f;
        #pragma unroll
        for (int ks = 0; ks < 7; ks++) {
            uint32_t afr[4];
            const uint32_t* ap = (const uint32_t*)
                (P + (row0 + g) * PLD + ks * 16 + tg * 2);
            afr[0] = ap[0];
            afr[1] = ap[8 * (PLD / 2)];
            afr[2] = ap[4];
            afr[3] = ap[8 * (PLD / 2) + 4];
            #pragma unroll
            for (int nt = 0; nt < 4; nt++) {
                const uint32_t* bp = (const uint32_t*)
                    (Vt + (nt * 8 + g) * VLD + ks * 16 + tg * 2);
                mma_bf16(acc[nt], afr, bp[0], bp[4]);
            }
        }
        int r = row0 + g;
        size_t obase = ((size_t)win * NTOKW + r) * CDIM + head * HDIM;
        #pragma unroll
        for (int nt = 0; nt < 4; nt++) {
            int c0 = nt * 8 + tg * 2;
            if (r < NTOKW)
                *(bf162*)&g_attnh[obase + c0] =
                    __floats2bfloat162_rn(acc[nt][0], acc[nt][1]);
            if (r + 8 < NTOKW)
                *(bf162*)&g_attnh[obase + 8 * CDIM + c0] =
                    __floats2bfloat162_rn(acc[nt][2], acc[nt][3]);
        }
    }
}

// ---------------------------------------------------------------------------
__global__ void residual_ln2(const float* __restrict__ x,
                             const float* __restrict__ g,
                             const float* __restrict__ b) {
    int t    = blockIdx.x * 4 + (threadIdx.x >> 5);
    int lane = threadIdx.x & 31;
    int w = t % 112; int r = t / 112;
    int h = r % 112; r /= 112;
    int d = r % 16;  int bb = r / 16;
    int sd = d - 1; if (sd < 0) sd += 16;
    int sh = h - 3; if (sh < 0) sh += 112;
    int sw = w - 3; if (sw < 0) sw += 112;
    int win = ((bb * 8 + (sd >> 1)) * 16 + sh / 7) * 16 + sw / 7;
    int n   = ((sd & 1) * 7 + sh % 7) * 7 + sw % 7;
    const float* pp = g_xw + ((size_t)win * NTOKW + n) * CDIM;
    const float* px = x + (size_t)t * CDIM;
    float v0 = px[lane]      + pp[lane];
    float v1 = px[lane + 32] + pp[lane + 32];
    float v2 = px[lane + 64] + pp[lane + 64];
    float* pr = g_xres + (size_t)t * CDIM;
    pr[lane] = v0; pr[lane + 32] = v1; pr[lane + 64] = v2;
    float s  = v0 + v1 + v2;
    float ss = v0 * v0 + v1 * v1 + v2 * v2;
    #pragma unroll
    for (int o = 16; o; o >>= 1) {
        s  += __shfl_xor_sync(0xFFFFFFFFu, s, o);
        ss += __shfl_xor_sync(0xFFFFFFFFu, ss, o);
    }
    float mu   = s * (1.0f / 96.0f);
    float var  = ss * (1.0f / 96.0f) - mu * mu;
    float rstd = rsqrtf(var + 1e-5f);
    bf16* po = g_xwh + (size_t)t * CDIM;
    po[lane]      = __float2bfloat16((v0 - mu) * rstd * g[lane]      + b[lane]);
    po[lane + 32] = __float2bfloat16((v1 - mu) * rstd * g[lane + 32] + b[lane + 32]);
    po[lane + 64] = __float2bfloat16((v2 - mu) * rstd * g[lane + 64] + b[lane + 64]);
}

// ---------------------------------------------------------------------------
extern "C" void kernel_launch(void* const* d_in, const int* in_sizes, int n_in,
                              void* d_out, int out_size) {
    const float* x         = (const float*)d_in[0];
    const float* attn_mask = (const float*)d_in[1];
    const float* g1        = (const float*)d_in[2];
    const float* b1        = (const float*)d_in[3];
    const float* qkv_w     = (const float*)d_in[4];
    const float* qkv_b     = (const float*)d_in[5];
    const float* rpb_table = (const float*)d_in[6];
    const float* proj_w    = (const float*)d_in[7];
    const float* proj_b    = (const float*)d_in[8];
    const float* g2        = (const float*)d_in[9];
    const float* b2        = (const float*)d_in[10];
    const float* fc1_w     = (const float*)d_in[11];
    const float* fc1_b     = (const float*)d_in[12];
    const float* fc2_w     = (const float*)d_in[13];
    const float* fc2_b     = (const float*)d_in[14];
    float* out = (float*)d_out;

    bf16 *p_xwh, *p_qkvh, *p_attnh, *p_h, *p_wh;
    float *p_xw, *p_xres;
    cudaGetSymbolAddress((void**)&p_xwh,   g_xwh);
    cudaGetSymbolAddress((void**)&p_qkvh,  g_qkvh);
    cudaGetSymbolAddress((void**)&p_attnh, g_attnh);
    cudaGetSymbolAddress((void**)&p_h,     g_h);
    cudaGetSymbolAddress((void**)&p_wh,    g_wh);
    cudaGetSymbolAddress((void**)&p_xw,    g_xw);
    cudaGetSymbolAddress((void**)&p_xres,  g_xres);

    const int attn_smem = SMEM_ATTN_BF * 2;          // 48.96 KB
    cudaFuncSetAttribute(attn_kernel, cudaFuncAttributeMaxDynamicSharedMemorySize, attn_smem);

    conv_weights<<<432, 256>>>(qkv_w, proj_w, fc1_w, fc2_w);

    size_t nbias = (size_t)NW_PB * HEADS * 4802;
    bias_precompute<<<(unsigned)((nbias + 255) / 256), 256>>>(rpb_table, attn_mask);

    ln1_shift_win<<<NTOK / 4, 128>>>(x, g1, b1);

    // QKV gemm (M, 288, 96) -> bf16
    mma_gemm<0,1><<<dim3(288 / 96, NTOK / 64), 256>>>(
        p_xwh, p_wh, qkv_b, nullptr, p_qkvh, NTOK, 288, 96);

    attn_kernel<<<NWIN * HEADS, 256, attn_smem>>>();

    // proj gemm (M, 96, 96) -> fp32 g_xw
    mma_gemm<0,0><<<dim3(1, NTOK / 64), 256>>>(
        p_attnh, p_wh + 27648, proj_b, nullptr, p_xw, NTOK, 96, 96);

    residual_ln2<<<NTOK / 4, 128>>>(x, g2, b2);

    // fc1 + gelu (M, 384, 96) -> bf16 h
    mma_gemm<1,1><<<dim3(HID / 96, NTOK / 64), 256>>>(
        p_xwh, p_wh + 36864, fc1_b, nullptr, p_h, NTOK, HID, 96);

    // fc2 + residual (M, 96, 384) -> fp32 d_out
    mma_gemm<2,0><<<dim3(1, NTOK / 64), 256>>>(
        p_h, p_wh + 73728, fc2_b, p_xres, out, NTOK, 96, HID);
}

// round 11
// speedup vs baseline: 3.1184x; 1.0704x over previous
#include <cuda_runtime.h>
#include <cuda_bf16.h>
#include <cstdint>
#include <math.h>

// ---------------------------------------------------------------------------
// Swin Transformer 3D block — round 11: remove the 29.5M-thread
// bias_precompute (R6 self-inflicted elephant).  Bias = rpb+mask combined
// on-the-fly in attn from two small bf16 tables.  GEMM v3 + bf16 mma
// attention otherwise identical to the passing round-10 build.
// ---------------------------------------------------------------------------

#define NTOK   401408
#define CDIM   96
#define NWIN   4096
#define NW_PB  2048
#define NTOKW  98
#define HEADS  3
#define HDIM   32
#define SCALE  0.17677669529663687f
#define HID    384

typedef __nv_bfloat16 bf16;
typedef __nv_bfloat162 bf162;

// -------------------------- device scratch ---------------------------------
__device__ bf16  g_xwh  [(size_t)NTOK * CDIM];
__device__ bf16  g_qkvh [(size_t)NTOK * 288];
__device__ bf16  g_attnh[(size_t)NTOK * CDIM];
__device__ bf16  g_h    [(size_t)NTOK * HID];
__device__ float g_xw   [(size_t)NTOK * CDIM];
__device__ float g_xres [(size_t)NTOK * CDIM];
__device__ bf16  g_rpbh [HEADS * NTOKW * NTOKW];        // 57.6 KB, L2-resident
__device__ bf16  g_maskh[(size_t)NW_PB * NTOKW * NTOKW]; // 39 MB
__device__ bf16  g_wh   [110592];

// ---------------------------------------------------------------------------
// weight conversion (qkv 27648 | proj 9216 | fc1 36864 | fc2 36864)
// ---------------------------------------------------------------------------
__global__ void conv_weights(const float* __restrict__ qkv_w,
                             const float* __restrict__ proj_w,
                             const float* __restrict__ fc1_w,
                             const float* __restrict__ fc2_w) {
    int idx = blockIdx.x * 256 + threadIdx.x;       // 110592 total, exact
    const float* src; int off;
    if (idx < 27648)       { src = qkv_w;  off = idx; }
    else if (idx < 36864)  { src = proj_w; off = idx - 27648; }
    else if (idx < 73728)  { src = fc1_w;  off = idx - 36864; }
    else                   { src = fc2_w;  off = idx - 73728; }
    g_wh[idx] = __float2bfloat16(src[off]);
}

// ---------------------------------------------------------------------------
// expand relative-position-bias table -> bf16 (3, 98, 98).  28812 threads.
// ---------------------------------------------------------------------------
__global__ void rpb_expand(const float* __restrict__ table) {
    int idx = blockIdx.x * 256 + threadIdx.x;
    if (idx >= HEADS * NTOKW * NTOKW) return;
    int head = idx / (NTOKW * NTOKW);
    int r = idx % (NTOKW * NTOKW);
    int i = r / NTOKW, j = r % NTOKW;
    int zdi = i / 49, zhi = (i / 7) % 7, zwi = i % 7;
    int zdj = j / 49, zhj = (j / 7) % 7, zwj = j % 7;
    int ridx = (zdi - zdj + 1) * 169 + (zhi - zhj + 6) * 13 + (zwi - zwj + 6);
    g_rpbh[idx] = __float2bfloat16(table[ridx * 3 + head]);
}

// ---------------------------------------------------------------------------
// mask fp32 -> bf16, float4 vectorized.  2048*9604/4 = 4,917,248 threads.
// ---------------------------------------------------------------------------
__global__ void mask_conv(const float* __restrict__ mask) {
    int idx = blockIdx.x * 256 + threadIdx.x;        // 19208 blocks, exact
    float4 m = *(const float4*)&mask[(size_t)idx * 4];
    bf162 lo = __floats2bfloat162_rn(m.x, m.y);
    bf162 hi = __floats2bfloat162_rn(m.z, m.w);
    uint2 pk = make_uint2(*(uint32_t*)&lo, *(uint32_t*)&hi);
    *(uint2*)&g_maskh[(size_t)idx * 4] = pk;
}

// ---------------------------------------------------------------------------
// LN1 + cyclic shift + window partition -> bf16.  One warp per token.
// ---------------------------------------------------------------------------
__global__ void ln1_shift_win(const float* __restrict__ x,
                              const float* __restrict__ g,
                              const float* __restrict__ b) {
    int t    = blockIdx.x * 4 + (threadIdx.x >> 5);
    int lane = threadIdx.x & 31;
    int win = t / NTOKW, n = t % NTOKW;
    int bb  = win >> 11;
    int rem = win & 2047;
    int wd = rem >> 8, wh = (rem >> 4) & 15, ww = rem & 15;
    int zd = n / 49, r2 = n % 49, zh = r2 / 7, zw = r2 % 7;
    int sd = (wd * 2 + zd + 1) & 15;
    int sh = wh * 7 + zh + 3; if (sh >= 112) sh -= 112;
    int sw = ww * 7 + zw + 3; if (sw >= 112) sw -= 112;
    const float* px = x + ((((size_t)bb * 16 + sd) * 112 + sh) * 112 + sw) * CDIM;
    float v0 = px[lane], v1 = px[lane + 32], v2 = px[lane + 64];
    float s  = v0 + v1 + v2;
    float ss = v0 * v0 + v1 * v1 + v2 * v2;
    #pragma unroll
    for (int o = 16; o; o >>= 1) {
        s  += __shfl_xor_sync(0xFFFFFFFFu, s, o);
        ss += __shfl_xor_sync(0xFFFFFFFFu, ss, o);
    }
    float mu   = s * (1.0f / 96.0f);
    float var  = ss * (1.0f / 96.0f) - mu * mu;
    float rstd = rsqrtf(var + 1e-5f);
    bf16* po = g_xwh + (size_t)t * CDIM;
    po[lane]      = __float2bfloat16((v0 - mu) * rstd * g[lane]      + b[lane]);
    po[lane + 32] = __float2bfloat16((v1 - mu) * rstd * g[lane + 32] + b[lane + 32]);
    po[lane + 64] = __float2bfloat16((v2 - mu) * rstd * g[lane + 64] + b[lane + 64]);
}

// ---------------------------------------------------------------------------
__device__ __forceinline__ void mma_bf16(float c[4], const uint32_t a[4],
                                         uint32_t b0, uint32_t b1) {
    asm volatile(
        "mma.sync.aligned.m16n8k16.row.col.f32.bf16.bf16.f32 "
        "{%0,%1,%2,%3}, {%4,%5,%6,%7}, {%8,%9}, {%0,%1,%2,%3};"
        : "+f"(c[0]), "+f"(c[1]), "+f"(c[2]), "+f"(c[3])
        : "r"(a[0]), "r"(a[1]), "r"(a[2]), "r"(a[3]), "r"(b0), "r"(b1));
}
__device__ __forceinline__ void cp_async16(uint32_t smem_addr, const void* gptr) {
    asm volatile("cp.async.ca.shared.global [%0], [%1], 16;"
                 :: "r"(smem_addr), "l"(gptr));
}
__device__ __forceinline__ void cp_commit() {
    asm volatile("cp.async.commit_group;" ::: "memory");
}
template<int N>
__device__ __forceinline__ void cp_wait() {
    asm volatile("cp.async.wait_group %0;" :: "n"(N) : "memory");
}

// ---------------------------------------------------------------------------
// GEMM v3: BM=64, BN=96, BK=32, 2-stage cp.async pipeline, 256 thr / 8 warps
//   warp tile 32x24 (warpM=w&1, warpN=w>>1).  2 blocks/SM.
//   EPI: 0=bias, 1=bias+gelu, 2=bias+res.  OUTB: 1 -> bf16 out, 0 -> fp32.
// ---------------------------------------------------------------------------
#define GLD  40                 // smem leading dim (bf16), 32 + 8 pad
#define STG  ((64 + 96) * GLD)  // bf16 units per stage = 6400

template<int EPI, int OUTB>
__global__ __launch_bounds__(256, 2)
void mma_gemm(const bf16* __restrict__ A, const bf16* __restrict__ B,
              const float* __restrict__ bias, const float* __restrict__ res,
              void* __restrict__ Cv, int M, int N, int K) {
    __shared__ bf16 sh[2 * STG];          // 25.6 KB

    int tid  = threadIdx.x;
    int w    = tid >> 5;
    int lane = tid & 31;
    int g    = lane >> 2;
    int tg   = lane & 3;
    int warpM = w & 1;
    int warpN = w >> 1;
    int m0 = blockIdx.y * 64;
    int n0 = blockIdx.x * 96;

    int ar = tid >> 2, ac = tid & 3;
    int br0 = tid >> 2, bc0 = tid & 3;
    int bi1 = 256 + tid;
    int br1 = bi1 >> 2, bc1 = bi1 & 3;

    uint32_t sbase = (uint32_t)__cvta_generic_to_shared(sh);

    float acc[2][3][4];
    #pragma unroll
    for (int i = 0; i < 2; i++)
        #pragma unroll
        for (int j = 0; j < 3; j++)
            #pragma unroll
            for (int t = 0; t < 4; t++) acc[i][j][t] = 0.0f;

    int KC = K >> 5;

    {
        cp_async16(sbase + (ar * GLD + ac * 8) * 2,
                   &A[(size_t)(m0 + ar) * K + ac * 8]);
        cp_async16(sbase + ((64 + br0) * GLD + bc0 * 8) * 2,
                   &B[(size_t)(n0 + br0) * K + bc0 * 8]);
        if (tid < 128)
            cp_async16(sbase + ((64 + br1) * GLD + bc1 * 8) * 2,
                       &B[(size_t)(n0 + br1) * K + bc1 * 8]);
        cp_commit();
    }

    for (int kc = 0; kc < KC; kc++) {
        if (kc + 1 < KC) {
            int k0 = (kc + 1) << 5;
            uint32_t sb = sbase + ((kc + 1) & 1) * STG * 2;
            cp_async16(sb + (ar * GLD + ac * 8) * 2,
                       &A[(size_t)(m0 + ar) * K + k0 + ac * 8]);
            cp_async16(sb + ((64 + br0) * GLD + bc0 * 8) * 2,
                       &B[(size_t)(n0 + br0) * K + k0 + bc0 * 8]);
            if (tid < 128)
                cp_async16(sb + ((64 + br1) * GLD + bc1 * 8) * 2,
                           &B[(size_t)(n0 + br1) * K + k0 + bc1 * 8]);
            cp_commit();
            cp_wait<1>();
        } else {
            cp_wait<0>();
        }
        __syncthreads();

        const bf16* As = sh + (kc & 1) * STG;
        const bf16* Bs = As + 64 * GLD;

        #pragma unroll
        for (int ks = 0; ks < 2; ks++) {
            uint32_t afr[2][4];
            #pragma unroll
            for (int mt = 0; mt < 2; mt++) {
                const uint32_t* ap = (const uint32_t*)
                    (As + (warpM * 32 + mt * 16 + g) * GLD + ks * 16 + tg * 2);
                afr[mt][0] = ap[0];
                afr[mt][1] = ap[8 * (GLD / 2)];
                afr[mt][2] = ap[4];
                afr[mt][3] = ap[8 * (GLD / 2) + 4];
            }
            #pragma unroll
            for (int nt = 0; nt < 3; nt++) {
                const uint32_t* bp = (const uint32_t*)
                    (Bs + (warpN * 24 + nt * 8 + g) * GLD + ks * 16 + tg * 2);
                uint32_t b0 = bp[0], b1 = bp[4];
                #pragma unroll
                for (int mt = 0; mt < 2; mt++)
                    mma_bf16(acc[mt][nt], afr[mt], b0, b1);
            }
        }
        __syncthreads();
    }

    #pragma unroll
    for (int mt = 0; mt < 2; mt++) {
        int r0 = m0 + warpM * 32 + mt * 16 + g;
        #pragma unroll
        for (int nt = 0; nt < 3; nt++) {
            int c0 = n0 + warpN * 24 + nt * 8 + tg * 2;
            float bs0 = bias[c0], bs1 = bias[c0 + 1];
            float v0 = acc[mt][nt][0] + bs0;
            float v1 = acc[mt][nt][1] + bs1;
            float v2 = acc[mt][nt][2] + bs0;
            float v3 = acc[mt][nt][3] + bs1;
            if (EPI == 1) {
                v0 = 0.5f * v0 * (1.0f + erff(v0 * 0.70710678118654752f));
                v1 = 0.5f * v1 * (1.0f + erff(v1 * 0.70710678118654752f));
                v2 = 0.5f * v2 * (1.0f + erff(v2 * 0.70710678118654752f));
                v3 = 0.5f * v3 * (1.0f + erff(v3 * 0.70710678118654752f));
            }
            if (EPI == 2) {
                const float* rp0 = &res[(size_t)r0 * N + c0];
                const float* rp1 = &res[(size_t)(r0 + 8) * N + c0];
                v0 += rp0[0]; v1 += rp0[1];
                v2 += rp1[0]; v3 += rp1[1];
            }
            if (OUTB) {
                bf16* C = (bf16*)Cv;
                *(bf162*)&C[(size_t)r0 * N + c0]       = __floats2bfloat162_rn(v0, v1);
                *(bf162*)&C[(size_t)(r0 + 8) * N + c0] = __floats2bfloat162_rn(v2, v3);
            } else {
                float* C = (float*)Cv;
                *(float2*)&C[(size_t)r0 * N + c0]       = make_float2(v0, v1);
                *(float2*)&C[(size_t)(r0 + 8) * N + c0] = make_float2(v2, v3);
            }
        }
    }
}

// ---------------------------------------------------------------------------
// Tensor-core attention.  P init combines mask+rpb bf16 tables on the fly
// (coalesced: pair index u maps to element offset 2u = i*98 + 2c exactly).
// ---------------------------------------------------------------------------
#define QLD 36
#define KLD 36
#define VLD 116
#define PLD 116
#define SMEM_ATTN_BF 24480

__global__ __launch_bounds__(256)
void attn_kernel() {
    int wh   = blockIdx.x;
    int win  = wh / HEADS, head = wh % HEADS;
    int mw   = win & (NW_PB - 1);
    extern __shared__ bf16 smh[];
    bf16* Qs = smh;
    bf16* Ks = smh + 4032;
    bf16* Vt = smh + 7776;
    bf16* P  = smh + 11488;
    int tid  = threadIdx.x;
    int w    = tid >> 5;
    int lane = tid & 31;
    int g    = lane >> 2;
    int tg   = lane & 3;
    bf16 Z = __float2bfloat16(0.0f);

    const bf16* qkv = g_qkvh + (size_t)win * NTOKW * 288 + head * HDIM;
    for (int idx = tid; idx < 112 * 32; idx += 256) {
        int n = idx >> 5, d = idx & 31;
        Qs[n * QLD + d] = (n < NTOKW) ? qkv[n * 288 + d] : Z;
    }
    for (int idx = tid; idx < 104 * 32; idx += 256) {
        int n = idx >> 5, d = idx & 31;
        Ks[n * KLD + d] = (n < NTOKW) ? qkv[n * 288 + 96 + d] : Z;
    }
    for (int idx = tid; idx < 112 * 32; idx += 256) {
        int n = idx >> 5, d = idx & 31;
        Vt[d * VLD + n] = (n < NTOKW) ? qkv[n * 288 + 192 + d] : Z;
    }
    // S init = mask + rpb (rows < 98, cols < 98) + zero pad cols 98..111
    {
        const uint32_t* mp = (const uint32_t*)(g_maskh + (size_t)mw * 9604);
        const uint32_t* rp = (const uint32_t*)(g_rpbh + head * 9604);
        uint32_t* Pu = (uint32_t*)P;
        for (int u = tid; u < 4802; u += 256) {
            int i = u / 49, c = u % 49;
            uint32_t mv = mp[u], rv = rp[u];
            bf162 sum = __hadd2(*(bf162*)&mv, *(bf162*)&rv);
            Pu[i * (PLD / 2) + c] = *(uint32_t*)&sum;
        }
        for (int u = tid; u < 98 * 7; u += 256) {
            int i = u / 7, c = 49 + u % 7;
            Pu[i * (PLD / 2) + c] = 0;
        }
    }
    __syncthreads();

    int row0 = w * 16;
    if (w < 7) {
        #pragma unroll
        for (int h2 = 0; h2 < 2; h2++) {
            int ntbase = h2 * 7;
            int NT = h2 ? 6 : 7;
            float acc[7][4];
            #pragma unroll
            for (int t = 0; t < 7; t++)
                #pragma unroll
                for (int q = 0; q < 4; q++) acc[t][q] = 0.0f;
            #pragma unroll
            for (int ks = 0; ks < 2; ks++) {
                uint32_t afr[4];
                const uint32_t* ap = (const uint32_t*)
                    (Qs + (row0 + g) * QLD + ks * 16 + tg * 2);
                afr[0] = ap[0];
                afr[1] = ap[8 * (QLD / 2)];
                afr[2] = ap[4];
                afr[3] = ap[8 * (QLD / 2) + 4];
                for (int t = 0; t < NT; t++) {
                    int n = (ntbase + t) * 8 + g;
                    const uint32_t* bp = (const uint32_t*)
                        (Ks + n * KLD + ks * 16 + tg * 2);
                    mma_bf16(acc[t], afr, bp[0], bp[4]);
                }
            }
            for (int t = 0; t < NT; t++) {
                int c0 = (ntbase + t) * 8 + tg * 2;
                bf162* p0 = (bf162*)(P + (row0 + g) * PLD + c0);
                bf162* p1 = (bf162*)(P + (row0 + g + 8) * PLD + c0);
                float2 f0 = __bfloat1622float2(*p0);
                float2 f1 = __bfloat1622float2(*p1);
                *p0 = __floats2bfloat162_rn(acc[t][0] * SCALE + f0.x,
                                            acc[t][1] * SCALE + f0.y);
                *p1 = __floats2bfloat162_rn(acc[t][2] * SCALE + f1.x,
                                            acc[t][3] * SCALE + f1.y);
            }
        }
    }
    __syncthreads();

    for (int r = w; r < NTOKW; r += 8) {
        bf16* prow = P + r * PLD;
        float m = -1e30f;
        for (int j = lane; j < NTOKW; j += 32)
            m = fmaxf(m, __bfloat162float(prow[j]));
        #pragma unroll
        for (int o = 16; o; o >>= 1) m = fmaxf(m, __shfl_xor_sync(0xFFFFFFFFu, m, o));
        float s = 0.0f;
        for (int j = lane; j < NTOKW; j += 32) {
            float e = __expf(__bfloat162float(prow[j]) - m);
            prow[j] = __float2bfloat16(e);
            s += e;
        }
        #pragma unroll
        for (int o = 16; o; o >>= 1) s += __shfl_xor_sync(0xFFFFFFFFu, s, o);
        float inv = 1.0f / s;
        for (int j = lane; j < NTOKW; j += 32)
            prow[j] = __float2bfloat16(__bfloat162float(prow[j]) * inv);
    }
    __syncthreads();

    if (w < 7) {
        float acc[4][4];
        #pragma unroll
        for (int t = 0; t < 4; t++)
            #pragma unroll
            for (int q = 0; q < 4; q++) acc[t][q] = 0.0f;
        #pragma unroll
        for (int ks = 0; ks < 7; ks++) {
            uint32_t afr[4];
            const uint32_t* ap = (const uint32_t*)
                (P + (row0 + g) * PLD + ks * 16 + tg * 2);
            afr[0] = ap[0];
            afr[1] = ap[8 * (PLD / 2)];
            afr[2] = ap[4];
            afr[3] = ap[8 * (PLD / 2) + 4];
            #pragma unroll
            for (int nt = 0; nt < 4; nt++) {
                const uint32_t* bp = (const uint32_t*)
                    (Vt + (nt * 8 + g) * VLD + ks * 16 + tg * 2);
                mma_bf16(acc[nt], afr, bp[0], bp[4]);
            }
        }
        int r = row0 + g;
        size_t obase = ((size_t)win * NTOKW + r) * CDIM + head * HDIM;
        #pragma unroll
        for (int nt = 0; nt < 4; nt++) {
            int c0 = nt * 8 + tg * 2;
            if (r < NTOKW)
                *(bf162*)&g_attnh[obase + c0] =
                    __floats2bfloat162_rn(acc[nt][0], acc[nt][1]);
            if (r + 8 < NTOKW)
                *(bf162*)&g_attnh[obase + 8 * CDIM + c0] =
                    __floats2bfloat162_rn(acc[nt][2], acc[nt][3]);
        }
    }
}

// ---------------------------------------------------------------------------
__global__ void residual_ln2(const float* __restrict__ x,
                             const float* __restrict__ g,
                             const float* __restrict__ b) {
    int t    = blockIdx.x * 4 + (threadIdx.x >> 5);
    int lane = threadIdx.x & 31;
    int w = t % 112; int r = t / 112;
    int h = r % 112; r /= 112;
    int d = r % 16;  int bb = r / 16;
    int sd = d - 1; if (sd < 0) sd += 16;
    int sh = h - 3; if (sh < 0) sh += 112;
    int sw = w - 3; if (sw < 0) sw += 112;
    int win = ((bb * 8 + (sd >> 1)) * 16 + sh / 7) * 16 + sw / 7;
    int n   = ((sd & 1) * 7 + sh % 7) * 7 + sw % 7;
    const float* pp = g_xw + ((size_t)win * NTOKW + n) * CDIM;
    const float* px = x + (size_t)t * CDIM;
    float v0 = px[lane]      + pp[lane];
    float v1 = px[lane + 32] + pp[lane + 32];
    float v2 = px[lane + 64] + pp[lane + 64];
    float* pr = g_xres + (size_t)t * CDIM;
    pr[lane] = v0; pr[lane + 32] = v1; pr[lane + 64] = v2;
    float s  = v0 + v1 + v2;
    float ss = v0 * v0 + v1 * v1 + v2 * v2;
    #pragma unroll
    for (int o = 16; o; o >>= 1) {
        s  += __shfl_xor_sync(0xFFFFFFFFu, s, o);
        ss += __shfl_xor_sync(0xFFFFFFFFu, ss, o);
    }
    float mu   = s * (1.0f / 96.0f);
    float var  = ss * (1.0f / 96.0f) - mu * mu;
    float rstd = rsqrtf(var + 1e-5f);
    bf16* po = g_xwh + (size_t)t * CDIM;
    po[lane]      = __float2bfloat16((v0 - mu) * rstd * g[lane]      + b[lane]);
    po[lane + 32] = __float2bfloat16((v1 - mu) * rstd * g[lane + 32] + b[lane + 32]);
    po[lane + 64] = __float2bfloat16((v2 - mu) * rstd * g[lane + 64] + b[lane + 64]);
}

// ---------------------------------------------------------------------------
extern "C" void kernel_launch(void* const* d_in, const int* in_sizes, int n_in,
                              void* d_out, int out_size) {
    const float* x         = (const float*)d_in[0];
    const float* attn_mask = (const float*)d_in[1];
    const float* g1        = (const float*)d_in[2];
    const float* b1        = (const float*)d_in[3];
    const float* qkv_w     = (const float*)d_in[4];
    const float* qkv_b     = (const float*)d_in[5];
    const float* rpb_table = (const float*)d_in[6];
    const float* proj_w    = (const float*)d_in[7];
    const float* proj_b    = (const float*)d_in[8];
    const float* g2        = (const float*)d_in[9];
    const float* b2        = (const float*)d_in[10];
    const float* fc1_w     = (const float*)d_in[11];
    const float* fc1_b     = (const float*)d_in[12];
    const float* fc2_w     = (const float*)d_in[13];
    const float* fc2_b     = (const float*)d_in[14];
    float* out = (float*)d_out;

    bf16 *p_xwh, *p_qkvh, *p_attnh, *p_h, *p_wh;
    float *p_xw, *p_xres;
    cudaGetSymbolAddress((void**)&p_xwh,   g_xwh);
    cudaGetSymbolAddress((void**)&p_qkvh,  g_qkvh);
    cudaGetSymbolAddress((void**)&p_attnh, g_attnh);
    cudaGetSymbolAddress((void**)&p_h,     g_h);
    cudaGetSymbolAddress((void**)&p_wh,    g_wh);
    cudaGetSymbolAddress((void**)&p_xw,    g_xw);
    cudaGetSymbolAddress((void**)&p_xres,  g_xres);

    const int attn_smem = SMEM_ATTN_BF * 2;          // 48.96 KB
    cudaFuncSetAttribute(attn_kernel, cudaFuncAttributeMaxDynamicSharedMemorySize, attn_smem);

    conv_weights<<<432, 256>>>(qkv_w, proj_w, fc1_w, fc2_w);
    rpb_expand<<<(HEADS * NTOKW * NTOKW + 255) / 256, 256>>>(rpb_table);
    mask_conv<<<(NW_PB * NTOKW * NTOKW) / (4 * 256), 256>>>(attn_mask);

    ln1_shift_win<<<NTOK / 4, 128>>>(x, g1, b1);

    // QKV gemm (M, 288, 96) -> bf16
    mma_gemm<0,1><<<dim3(288 / 96, NTOK / 64), 256>>>(
        p_xwh, p_wh, qkv_b, nullptr, p_qkvh, NTOK, 288, 96);

    attn_kernel<<<NWIN * HEADS, 256, attn_smem>>>();

    // proj gemm (M, 96, 96) -> fp32 g_xw
    mma_gemm<0,0><<<dim3(1, NTOK / 64), 256>>>(
        p_attnh, p_wh + 27648, proj_b, nullptr, p_xw, NTOK, 96, 96);

    residual_ln2<<<NTOK / 4, 128>>>(x, g2, b2);

    // fc1 + gelu (M, 384, 96) -> bf16 h
    mma_gemm<1,1><<<dim3(HID / 96, NTOK / 64), 256>>>(
        p_xwh, p_wh + 36864, fc1_b, nullptr, p_h, NTOK, HID, 96);

    // fc2 + residual (M, 96, 384) -> fp32 d_out
    mma_gemm<2,0><<<dim3(1, NTOK / 64), 256>>>(
        p_h, p_wh + 73728, fc2_b, p_xres, out, NTOK, 96, HID);
}

// round 12
// speedup vs baseline: 3.4821x; 1.1166x over previous
#include <cuda_runtime.h>
#include <cuda_bf16.h>
#include <cstdint>
#include <math.h>

// ---------------------------------------------------------------------------
// Swin Transformer 3D block — round 12:
//   (1) proj GEMM fused with window-reverse residual + LN2 (residual_ln2 gone)
//   (2) attn Q/K/V global loads vectorized (uint2)
//   GEMM v3 pipeline + bf16 mma attention otherwise as round 11.
// ---------------------------------------------------------------------------

#define NTOK   401408
#define CDIM   96
#define NWIN   4096
#define NW_PB  2048
#define NTOKW  98
#define HEADS  3
#define HDIM   32
#define SCALE  0.17677669529663687f
#define HID    384

typedef __nv_bfloat16 bf16;
typedef __nv_bfloat162 bf162;

// -------------------------- device scratch ---------------------------------
__device__ bf16  g_xwh  [(size_t)NTOK * CDIM];
__device__ bf16  g_qkvh [(size_t)NTOK * 288];
__device__ bf16  g_attnh[(size_t)NTOK * CDIM];
__device__ bf16  g_h    [(size_t)NTOK * HID];
__device__ float g_xres [(size_t)NTOK * CDIM];
__device__ bf16  g_rpbh [HEADS * NTOKW * NTOKW];
__device__ bf16  g_maskh[(size_t)NW_PB * NTOKW * NTOKW];
__device__ bf16  g_wh   [110592];

// ---------------------------------------------------------------------------
__global__ void conv_weights(const float* __restrict__ qkv_w,
                             const float* __restrict__ proj_w,
                             const float* __restrict__ fc1_w,
                             const float* __restrict__ fc2_w) {
    int idx = blockIdx.x * 256 + threadIdx.x;       // 110592 total, exact
    const float* src; int off;
    if (idx < 27648)       { src = qkv_w;  off = idx; }
    else if (idx < 36864)  { src = proj_w; off = idx - 27648; }
    else if (idx < 73728)  { src = fc1_w;  off = idx - 36864; }
    else                   { src = fc2_w;  off = idx - 73728; }
    g_wh[idx] = __float2bfloat16(src[off]);
}

// ---------------------------------------------------------------------------
__global__ void rpb_expand(const float* __restrict__ table) {
    int idx = blockIdx.x * 256 + threadIdx.x;
    if (idx >= HEADS * NTOKW * NTOKW) return;
    int head = idx / (NTOKW * NTOKW);
    int r = idx % (NTOKW * NTOKW);
    int i = r / NTOKW, j = r % NTOKW;
    int zdi = i / 49, zhi = (i / 7) % 7, zwi = i % 7;
    int zdj = j / 49, zhj = (j / 7) % 7, zwj = j % 7;
    int ridx = (zdi - zdj + 1) * 169 + (zhi - zhj + 6) * 13 + (zwi - zwj + 6);
    g_rpbh[idx] = __float2bfloat16(table[ridx * 3 + head]);
}

// ---------------------------------------------------------------------------
__global__ void mask_conv(const float* __restrict__ mask) {
    int idx = blockIdx.x * 256 + threadIdx.x;        // 19208 blocks, exact
    float4 m = *(const float4*)&mask[(size_t)idx * 4];
    bf162 lo = __floats2bfloat162_rn(m.x, m.y);
    bf162 hi = __floats2bfloat162_rn(m.z, m.w);
    uint2 pk = make_uint2(*(uint32_t*)&lo, *(uint32_t*)&hi);
    *(uint2*)&g_maskh[(size_t)idx * 4] = pk;
}

// ---------------------------------------------------------------------------
__global__ void ln1_shift_win(const float* __restrict__ x,
                              const float* __restrict__ g,
                              const float* __restrict__ b) {
    int t    = blockIdx.x * 4 + (threadIdx.x >> 5);
    int lane = threadIdx.x & 31;
    int win = t / NTOKW, n = t % NTOKW;
    int bb  = win >> 11;
    int rem = win & 2047;
    int wd = rem >> 8, wh = (rem >> 4) & 15, ww = rem & 15;
    int zd = n / 49, r2 = n % 49, zh = r2 / 7, zw = r2 % 7;
    int sd = (wd * 2 + zd + 1) & 15;
    int sh = wh * 7 + zh + 3; if (sh >= 112) sh -= 112;
    int sw = ww * 7 + zw + 3; if (sw >= 112) sw -= 112;
    const float* px = x + ((((size_t)bb * 16 + sd) * 112 + sh) * 112 + sw) * CDIM;
    float v0 = px[lane], v1 = px[lane + 32], v2 = px[lane + 64];
    float s  = v0 + v1 + v2;
    float ss = v0 * v0 + v1 * v1 + v2 * v2;
    #pragma unroll
    for (int o = 16; o; o >>= 1) {
        s  += __shfl_xor_sync(0xFFFFFFFFu, s, o);
        ss += __shfl_xor_sync(0xFFFFFFFFu, ss, o);
    }
    float mu   = s * (1.0f / 96.0f);
    float var  = ss * (1.0f / 96.0f) - mu * mu;
    float rstd = rsqrtf(var + 1e-5f);
    bf16* po = g_xwh + (size_t)t * CDIM;
    po[lane]      = __float2bfloat16((v0 - mu) * rstd * g[lane]      + b[lane]);
    po[lane + 32] = __float2bfloat16((v1 - mu) * rstd * g[lane + 32] + b[lane + 32]);
    po[lane + 64] = __float2bfloat16((v2 - mu) * rstd * g[lane + 64] + b[lane + 64]);
}

// ---------------------------------------------------------------------------
__device__ __forceinline__ void mma_bf16(float c[4], const uint32_t a[4],
                                         uint32_t b0, uint32_t b1) {
    asm volatile(
        "mma.sync.aligned.m16n8k16.row.col.f32.bf16.bf16.f32 "
        "{%0,%1,%2,%3}, {%4,%5,%6,%7}, {%8,%9}, {%0,%1,%2,%3};"
        : "+f"(c[0]), "+f"(c[1]), "+f"(c[2]), "+f"(c[3])
        : "r"(a[0]), "r"(a[1]), "r"(a[2]), "r"(a[3]), "r"(b0), "r"(b1));
}
__device__ __forceinline__ void cp_async16(uint32_t smem_addr, const void* gptr) {
    asm volatile("cp.async.ca.shared.global [%0], [%1], 16;"
                 :: "r"(smem_addr), "l"(gptr));
}
__device__ __forceinline__ void cp_commit() {
    asm volatile("cp.async.commit_group;" ::: "memory");
}
template<int N>
__device__ __forceinline__ void cp_wait() {
    asm volatile("cp.async.wait_group %0;" :: "n"(N) : "memory");
}

// ---------------------------------------------------------------------------
// GEMM v3 (QKV / fc1 / fc2): BM=64, BN=96, BK=32, 2-stage cp.async, 8 warps.
//   EPI: 0=bias, 1=bias+gelu, 2=bias+res.  OUTB: 1 -> bf16 out, 0 -> fp32.
// ---------------------------------------------------------------------------
#define GLD  40                 // smem leading dim (bf16), 32 + 8 pad
#define STG  ((64 + 96) * GLD)  // bf16 units per stage = 6400

template<int EPI, int OUTB>
__global__ __launch_bounds__(256, 2)
void mma_gemm(const bf16* __restrict__ A, const bf16* __restrict__ B,
              const float* __restrict__ bias, const float* __restrict__ res,
              void* __restrict__ Cv, int M, int N, int K) {
    __shared__ bf16 sh[2 * STG];          // 25.6 KB

    int tid  = threadIdx.x;
    int w    = tid >> 5;
    int lane = tid & 31;
    int g    = lane >> 2;
    int tg   = lane & 3;
    int warpM = w & 1;
    int warpN = w >> 1;
    int m0 = blockIdx.y * 64;
    int n0 = blockIdx.x * 96;

    int ar = tid >> 2, ac = tid & 3;
    int br0 = tid >> 2, bc0 = tid & 3;
    int bi1 = 256 + tid;
    int br1 = bi1 >> 2, bc1 = bi1 & 3;

    uint32_t sbase = (uint32_t)__cvta_generic_to_shared(sh);

    float acc[2][3][4];
    #pragma unroll
    for (int i = 0; i < 2; i++)
        #pragma unroll
        for (int j = 0; j < 3; j++)
            #pragma unroll
            for (int t = 0; t < 4; t++) acc[i][j][t] = 0.0f;

    int KC = K >> 5;

    {
        cp_async16(sbase + (ar * GLD + ac * 8) * 2,
                   &A[(size_t)(m0 + ar) * K + ac * 8]);
        cp_async16(sbase + ((64 + br0) * GLD + bc0 * 8) * 2,
                   &B[(size_t)(n0 + br0) * K + bc0 * 8]);
        if (tid < 128)
            cp_async16(sbase + ((64 + br1) * GLD + bc1 * 8) * 2,
                       &B[(size_t)(n0 + br1) * K + bc1 * 8]);
        cp_commit();
    }

    for (int kc = 0; kc < KC; kc++) {
        if (kc + 1 < KC) {
            int k0 = (kc + 1) << 5;
            uint32_t sb = sbase + ((kc + 1) & 1) * STG * 2;
            cp_async16(sb + (ar * GLD + ac * 8) * 2,
                       &A[(size_t)(m0 + ar) * K + k0 + ac * 8]);
            cp_async16(sb + ((64 + br0) * GLD + bc0 * 8) * 2,
                       &B[(size_t)(n0 + br0) * K + k0 + bc0 * 8]);
            if (tid < 128)
                cp_async16(sb + ((64 + br1) * GLD + bc1 * 8) * 2,
                           &B[(size_t)(n0 + br1) * K + k0 + bc1 * 8]);
            cp_commit();
            cp_wait<1>();
        } else {
            cp_wait<0>();
        }
        __syncthreads();

        const bf16* As = sh + (kc & 1) * STG;
        const bf16* Bs = As + 64 * GLD;

        #pragma unroll
        for (int ks = 0; ks < 2; ks++) {
            uint32_t afr[2][4];
            #pragma unroll
            for (int mt = 0; mt < 2; mt++) {
                const uint32_t* ap = (const uint32_t*)
                    (As + (warpM * 32 + mt * 16 + g) * GLD + ks * 16 + tg * 2);
                afr[mt][0] = ap[0];
                afr[mt][1] = ap[8 * (GLD / 2)];
                afr[mt][2] = ap[4];
                afr[mt][3] = ap[8 * (GLD / 2) + 4];
            }
            #pragma unroll
            for (int nt = 0; nt < 3; nt++) {
                const uint32_t* bp = (const uint32_t*)
                    (Bs + (warpN * 24 + nt * 8 + g) * GLD + ks * 16 + tg * 2);
                uint32_t b0 = bp[0], b1 = bp[4];
                #pragma unroll
                for (int mt = 0; mt < 2; mt++)
                    mma_bf16(acc[mt][nt], afr[mt], b0, b1);
            }
        }
        __syncthreads();
    }

    #pragma unroll
    for (int mt = 0; mt < 2; mt++) {
        int r0 = m0 + warpM * 32 + mt * 16 + g;
        #pragma unroll
        for (int nt = 0; nt < 3; nt++) {
            int c0 = n0 + warpN * 24 + nt * 8 + tg * 2;
            float bs0 = bias[c0], bs1 = bias[c0 + 1];
            float v0 = acc[mt][nt][0] + bs0;
            float v1 = acc[mt][nt][1] + bs1;
            float v2 = acc[mt][nt][2] + bs0;
            float v3 = acc[mt][nt][3] + bs1;
            if (EPI == 1) {
                v0 = 0.5f * v0 * (1.0f + erff(v0 * 0.70710678118654752f));
                v1 = 0.5f * v1 * (1.0f + erff(v1 * 0.70710678118654752f));
                v2 = 0.5f * v2 * (1.0f + erff(v2 * 0.70710678118654752f));
                v3 = 0.5f * v3 * (1.0f + erff(v3 * 0.70710678118654752f));
            }
            if (EPI == 2) {
                const float* rp0 = &res[(size_t)r0 * N + c0];
                const float* rp1 = &res[(size_t)(r0 + 8) * N + c0];
                v0 += rp0[0]; v1 += rp0[1];
                v2 += rp1[0]; v3 += rp1[1];
            }
            if (OUTB) {
                bf16* C = (bf16*)Cv;
                *(bf162*)&C[(size_t)r0 * N + c0]       = __floats2bfloat162_rn(v0, v1);
                *(bf162*)&C[(size_t)(r0 + 8) * N + c0] = __floats2bfloat162_rn(v2, v3);
            } else {
                float* C = (float*)Cv;
                *(float2*)&C[(size_t)r0 * N + c0]       = make_float2(v0, v1);
                *(float2*)&C[(size_t)(r0 + 8) * N + c0] = make_float2(v2, v3);
            }
        }
    }
}

// ---------------------------------------------------------------------------
// proj GEMM fused with window-reverse residual + LN2.
//   A = g_attnh (window layout), B = proj weights, N=96 (one tile), K=96.
//   Epilogue: S[64][100] fp32 staging in the pipeline smem, then per-row
//   inverse-shift gather of x, xres = x + proj, LN2 -> g_xwh (both spatial).
// ---------------------------------------------------------------------------
__global__ __launch_bounds__(256, 2)
void proj_fused(const bf16* __restrict__ A, const bf16* __restrict__ B,
                const float* __restrict__ bias,
                const float* __restrict__ x,
                const float* __restrict__ g2v, const float* __restrict__ b2v,
                float* __restrict__ xres, bf16* __restrict__ xwh) {
    __shared__ bf16 sh[2 * STG];          // 25.6 KB; reused as fp32 S[64][100]
    const int K = 96;

    int tid  = threadIdx.x;
    int w    = tid >> 5;
    int lane = tid & 31;
    int g    = lane >> 2;
    int tg   = lane & 3;
    int warpM = w & 1;
    int warpN = w >> 1;
    int m0 = blockIdx.x * 64;

    int ar = tid >> 2, ac = tid & 3;
    int br0 = tid >> 2, bc0 = tid & 3;
    int bi1 = 256 + tid;
    int br1 = bi1 >> 2, bc1 = bi1 & 3;

    uint32_t sbase = (uint32_t)__cvta_generic_to_shared(sh);

    float acc[2][3][4];
    #pragma unroll
    for (int i = 0; i < 2; i++)
        #pragma unroll
        for (int j = 0; j < 3; j++)
            #pragma unroll
            for (int t = 0; t < 4; t++) acc[i][j][t] = 0.0f;

    {
        cp_async16(sbase + (ar * GLD + ac * 8) * 2,
                   &A[(size_t)(m0 + ar) * K + ac * 8]);
        cp_async16(sbase + ((64 + br0) * GLD + bc0 * 8) * 2,
                   &B[(size_t)br0 * K + bc0 * 8]);
        if (tid < 128)
            cp_async16(sbase + ((64 + br1) * GLD + bc1 * 8) * 2,
                       &B[(size_t)br1 * K + bc1 * 8]);
        cp_commit();
    }

    for (int kc = 0; kc < 3; kc++) {
        if (kc + 1 < 3) {
            int k0 = (kc + 1) << 5;
            uint32_t sb = sbase + ((kc + 1) & 1) * STG * 2;
            cp_async16(sb + (ar * GLD + ac * 8) * 2,
                       &A[(size_t)(m0 + ar) * K + k0 + ac * 8]);
            cp_async16(sb + ((64 + br0) * GLD + bc0 * 8) * 2,
                       &B[(size_t)br0 * K + k0 + bc0 * 8]);
            if (tid < 128)
                cp_async16(sb + ((64 + br1) * GLD + bc1 * 8) * 2,
                           &B[(size_t)br1 * K + k0 + bc1 * 8]);
            cp_commit();
            cp_wait<1>();
        } else {
            cp_wait<0>();
        }
        __syncthreads();

        const bf16* As = sh + (kc & 1) * STG;
        const bf16* Bs = As + 64 * GLD;

        #pragma unroll
        for (int ks = 0; ks < 2; ks++) {
            uint32_t afr[2][4];
            #pragma unroll
            for (int mt = 0; mt < 2; mt++) {
                const uint32_t* ap = (const uint32_t*)
                    (As + (warpM * 32 + mt * 16 + g) * GLD + ks * 16 + tg * 2);
                afr[mt][0] = ap[0];
                afr[mt][1] = ap[8 * (GLD / 2)];
                afr[mt][2] = ap[4];
                afr[mt][3] = ap[8 * (GLD / 2) + 4];
            }
            #pragma unroll
            for (int nt = 0; nt < 3; nt++) {
                const uint32_t* bp = (const uint32_t*)
                    (Bs + (warpN * 24 + nt * 8 + g) * GLD + ks * 16 + tg * 2);
                uint32_t b0 = bp[0], b1 = bp[4];
                #pragma unroll
                for (int mt = 0; mt < 2; mt++)
                    mma_bf16(acc[mt][nt], afr[mt], b0, b1);
            }
        }
        __syncthreads();
    }

    // stage proj+bias into smem fp32  S[64][100]  (25600 B == sizeof(sh))
    float* S = (float*)sh;
    #pragma unroll
    for (int mt = 0; mt < 2; mt++) {
        int rr = warpM * 32 + mt * 16 + g;
        #pragma unroll
        for (int nt = 0; nt < 3; nt++) {
            int c0 = warpN * 24 + nt * 8 + tg * 2;
            float bs0 = bias[c0], bs1 = bias[c0 + 1];
            S[rr * 100 + c0]            = acc[mt][nt][0] + bs0;
            S[rr * 100 + c0 + 1]        = acc[mt][nt][1] + bs1;
            S[(rr + 8) * 100 + c0]      = acc[mt][nt][2] + bs0;
            S[(rr + 8) * 100 + c0 + 1]  = acc[mt][nt][3] + bs1;
        }
    }
    __syncthreads();

    // per-row: gather x at the inverse-shift location, residual + LN2
    for (int rr = w; rr < 64; rr += 8) {
        int t = m0 + rr;
        int win = t / NTOKW, n = t % NTOKW;
        int bb  = win >> 11;
        int rem = win & 2047;
        int wd = rem >> 8, wh = (rem >> 4) & 15, ww = rem & 15;
        int zd = n / 49, r2 = n % 49, zh = r2 / 7, zw = r2 % 7;
        int sd = (wd * 2 + zd + 1) & 15;
        int shh = wh * 7 + zh + 3; if (shh >= 112) shh -= 112;
        int sww = ww * 7 + zw + 3; if (sww >= 112) sww -= 112;
        size_t sidx = (((size_t)bb * 16 + sd) * 112 + shh) * 112 + sww;
        const float* px = x + sidx * CDIM;
        const float* ps = S + rr * 100;
        float v0 = px[lane]      + ps[lane];
        float v1 = px[lane + 32] + ps[lane + 32];
        float v2 = px[lane + 64] + ps[lane + 64];
        float* pr = xres + sidx * CDIM;
        pr[lane] = v0; pr[lane + 32] = v1; pr[lane + 64] = v2;
        float s  = v0 + v1 + v2;
        float ss = v0 * v0 + v1 * v1 + v2 * v2;
        #pragma unroll
        for (int o = 16; o; o >>= 1) {
            s  += __shfl_xor_sync(0xFFFFFFFFu, s, o);
            ss += __shfl_xor_sync(0xFFFFFFFFu, ss, o);
        }
        float mu   = s * (1.0f / 96.0f);
        float var  = ss * (1.0f / 96.0f) - mu * mu;
        float rstd = rsqrtf(var + 1e-5f);
        bf16* po = xwh + sidx * CDIM;
        po[lane]      = __float2bfloat16((v0 - mu) * rstd * g2v[lane]      + b2v[lane]);
        po[lane + 32] = __float2bfloat16((v1 - mu) * rstd * g2v[lane + 32] + b2v[lane + 32]);
        po[lane + 64] = __float2bfloat16((v2 - mu) * rstd * g2v[lane + 64] + b2v[lane + 64]);
    }
}

// ---------------------------------------------------------------------------
// Tensor-core attention; vectorized uint2 Q/K/V global loads.
// ---------------------------------------------------------------------------
#define QLD 36
#define KLD 36
#define VLD 116
#define PLD 116
#define SMEM_ATTN_BF 24480

__global__ __launch_bounds__(256)
void attn_kernel() {
    int wh   = blockIdx.x;
    int win  = wh / HEADS, head = wh % HEADS;
    int mw   = win & (NW_PB - 1);
    extern __shared__ bf16 smh[];
    bf16* Qs = smh;
    bf16* Ks = smh + 4032;
    bf16* Vt = smh + 7776;
    bf16* P  = smh + 11488;
    int tid  = threadIdx.x;
    int w    = tid >> 5;
    int lane = tid & 31;
    int g    = lane >> 2;
    int tg   = lane & 3;
    uint2 Z2 = make_uint2(0u, 0u);

    const bf16* qkv = g_qkvh + (size_t)win * NTOKW * 288 + head * HDIM;
    // Q: 112x32 as uint2 (4 bf16) chunks: 112*8 = 896 jobs
    for (int idx = tid; idx < 112 * 8; idx += 256) {
        int n = idx >> 3, d4 = (idx & 7) * 4;
        uint2 val = (n < NTOKW) ? *(const uint2*)(qkv + n * 288 + d4) : Z2;
        *(uint2*)(Qs + n * QLD + d4) = val;
    }
    // K: 104x32
    for (int idx = tid; idx < 104 * 8; idx += 256) {
        int n = idx >> 3, d4 = (idx & 7) * 4;
        uint2 val = (n < NTOKW) ? *(const uint2*)(qkv + n * 288 + 96 + d4) : Z2;
        *(uint2*)(Ks + n * KLD + d4) = val;
    }
    // V transposed: load uint2, scatter 4 scalar smem stores
    for (int idx = tid; idx < 112 * 8; idx += 256) {
        int n = idx >> 3, d4 = (idx & 7) * 4;
        uint2 val = (n < NTOKW) ? *(const uint2*)(qkv + n * 288 + 192 + d4) : Z2;
        bf162 lo = *(bf162*)&val.x;
        bf162 hi = *(bf162*)&val.y;
        Vt[(d4 + 0) * VLD + n] = lo.x;
        Vt[(d4 + 1) * VLD + n] = lo.y;
        Vt[(d4 + 2) * VLD + n] = hi.x;
        Vt[(d4 + 3) * VLD + n] = hi.y;
    }
    // S init = mask + rpb; pad cols zeroed
    {
        const uint32_t* mp = (const uint32_t*)(g_maskh + (size_t)mw * 9604);
        const uint32_t* rp = (const uint32_t*)(g_rpbh + head * 9604);
        uint32_t* Pu = (uint32_t*)P;
        for (int u = tid; u < 4802; u += 256) {
            int i = u / 49, c = u % 49;
            uint32_t mv = mp[u], rv = rp[u];
            bf162 sum = __hadd2(*(bf162*)&mv, *(bf162*)&rv);
            Pu[i * (PLD / 2) + c] = *(uint32_t*)&sum;
        }
        for (int u = tid; u < 98 * 7; u += 256) {
            int i = u / 7, c = 49 + u % 7;
            Pu[i * (PLD / 2) + c] = 0;
        }
    }
    __syncthreads();

    int row0 = w * 16;
    if (w < 7) {
        #pragma unroll
        for (int h2 = 0; h2 < 2; h2++) {
            int ntbase = h2 * 7;
            int NT = h2 ? 6 : 7;
            float acc[7][4];
            #pragma unroll
            for (int t = 0; t < 7; t++)
                #pragma unroll
                for (int q = 0; q < 4; q++) acc[t][q] = 0.0f;
            #pragma unroll
            for (int ks = 0; ks < 2; ks++) {
                uint32_t afr[4];
                const uint32_t* ap = (const uint32_t*)
                    (Qs + (row0 + g) * QLD + ks * 16 + tg * 2);
                afr[0] = ap[0];
                afr[1] = ap[8 * (QLD / 2)];
                afr[2] = ap[4];
                afr[3] = ap[8 * (QLD / 2) + 4];
                for (int t = 0; t < NT; t++) {
                    int n = (ntbase + t) * 8 + g;
                    const uint32_t* bp = (const uint32_t*)
                        (Ks + n * KLD + ks * 16 + tg * 2);
                    mma_bf16(acc[t], afr, bp[0], bp[4]);
                }
            }
            for (int t = 0; t < NT; t++) {
                int c0 = (ntbase + t) * 8 + tg * 2;
                bf162* p0 = (bf162*)(P + (row0 + g) * PLD + c0);
                bf162* p1 = (bf162*)(P + (row0 + g + 8) * PLD + c0);
                float2 f0 = __bfloat1622float2(*p0);
                float2 f1 = __bfloat1622float2(*p1);
                *p0 = __floats2bfloat162_rn(acc[t][0] * SCALE + f0.x,
                                            acc[t][1] * SCALE + f0.y);
                *p1 = __floats2bfloat162_rn(acc[t][2] * SCALE + f1.x,
                                            acc[t][3] * SCALE + f1.y);
            }
        }
    }
    __syncthreads();

    for (int r = w; r < NTOKW; r += 8) {
        bf16* prow = P + r * PLD;
        float m = -1e30f;
        for (int j = lane; j < NTOKW; j += 32)
            m = fmaxf(m, __bfloat162float(prow[j]));
        #pragma unroll
        for (int o = 16; o; o >>= 1) m = fmaxf(m, __shfl_xor_sync(0xFFFFFFFFu, m, o));
        float s = 0.0f;
        for (int j = lane; j < NTOKW; j += 32) {
            float e = __expf(__bfloat162float(prow[j]) - m);
            prow[j] = __float2bfloat16(e);
            s += e;
        }
        #pragma unroll
        for (int o = 16; o; o >>= 1) s += __shfl_xor_sync(0xFFFFFFFFu, s, o);
        float inv = 1.0f / s;
        for (int j = lane; j < NTOKW; j += 32)
            prow[j] = __float2bfloat16(__bfloat162float(prow[j]) * inv);
    }
    __syncthreads();

    if (w < 7) {
        float acc[4][4];
        #pragma unroll
        for (int t = 0; t < 4; t++)
            #pragma unroll
            for (int q = 0; q < 4; q++) acc[t][q] = 0.0f;
        #pragma unroll
        for (int ks = 0; ks < 7; ks++) {
            uint32_t afr[4];
            const uint32_t* ap = (const uint32_t*)
                (P + (row0 + g) * PLD + ks * 16 + tg * 2);
            afr[0] = ap[0];
            afr[1] = ap[8 * (PLD / 2)];
            afr[2] = ap[4];
            afr[3] = ap[8 * (PLD / 2) + 4];
            #pragma unroll
            for (int nt = 0; nt < 4; nt++) {
                const uint32_t* bp = (const uint32_t*)
                    (Vt + (nt * 8 + g) * VLD + ks * 16 + tg * 2);
                mma_bf16(acc[nt], afr, bp[0], bp[4]);
            }
        }
        int r = row0 + g;
        size_t obase = ((size_t)win * NTOKW + r) * CDIM + head * HDIM;
        #pragma unroll
        for (int nt = 0; nt < 4; nt++) {
            int c0 = nt * 8 + tg * 2;
            if (r < NTOKW)
                *(bf162*)&g_attnh[obase + c0] =
                    __floats2bfloat162_rn(acc[nt][0], acc[nt][1]);
            if (r + 8 < NTOKW)
                *(bf162*)&g_attnh[obase + 8 * CDIM + c0] =
                    __floats2bfloat162_rn(acc[nt][2], acc[nt][3]);
        }
    }
}

// ---------------------------------------------------------------------------
extern "C" void kernel_launch(void* const* d_in, const int* in_sizes, int n_in,
                              void* d_out, int out_size) {
    const float* x         = (const float*)d_in[0];
    const float* attn_mask = (const float*)d_in[1];
    const float* g1        = (const float*)d_in[2];
    const float* b1        = (const float*)d_in[3];
    const float* qkv_w     = (const float*)d_in[4];
    const float* qkv_b     = (const float*)d_in[5];
    const float* rpb_table = (const float*)d_in[6];
    const float* proj_w    = (const float*)d_in[7];
    const float* proj_b    = (const float*)d_in[8];
    const float* g2        = (const float*)d_in[9];
    const float* b2        = (const float*)d_in[10];
    const float* fc1_w     = (const float*)d_in[11];
    const float* fc1_b     = (const float*)d_in[12];
    const float* fc2_w     = (const float*)d_in[13];
    const float* fc2_b     = (const float*)d_in[14];
    float* out = (float*)d_out;

    bf16 *p_xwh, *p_qkvh, *p_attnh, *p_h, *p_wh;
    float *p_xres;
    cudaGetSymbolAddress((void**)&p_xwh,   g_xwh);
    cudaGetSymbolAddress((void**)&p_qkvh,  g_qkvh);
    cudaGetSymbolAddress((void**)&p_attnh, g_attnh);
    cudaGetSymbolAddress((void**)&p_h,     g_h);
    cudaGetSymbolAddress((void**)&p_wh,    g_wh);
    cudaGetSymbolAddress((void**)&p_xres,  g_xres);

    const int attn_smem = SMEM_ATTN_BF * 2;          // 48.96 KB
    cudaFuncSetAttribute(attn_kernel, cudaFuncAttributeMaxDynamicSharedMemorySize, attn_smem);

    conv_weights<<<432, 256>>>(qkv_w, proj_w, fc1_w, fc2_w);
    rpb_expand<<<(HEADS * NTOKW * NTOKW + 255) / 256, 256>>>(rpb_table);
    mask_conv<<<(NW_PB * NTOKW * NTOKW) / (4 * 256), 256>>>(attn_mask);

    ln1_shift_win<<<NTOK / 4, 128>>>(x, g1, b1);

    // QKV gemm (M, 288, 96) -> bf16
    mma_gemm<0,1><<<dim3(288 / 96, NTOK / 64), 256>>>(
        p_xwh, p_wh, qkv_b, nullptr, p_qkvh, NTOK, 288, 96);

    attn_kernel<<<NWIN * HEADS, 256, attn_smem>>>();

    // proj gemm + residual + LN2 (fused)
    proj_fused<<<NTOK / 64, 256>>>(
        p_attnh, p_wh + 27648, proj_b, x, g2, b2, p_xres, p_xwh);

    // fc1 + gelu (M, 384, 96) -> bf16 h
    mma_gemm<1,1><<<dim3(HID / 96, NTOK / 64), 256>>>(
        p_xwh, p_wh + 36864, fc1_b, nullptr, p_h, NTOK, HID, 96);

    // fc2 + residual (M, 96, 384) -> fp32 d_out
    mma_gemm<2,0><<<dim3(1, NTOK / 64), 256>>>(
        p_h, p_wh + 73728, fc2_b, p_xres, out, NTOK, 96, HID);
}

// round 13
// speedup vs baseline: 3.7587x; 1.0794x over previous
#include <cuda_runtime.h>
#include <cuda_bf16.h>
#include <cstdint>
#include <math.h>

// ---------------------------------------------------------------------------
// Swin Transformer 3D block — round 13: softmax pipe surgery.
//   - h2exp on bf16x2 pairs (halves MUFU ops: 118M -> 59M)
//   - no max-subtraction pass (logits bounded; mask -100 underflows to 0)
//   - 1/sum folded into PV epilogue via per-row sinv[] (third pass gone)
//   Everything else identical to the passing round-12 build.
// ---------------------------------------------------------------------------

#define NTOK   401408
#define CDIM   96
#define NWIN   4096
#define NW_PB  2048
#define NTOKW  98
#define HEADS  3
#define HDIM   32
#define SCALE  0.17677669529663687f
#define HID    384

typedef __nv_bfloat16 bf16;
typedef __nv_bfloat162 bf162;

// -------------------------- device scratch ---------------------------------
__device__ bf16  g_xwh  [(size_t)NTOK * CDIM];
__device__ bf16  g_qkvh [(size_t)NTOK * 288];
__device__ bf16  g_attnh[(size_t)NTOK * CDIM];
__device__ bf16  g_h    [(size_t)NTOK * HID];
__device__ float g_xres [(size_t)NTOK * CDIM];
__device__ bf16  g_rpbh [HEADS * NTOKW * NTOKW];
__device__ bf16  g_maskh[(size_t)NW_PB * NTOKW * NTOKW];
__device__ bf16  g_wh   [110592];

// ---------------------------------------------------------------------------
__global__ void conv_weights(const float* __restrict__ qkv_w,
                             const float* __restrict__ proj_w,
                             const float* __restrict__ fc1_w,
                             const float* __restrict__ fc2_w) {
    int idx = blockIdx.x * 256 + threadIdx.x;       // 110592 total, exact
    const float* src; int off;
    if (idx < 27648)       { src = qkv_w;  off = idx; }
    else if (idx < 36864)  { src = proj_w; off = idx - 27648; }
    else if (idx < 73728)  { src = fc1_w;  off = idx - 36864; }
    else                   { src = fc2_w;  off = idx - 73728; }
    g_wh[idx] = __float2bfloat16(src[off]);
}

// ---------------------------------------------------------------------------
__global__ void rpb_expand(const float* __restrict__ table) {
    int idx = blockIdx.x * 256 + threadIdx.x;
    if (idx >= HEADS * NTOKW * NTOKW) return;
    int head = idx / (NTOKW * NTOKW);
    int r = idx % (NTOKW * NTOKW);
    int i = r / NTOKW, j = r % NTOKW;
    int zdi = i / 49, zhi = (i / 7) % 7, zwi = i % 7;
    int zdj = j / 49, zhj = (j / 7) % 7, zwj = j % 7;
    int ridx = (zdi - zdj + 1) * 169 + (zhi - zhj + 6) * 13 + (zwi - zwj + 6);
    g_rpbh[idx] = __float2bfloat16(table[ridx * 3 + head]);
}

// ---------------------------------------------------------------------------
__global__ void mask_conv(const float* __restrict__ mask) {
    int idx = blockIdx.x * 256 + threadIdx.x;        // 19208 blocks, exact
    float4 m = *(const float4*)&mask[(size_t)idx * 4];
    bf162 lo = __floats2bfloat162_rn(m.x, m.y);
    bf162 hi = __floats2bfloat162_rn(m.z, m.w);
    uint2 pk = make_uint2(*(uint32_t*)&lo, *(uint32_t*)&hi);
    *(uint2*)&g_maskh[(size_t)idx * 4] = pk;
}

// ---------------------------------------------------------------------------
__global__ void ln1_shift_win(const float* __restrict__ x,
                              const float* __restrict__ g,
                              const float* __restrict__ b) {
    int t    = blockIdx.x * 4 + (threadIdx.x >> 5);
    int lane = threadIdx.x & 31;
    int win = t / NTOKW, n = t % NTOKW;
    int bb  = win >> 11;
    int rem = win & 2047;
    int wd = rem >> 8, wh = (rem >> 4) & 15, ww = rem & 15;
    int zd = n / 49, r2 = n % 49, zh = r2 / 7, zw = r2 % 7;
    int sd = (wd * 2 + zd + 1) & 15;
    int sh = wh * 7 + zh + 3; if (sh >= 112) sh -= 112;
    int sw = ww * 7 + zw + 3; if (sw >= 112) sw -= 112;
    const float* px = x + ((((size_t)bb * 16 + sd) * 112 + sh) * 112 + sw) * CDIM;
    float v0 = px[lane], v1 = px[lane + 32], v2 = px[lane + 64];
    float s  = v0 + v1 + v2;
    float ss = v0 * v0 + v1 * v1 + v2 * v2;
    #pragma unroll
    for (int o = 16; o; o >>= 1) {
        s  += __shfl_xor_sync(0xFFFFFFFFu, s, o);
        ss += __shfl_xor_sync(0xFFFFFFFFu, ss, o);
    }
    float mu   = s * (1.0f / 96.0f);
    float var  = ss * (1.0f / 96.0f) - mu * mu;
    float rstd = rsqrtf(var + 1e-5f);
    bf16* po = g_xwh + (size_t)t * CDIM;
    po[lane]      = __float2bfloat16((v0 - mu) * rstd * g[lane]      + b[lane]);
    po[lane + 32] = __float2bfloat16((v1 - mu) * rstd * g[lane + 32] + b[lane + 32]);
    po[lane + 64] = __float2bfloat16((v2 - mu) * rstd * g[lane + 64] + b[lane + 64]);
}

// ---------------------------------------------------------------------------
__device__ __forceinline__ void mma_bf16(float c[4], const uint32_t a[4],
                                         uint32_t b0, uint32_t b1) {
    asm volatile(
        "mma.sync.aligned.m16n8k16.row.col.f32.bf16.bf16.f32 "
        "{%0,%1,%2,%3}, {%4,%5,%6,%7}, {%8,%9}, {%0,%1,%2,%3};"
        : "+f"(c[0]), "+f"(c[1]), "+f"(c[2]), "+f"(c[3])
        : "r"(a[0]), "r"(a[1]), "r"(a[2]), "r"(a[3]), "r"(b0), "r"(b1));
}
__device__ __forceinline__ void cp_async16(uint32_t smem_addr, const void* gptr) {
    asm volatile("cp.async.ca.shared.global [%0], [%1], 16;"
                 :: "r"(smem_addr), "l"(gptr));
}
__device__ __forceinline__ void cp_commit() {
    asm volatile("cp.async.commit_group;" ::: "memory");
}
template<int N>
__device__ __forceinline__ void cp_wait() {
    asm volatile("cp.async.wait_group %0;" :: "n"(N) : "memory");
}

// ---------------------------------------------------------------------------
// GEMM v3 (QKV / fc1 / fc2): BM=64, BN=96, BK=32, 2-stage cp.async, 8 warps.
//   EPI: 0=bias, 1=bias+gelu, 2=bias+res.  OUTB: 1 -> bf16 out, 0 -> fp32.
// ---------------------------------------------------------------------------
#define GLD  40                 // smem leading dim (bf16), 32 + 8 pad
#define STG  ((64 + 96) * GLD)  // bf16 units per stage = 6400

template<int EPI, int OUTB>
__global__ __launch_bounds__(256, 2)
void mma_gemm(const bf16* __restrict__ A, const bf16* __restrict__ B,
              const float* __restrict__ bias, const float* __restrict__ res,
              void* __restrict__ Cv, int M, int N, int K) {
    __shared__ bf16 sh[2 * STG];          // 25.6 KB

    int tid  = threadIdx.x;
    int w    = tid >> 5;
    int lane = tid & 31;
    int g    = lane >> 2;
    int tg   = lane & 3;
    int warpM = w & 1;
    int warpN = w >> 1;
    int m0 = blockIdx.y * 64;
    int n0 = blockIdx.x * 96;

    int ar = tid >> 2, ac = tid & 3;
    int br0 = tid >> 2, bc0 = tid & 3;
    int bi1 = 256 + tid;
    int br1 = bi1 >> 2, bc1 = bi1 & 3;

    uint32_t sbase = (uint32_t)__cvta_generic_to_shared(sh);

    float acc[2][3][4];
    #pragma unroll
    for (int i = 0; i < 2; i++)
        #pragma unroll
        for (int j = 0; j < 3; j++)
            #pragma unroll
            for (int t = 0; t < 4; t++) acc[i][j][t] = 0.0f;

    int KC = K >> 5;

    {
        cp_async16(sbase + (ar * GLD + ac * 8) * 2,
                   &A[(size_t)(m0 + ar) * K + ac * 8]);
        cp_async16(sbase + ((64 + br0) * GLD + bc0 * 8) * 2,
                   &B[(size_t)(n0 + br0) * K + bc0 * 8]);
        if (tid < 128)
            cp_async16(sbase + ((64 + br1) * GLD + bc1 * 8) * 2,
                       &B[(size_t)(n0 + br1) * K + bc1 * 8]);
        cp_commit();
    }

    for (int kc = 0; kc < KC; kc++) {
        if (kc + 1 < KC) {
            int k0 = (kc + 1) << 5;
            uint32_t sb = sbase + ((kc + 1) & 1) * STG * 2;
            cp_async16(sb + (ar * GLD + ac * 8) * 2,
                       &A[(size_t)(m0 + ar) * K + k0 + ac * 8]);
            cp_async16(sb + ((64 + br0) * GLD + bc0 * 8) * 2,
                       &B[(size_t)(n0 + br0) * K + k0 + bc0 * 8]);
            if (tid < 128)
                cp_async16(sb + ((64 + br1) * GLD + bc1 * 8) * 2,
                           &B[(size_t)(n0 + br1) * K + k0 + bc1 * 8]);
            cp_commit();
            cp_wait<1>();
        } else {
            cp_wait<0>();
        }
        __syncthreads();

        const bf16* As = sh + (kc & 1) * STG;
        const bf16* Bs = As + 64 * GLD;

        #pragma unroll
        for (int ks = 0; ks < 2; ks++) {
            uint32_t afr[2][4];
            #pragma unroll
            for (int mt = 0; mt < 2; mt++) {
                const uint32_t* ap = (const uint32_t*)
                    (As + (warpM * 32 + mt * 16 + g) * GLD + ks * 16 + tg * 2);
                afr[mt][0] = ap[0];
                afr[mt][1] = ap[8 * (GLD / 2)];
                afr[mt][2] = ap[4];
                afr[mt][3] = ap[8 * (GLD / 2) + 4];
            }
            #pragma unroll
            for (int nt = 0; nt < 3; nt++) {
                const uint32_t* bp = (const uint32_t*)
                    (Bs + (warpN * 24 + nt * 8 + g) * GLD + ks * 16 + tg * 2);
                uint32_t b0 = bp[0], b1 = bp[4];
                #pragma unroll
                for (int mt = 0; mt < 2; mt++)
                    mma_bf16(acc[mt][nt], afr[mt], b0, b1);
            }
        }
        __syncthreads();
    }

    #pragma unroll
    for (int mt = 0; mt < 2; mt++) {
        int r0 = m0 + warpM * 32 + mt * 16 + g;
        #pragma unroll
        for (int nt = 0; nt < 3; nt++) {
            int c0 = n0 + warpN * 24 + nt * 8 + tg * 2;
            float bs0 = bias[c0], bs1 = bias[c0 + 1];
            float v0 = acc[mt][nt][0] + bs0;
            float v1 = acc[mt][nt][1] + bs1;
            float v2 = acc[mt][nt][2] + bs0;
            float v3 = acc[mt][nt][3] + bs1;
            if (EPI == 1) {
                v0 = 0.5f * v0 * (1.0f + erff(v0 * 0.70710678118654752f));
                v1 = 0.5f * v1 * (1.0f + erff(v1 * 0.70710678118654752f));
                v2 = 0.5f * v2 * (1.0f + erff(v2 * 0.70710678118654752f));
                v3 = 0.5f * v3 * (1.0f + erff(v3 * 0.70710678118654752f));
            }
            if (EPI == 2) {
                const float* rp0 = &res[(size_t)r0 * N + c0];
                const float* rp1 = &res[(size_t)(r0 + 8) * N + c0];
                v0 += rp0[0]; v1 += rp0[1];
                v2 += rp1[0]; v3 += rp1[1];
            }
            if (OUTB) {
                bf16* C = (bf16*)Cv;
                *(bf162*)&C[(size_t)r0 * N + c0]       = __floats2bfloat162_rn(v0, v1);
                *(bf162*)&C[(size_t)(r0 + 8) * N + c0] = __floats2bfloat162_rn(v2, v3);
            } else {
                float* C = (float*)Cv;
                *(float2*)&C[(size_t)r0 * N + c0]       = make_float2(v0, v1);
                *(float2*)&C[(size_t)(r0 + 8) * N + c0] = make_float2(v2, v3);
            }
        }
    }
}

// ---------------------------------------------------------------------------
// proj GEMM fused with window-reverse residual + LN2 (as round 12).
// ---------------------------------------------------------------------------
__global__ __launch_bounds__(256, 2)
void proj_fused(const bf16* __restrict__ A, const bf16* __restrict__ B,
                const float* __restrict__ bias,
                const float* __restrict__ x,
                const float* __restrict__ g2v, const float* __restrict__ b2v,
                float* __restrict__ xres, bf16* __restrict__ xwh) {
    __shared__ bf16 sh[2 * STG];          // 25.6 KB; reused as fp32 S[64][100]
    const int K = 96;

    int tid  = threadIdx.x;
    int w    = tid >> 5;
    int lane = tid & 31;
    int g    = lane >> 2;
    int tg   = lane & 3;
    int warpM = w & 1;
    int warpN = w >> 1;
    int m0 = blockIdx.x * 64;

    int ar = tid >> 2, ac = tid & 3;
    int br0 = tid >> 2, bc0 = tid & 3;
    int bi1 = 256 + tid;
    int br1 = bi1 >> 2, bc1 = bi1 & 3;

    uint32_t sbase = (uint32_t)__cvta_generic_to_shared(sh);

    float acc[2][3][4];
    #pragma unroll
    for (int i = 0; i < 2; i++)
        #pragma unroll
        for (int j = 0; j < 3; j++)
            #pragma unroll
            for (int t = 0; t < 4; t++) acc[i][j][t] = 0.0f;

    {
        cp_async16(sbase + (ar * GLD + ac * 8) * 2,
                   &A[(size_t)(m0 + ar) * K + ac * 8]);
        cp_async16(sbase + ((64 + br0) * GLD + bc0 * 8) * 2,
                   &B[(size_t)br0 * K + bc0 * 8]);
        if (tid < 128)
            cp_async16(sbase + ((64 + br1) * GLD + bc1 * 8) * 2,
                       &B[(size_t)br1 * K + bc1 * 8]);
        cp_commit();
    }

    for (int kc = 0; kc < 3; kc++) {
        if (kc + 1 < 3) {
            int k0 = (kc + 1) << 5;
            uint32_t sb = sbase + ((kc + 1) & 1) * STG * 2;
            cp_async16(sb + (ar * GLD + ac * 8) * 2,
                       &A[(size_t)(m0 + ar) * K + k0 + ac * 8]);
            cp_async16(sb + ((64 + br0) * GLD + bc0 * 8) * 2,
                       &B[(size_t)br0 * K + k0 + bc0 * 8]);
            if (tid < 128)
                cp_async16(sb + ((64 + br1) * GLD + bc1 * 8) * 2,
                           &B[(size_t)br1 * K + k0 + bc1 * 8]);
            cp_commit();
            cp_wait<1>();
        } else {
            cp_wait<0>();
        }
        __syncthreads();

        const bf16* As = sh + (kc & 1) * STG;
        const bf16* Bs = As + 64 * GLD;

        #pragma unroll
        for (int ks = 0; ks < 2; ks++) {
            uint32_t afr[2][4];
            #pragma unroll
            for (int mt = 0; mt < 2; mt++) {
                const uint32_t* ap = (const uint32_t*)
                    (As + (warpM * 32 + mt * 16 + g) * GLD + ks * 16 + tg * 2);
                afr[mt][0] = ap[0];
                afr[mt][1] = ap[8 * (GLD / 2)];
                afr[mt][2] = ap[4];
                afr[mt][3] = ap[8 * (GLD / 2) + 4];
            }
            #pragma unroll
            for (int nt = 0; nt < 3; nt++) {
                const uint32_t* bp = (const uint32_t*)
                    (Bs + (warpN * 24 + nt * 8 + g) * GLD + ks * 16 + tg * 2);
                uint32_t b0 = bp[0], b1 = bp[4];
                #pragma unroll
                for (int mt = 0; mt < 2; mt++)
                    mma_bf16(acc[mt][nt], afr[mt], b0, b1);
            }
        }
        __syncthreads();
    }

    float* S = (float*)sh;
    #pragma unroll
    for (int mt = 0; mt < 2; mt++) {
        int rr = warpM * 32 + mt * 16 + g;
        #pragma unroll
        for (int nt = 0; nt < 3; nt++) {
            int c0 = warpN * 24 + nt * 8 + tg * 2;
            float bs0 = bias[c0], bs1 = bias[c0 + 1];
            S[rr * 100 + c0]            = acc[mt][nt][0] + bs0;
            S[rr * 100 + c0 + 1]        = acc[mt][nt][1] + bs1;
            S[(rr + 8) * 100 + c0]      = acc[mt][nt][2] + bs0;
            S[(rr + 8) * 100 + c0 + 1]  = acc[mt][nt][3] + bs1;
        }
    }
    __syncthreads();

    for (int rr = w; rr < 64; rr += 8) {
        int t = m0 + rr;
        int win = t / NTOKW, n = t % NTOKW;
        int bb  = win >> 11;
        int rem = win & 2047;
        int wd = rem >> 8, wh = (rem >> 4) & 15, ww = rem & 15;
        int zd = n / 49, r2 = n % 49, zh = r2 / 7, zw = r2 % 7;
        int sd = (wd * 2 + zd + 1) & 15;
        int shh = wh * 7 + zh + 3; if (shh >= 112) shh -= 112;
        int sww = ww * 7 + zw + 3; if (sww >= 112) sww -= 112;
        size_t sidx = (((size_t)bb * 16 + sd) * 112 + shh) * 112 + sww;
        const float* px = x + sidx * CDIM;
        const float* ps = S + rr * 100;
        float v0 = px[lane]      + ps[lane];
        float v1 = px[lane + 32] + ps[lane + 32];
        float v2 = px[lane + 64] + ps[lane + 64];
        float* pr = xres + sidx * CDIM;
        pr[lane] = v0; pr[lane + 32] = v1; pr[lane + 64] = v2;
        float s  = v0 + v1 + v2;
        float ss = v0 * v0 + v1 * v1 + v2 * v2;
        #pragma unroll
        for (int o = 16; o; o >>= 1) {
            s  += __shfl_xor_sync(0xFFFFFFFFu, s, o);
            ss += __shfl_xor_sync(0xFFFFFFFFu, ss, o);
        }
        float mu   = s * (1.0f / 96.0f);
        float var  = ss * (1.0f / 96.0f) - mu * mu;
        float rstd = rsqrtf(var + 1e-5f);
        bf16* po = xwh + sidx * CDIM;
        po[lane]      = __float2bfloat16((v0 - mu) * rstd * g2v[lane]      + b2v[lane]);
        po[lane + 32] = __float2bfloat16((v1 - mu) * rstd * g2v[lane + 32] + b2v[lane + 32]);
        po[lane + 64] = __float2bfloat16((v2 - mu) * rstd * g2v[lane + 64] + b2v[lane + 64]);
    }
}

// ---------------------------------------------------------------------------
// Tensor-core attention; bf16x2 h2exp softmax (no max pass), sinv folded
// into PV epilogue.
// ---------------------------------------------------------------------------
#define QLD 36
#define KLD 36
#define VLD 116
#define PLD 116
#define SMEM_ATTN_BF 24480                 // bf16 units before sinv
#define SMEM_ATTN_BYTES (SMEM_ATTN_BF * 2 + 112 * 4)   // + sinv[112] fp32

__global__ __launch_bounds__(256)
void attn_kernel() {
    int wh   = blockIdx.x;
    int win  = wh / HEADS, head = wh % HEADS;
    int mw   = win & (NW_PB - 1);
    extern __shared__ bf16 smh[];
    bf16* Qs = smh;
    bf16* Ks = smh + 4032;
    bf16* Vt = smh + 7776;
    bf16* P  = smh + 11488;
    float* sinv = (float*)(smh + SMEM_ATTN_BF);   // 112 floats
    int tid  = threadIdx.x;
    int w    = tid >> 5;
    int lane = tid & 31;
    int g    = lane >> 2;
    int tg   = lane & 3;
    uint2 Z2 = make_uint2(0u, 0u);

    const bf16* qkv = g_qkvh + (size_t)win * NTOKW * 288 + head * HDIM;
    for (int idx = tid; idx < 112 * 8; idx += 256) {
        int n = idx >> 3, d4 = (idx & 7) * 4;
        uint2 val = (n < NTOKW) ? *(const uint2*)(qkv + n * 288 + d4) : Z2;
        *(uint2*)(Qs + n * QLD + d4) = val;
    }
    for (int idx = tid; idx < 104 * 8; idx += 256) {
        int n = idx >> 3, d4 = (idx & 7) * 4;
        uint2 val = (n < NTOKW) ? *(const uint2*)(qkv + n * 288 + 96 + d4) : Z2;
        *(uint2*)(Ks + n * KLD + d4) = val;
    }
    for (int idx = tid; idx < 112 * 8; idx += 256) {
        int n = idx >> 3, d4 = (idx & 7) * 4;
        uint2 val = (n < NTOKW) ? *(const uint2*)(qkv + n * 288 + 192 + d4) : Z2;
        bf162 lo = *(bf162*)&val.x;
        bf162 hi = *(bf162*)&val.y;
        Vt[(d4 + 0) * VLD + n] = lo.x;
        Vt[(d4 + 1) * VLD + n] = lo.y;
        Vt[(d4 + 2) * VLD + n] = hi.x;
        Vt[(d4 + 3) * VLD + n] = hi.y;
    }
    {
        const uint32_t* mp = (const uint32_t*)(g_maskh + (size_t)mw * 9604);
        const uint32_t* rp = (const uint32_t*)(g_rpbh + head * 9604);
        uint32_t* Pu = (uint32_t*)P;
        for (int u = tid; u < 4802; u += 256) {
            int i = u / 49, c = u % 49;
            uint32_t mv = mp[u], rv = rp[u];
            bf162 sum = __hadd2(*(bf162*)&mv, *(bf162*)&rv);
            Pu[i * (PLD / 2) + c] = *(uint32_t*)&sum;
        }
        for (int u = tid; u < 98 * 7; u += 256) {
            int i = u / 7, c = 49 + u % 7;
            Pu[i * (PLD / 2) + c] = 0;
        }
    }
    __syncthreads();

    int row0 = w * 16;
    if (w < 7) {
        #pragma unroll
        for (int h2 = 0; h2 < 2; h2++) {
            int ntbase = h2 * 7;
            int NT = h2 ? 6 : 7;
            float acc[7][4];
            #pragma unroll
            for (int t = 0; t < 7; t++)
                #pragma unroll
                for (int q = 0; q < 4; q++) acc[t][q] = 0.0f;
            #pragma unroll
            for (int ks = 0; ks < 2; ks++) {
                uint32_t afr[4];
                const uint32_t* ap = (const uint32_t*)
                    (Qs + (row0 + g) * QLD + ks * 16 + tg * 2);
                afr[0] = ap[0];
                afr[1] = ap[8 * (QLD / 2)];
                afr[2] = ap[4];
                afr[3] = ap[8 * (QLD / 2) + 4];
                for (int t = 0; t < NT; t++) {
                    int n = (ntbase + t) * 8 + g;
                    const uint32_t* bp = (const uint32_t*)
                        (Ks + n * KLD + ks * 16 + tg * 2);
                    mma_bf16(acc[t], afr, bp[0], bp[4]);
                }
            }
            for (int t = 0; t < NT; t++) {
                int c0 = (ntbase + t) * 8 + tg * 2;
                bf162* p0 = (bf162*)(P + (row0 + g) * PLD + c0);
                bf162* p1 = (bf162*)(P + (row0 + g + 8) * PLD + c0);
                float2 f0 = __bfloat1622float2(*p0);
                float2 f1 = __bfloat1622float2(*p1);
                *p0 = __floats2bfloat162_rn(acc[t][0] * SCALE + f0.x,
                                            acc[t][1] * SCALE + f0.y);
                *p1 = __floats2bfloat162_rn(acc[t][2] * SCALE + f1.x,
                                            acc[t][3] * SCALE + f1.y);
            }
        }
    }
    __syncthreads();

    // ---- softmax: single pass, bf16x2 h2exp, no max subtraction ----
    for (int r = w; r < NTOKW; r += 8) {
        uint32_t* prow = (uint32_t*)(P + r * PLD);
        float s = 0.0f;
        for (int jp = lane; jp < 49; jp += 32) {
            uint32_t v = prow[jp];
            bf162 e = h2exp(*(bf162*)&v);
            prow[jp] = *(uint32_t*)&e;
            float2 f = __bfloat1622float2(e);
            s += f.x + f.y;
        }
        #pragma unroll
        for (int o = 16; o; o >>= 1) s += __shfl_xor_sync(0xFFFFFFFFu, s, o);
        if (lane == 0) sinv[r] = 1.0f / s;
    }
    __syncthreads();

    // ---- PV; 1/sum folded into accumulator scaling ----
    if (w < 7) {
        float acc[4][4];
        #pragma unroll
        for (int t = 0; t < 4; t++)
            #pragma unroll
            for (int q = 0; q < 4; q++) acc[t][q] = 0.0f;
        #pragma unroll
        for (int ks = 0; ks < 7; ks++) {
            uint32_t afr[4];
            const uint32_t* ap = (const uint32_t*)
                (P + (row0 + g) * PLD + ks * 16 + tg * 2);
            afr[0] = ap[0];
            afr[1] = ap[8 * (PLD / 2)];
            afr[2] = ap[4];
            afr[3] = ap[8 * (PLD / 2) + 4];
            #pragma unroll
            for (int nt = 0; nt < 4; nt++) {
                const uint32_t* bp = (const uint32_t*)
                    (Vt + (nt * 8 + g) * VLD + ks * 16 + tg * 2);
                mma_bf16(acc[nt], afr, bp[0], bp[4]);
            }
        }
        int r = row0 + g;
        float i0 = (r < NTOKW)     ? sinv[r]     : 0.0f;
        float i1 = (r + 8 < NTOKW) ? sinv[r + 8] : 0.0f;
        size_t obase = ((size_t)win * NTOKW + r) * CDIM + head * HDIM;
        #pragma unroll
        for (int nt = 0; nt < 4; nt++) {
            int c0 = nt * 8 + tg * 2;
            if (r < NTOKW)
                *(bf162*)&g_attnh[obase + c0] =
                    __floats2bfloat162_rn(acc[nt][0] * i0, acc[nt][1] * i0);
            if (r + 8 < NTOKW)
                *(bf162*)&g_attnh[obase + 8 * CDIM + c0] =
                    __floats2bfloat162_rn(acc[nt][2] * i1, acc[nt][3] * i1);
        }
    }
}

// ---------------------------------------------------------------------------
extern "C" void kernel_launch(void* const* d_in, const int* in_sizes, int n_in,
                              void* d_out, int out_size) {
    const float* x         = (const float*)d_in[0];
    const float* attn_mask = (const float*)d_in[1];
    const float* g1        = (const float*)d_in[2];
    const float* b1        = (const float*)d_in[3];
    const float* qkv_w     = (const float*)d_in[4];
    const float* qkv_b     = (const float*)d_in[5];
    const float* rpb_table = (const float*)d_in[6];
    const float* proj_w    = (const float*)d_in[7];
    const float* proj_b    = (const float*)d_in[8];
    const float* g2        = (const float*)d_in[9];
    const float* b2        = (const float*)d_in[10];
    const float* fc1_w     = (const float*)d_in[11];
    const float* fc1_b     = (const float*)d_in[12];
    const float* fc2_w     = (const float*)d_in[13];
    const float* fc2_b     = (const float*)d_in[14];
    float* out = (float*)d_out;

    bf16 *p_xwh, *p_qkvh, *p_attnh, *p_h, *p_wh;
    float *p_xres;
    cudaGetSymbolAddress((void**)&p_xwh,   g_xwh);
    cudaGetSymbolAddress((void**)&p_qkvh,  g_qkvh);
    cudaGetSymbolAddress((void**)&p_attnh, g_attnh);
    cudaGetSymbolAddress((void**)&p_h,     g_h);
    cudaGetSymbolAddress((void**)&p_wh,    g_wh);
    cudaGetSymbolAddress((void**)&p_xres,  g_xres);

    const int attn_smem = SMEM_ATTN_BYTES;           // 49.4 KB
    cudaFuncSetAttribute(attn_kernel, cudaFuncAttributeMaxDynamicSharedMemorySize, attn_smem);

    conv_weights<<<432, 256>>>(qkv_w, proj_w, fc1_w, fc2_w);
    rpb_expand<<<(HEADS * NTOKW * NTOKW + 255) / 256, 256>>>(rpb_table);
    mask_conv<<<(NW_PB * NTOKW * NTOKW) / (4 * 256), 256>>>(attn_mask);

    ln1_shift_win<<<NTOK / 4, 128>>>(x, g1, b1);

    // QKV gemm (M, 288, 96) -> bf16
    mma_gemm<0,1><<<dim3(288 / 96, NTOK / 64), 256>>>(
        p_xwh, p_wh, qkv_b, nullptr, p_qkvh, NTOK, 288, 96);

    attn_kernel<<<NWIN * HEADS, 256, attn_smem>>>();

    // proj gemm + residual + LN2 (fused)
    proj_fused<<<NTOK / 64, 256>>>(
        p_attnh, p_wh + 27648, proj_b, x, g2, b2, p_xres, p_xwh);

    // fc1 + gelu (M, 384, 96) -> bf16 h
    mma_gemm<1,1><<<dim3(HID / 96, NTOK / 64), 256>>>(
        p_xwh, p_wh + 36864, fc1_b, nullptr, p_h, NTOK, HID, 96);

    // fc2 + residual (M, 96, 384) -> fp32 d_out
    mma_gemm<2,0><<<dim3(1, NTOK / 64), 256>>>(
        p_h, p_wh + 73728, fc2_b, p_xres, out, NTOK, 96, HID);
}

// round 14
// speedup vs baseline: 3.8151x; 1.0150x over previous
#include <cuda_runtime.h>
#include <cuda_bf16.h>
#include <cstdint>
#include <math.h>

// ---------------------------------------------------------------------------
// Swin Transformer 3D block — round 14: ldmatrix.x4 A-fragment loads in the
// GEMM family (mma_gemm + proj_fused).  Attention / elementwise identical to
// the passing round-13 build.
// ---------------------------------------------------------------------------

#define NTOK   401408
#define CDIM   96
#define NWIN   4096
#define NW_PB  2048
#define NTOKW  98
#define HEADS  3
#define HDIM   32
#define SCALE  0.17677669529663687f
#define HID    384

typedef __nv_bfloat16 bf16;
typedef __nv_bfloat162 bf162;

// -------------------------- device scratch ---------------------------------
__device__ bf16  g_xwh  [(size_t)NTOK * CDIM];
__device__ bf16  g_qkvh [(size_t)NTOK * 288];
__device__ bf16  g_attnh[(size_t)NTOK * CDIM];
__device__ bf16  g_h    [(size_t)NTOK * HID];
__device__ float g_xres [(size_t)NTOK * CDIM];
__device__ bf16  g_rpbh [HEADS * NTOKW * NTOKW];
__device__ bf16  g_maskh[(size_t)NW_PB * NTOKW * NTOKW];
__device__ bf16  g_wh   [110592];

// ---------------------------------------------------------------------------
__global__ void conv_weights(const float* __restrict__ qkv_w,
                             const float* __restrict__ proj_w,
                             const float* __restrict__ fc1_w,
                             const float* __restrict__ fc2_w) {
    int idx = blockIdx.x * 256 + threadIdx.x;       // 110592 total, exact
    const float* src; int off;
    if (idx < 27648)       { src = qkv_w;  off = idx; }
    else if (idx < 36864)  { src = proj_w; off = idx - 27648; }
    else if (idx < 73728)  { src = fc1_w;  off = idx - 36864; }
    else                   { src = fc2_w;  off = idx - 73728; }
    g_wh[idx] = __float2bfloat16(src[off]);
}

// ---------------------------------------------------------------------------
__global__ void rpb_expand(const float* __restrict__ table) {
    int idx = blockIdx.x * 256 + threadIdx.x;
    if (idx >= HEADS * NTOKW * NTOKW) return;
    int head = idx / (NTOKW * NTOKW);
    int r = idx % (NTOKW * NTOKW);
    int i = r / NTOKW, j = r % NTOKW;
    int zdi = i / 49, zhi = (i / 7) % 7, zwi = i % 7;
    int zdj = j / 49, zhj = (j / 7) % 7, zwj = j % 7;
    int ridx = (zdi - zdj + 1) * 169 + (zhi - zhj + 6) * 13 + (zwi - zwj + 6);
    g_rpbh[idx] = __float2bfloat16(table[ridx * 3 + head]);
}

// ---------------------------------------------------------------------------
__global__ void mask_conv(const float* __restrict__ mask) {
    int idx = blockIdx.x * 256 + threadIdx.x;        // 19208 blocks, exact
    float4 m = *(const float4*)&mask[(size_t)idx * 4];
    bf162 lo = __floats2bfloat162_rn(m.x, m.y);
    bf162 hi = __floats2bfloat162_rn(m.z, m.w);
    uint2 pk = make_uint2(*(uint32_t*)&lo, *(uint32_t*)&hi);
    *(uint2*)&g_maskh[(size_t)idx * 4] = pk;
}

// ---------------------------------------------------------------------------
__global__ void ln1_shift_win(const float* __restrict__ x,
                              const float* __restrict__ g,
                              const float* __restrict__ b) {
    int t    = blockIdx.x * 4 + (threadIdx.x >> 5);
    int lane = threadIdx.x & 31;
    int win = t / NTOKW, n = t % NTOKW;
    int bb  = win >> 11;
    int rem = win & 2047;
    int wd = rem >> 8, wh = (rem >> 4) & 15, ww = rem & 15;
    int zd = n / 49, r2 = n % 49, zh = r2 / 7, zw = r2 % 7;
    int sd = (wd * 2 + zd + 1) & 15;
    int sh = wh * 7 + zh + 3; if (sh >= 112) sh -= 112;
    int sw = ww * 7 + zw + 3; if (sw >= 112) sw -= 112;
    const float* px = x + ((((size_t)bb * 16 + sd) * 112 + sh) * 112 + sw) * CDIM;
    float v0 = px[lane], v1 = px[lane + 32], v2 = px[lane + 64];
    float s  = v0 + v1 + v2;
    float ss = v0 * v0 + v1 * v1 + v2 * v2;
    #pragma unroll
    for (int o = 16; o; o >>= 1) {
        s  += __shfl_xor_sync(0xFFFFFFFFu, s, o);
        ss += __shfl_xor_sync(0xFFFFFFFFu, ss, o);
    }
    float mu   = s * (1.0f / 96.0f);
    float var  = ss * (1.0f / 96.0f) - mu * mu;
    float rstd = rsqrtf(var + 1e-5f);
    bf16* po = g_xwh + (size_t)t * CDIM;
    po[lane]      = __float2bfloat16((v0 - mu) * rstd * g[lane]      + b[lane]);
    po[lane + 32] = __float2bfloat16((v1 - mu) * rstd * g[lane + 32] + b[lane + 32]);
    po[lane + 64] = __float2bfloat16((v2 - mu) * rstd * g[lane + 64] + b[lane + 64]);
}

// ---------------------------------------------------------------------------
__device__ __forceinline__ void mma_bf16(float c[4], const uint32_t a[4],
                                         uint32_t b0, uint32_t b1) {
    asm volatile(
        "mma.sync.aligned.m16n8k16.row.col.f32.bf16.bf16.f32 "
        "{%0,%1,%2,%3}, {%4,%5,%6,%7}, {%8,%9}, {%0,%1,%2,%3};"
        : "+f"(c[0]), "+f"(c[1]), "+f"(c[2]), "+f"(c[3])
        : "r"(a[0]), "r"(a[1]), "r"(a[2]), "r"(a[3]), "r"(b0), "r"(b1));
}
__device__ __forceinline__ void ldsm4(uint32_t r[4], uint32_t saddr) {
    asm volatile("ldmatrix.sync.aligned.m8n8.x4.shared.b16 {%0,%1,%2,%3}, [%4];"
        : "=r"(r[0]), "=r"(r[1]), "=r"(r[2]), "=r"(r[3]) : "r"(saddr));
}
__device__ __forceinline__ void cp_async16(uint32_t smem_addr, const void* gptr) {
    asm volatile("cp.async.ca.shared.global [%0], [%1], 16;"
                 :: "r"(smem_addr), "l"(gptr));
}
__device__ __forceinline__ void cp_commit() {
    asm volatile("cp.async.commit_group;" ::: "memory");
}
template<int N>
__device__ __forceinline__ void cp_wait() {
    asm volatile("cp.async.wait_group %0;" :: "n"(N) : "memory");
}

// ---------------------------------------------------------------------------
// GEMM v4 (QKV / fc1 / fc2): BM=64, BN=96, BK=32, 2-stage cp.async, 8 warps,
//   ldmatrix.x4 A-fragments.  EPI: 0=bias, 1=bias+gelu, 2=bias+res.
//   OUTB: 1 -> bf16 out, 0 -> fp32.
//   GLD=40 bf16 -> 80B row stride = 5x16B (LDSM-legal, conflict-free).
// ---------------------------------------------------------------------------
#define GLD  40
#define STG  ((64 + 96) * GLD)  // bf16 units per stage = 6400

template<int EPI, int OUTB>
__global__ __launch_bounds__(256, 2)
void mma_gemm(const bf16* __restrict__ A, const bf16* __restrict__ B,
              const float* __restrict__ bias, const float* __restrict__ res,
              void* __restrict__ Cv, int M, int N, int K) {
    __shared__ __align__(16) bf16 sh[2 * STG];          // 25.6 KB

    int tid  = threadIdx.x;
    int w    = tid >> 5;
    int lane = tid & 31;
    int g    = lane >> 2;
    int tg   = lane & 3;
    int warpM = w & 1;
    int warpN = w >> 1;
    int m0 = blockIdx.y * 64;
    int n0 = blockIdx.x * 96;

    int ar = tid >> 2, ac = tid & 3;
    int br0 = tid >> 2, bc0 = tid & 3;
    int bi1 = 256 + tid;
    int br1 = bi1 >> 2, bc1 = bi1 & 3;

    uint32_t sbase = (uint32_t)__cvta_generic_to_shared(sh);
    // ldmatrix per-lane offset: rows (lane&15), k-half (lane>>4)*8
    uint32_t loff = (((lane & 15) * GLD) + ((lane >> 4) * 8)) * 2;

    float acc[2][3][4];
    #pragma unroll
    for (int i = 0; i < 2; i++)
        #pragma unroll
        for (int j = 0; j < 3; j++)
            #pragma unroll
            for (int t = 0; t < 4; t++) acc[i][j][t] = 0.0f;

    int KC = K >> 5;

    {
        cp_async16(sbase + (ar * GLD + ac * 8) * 2,
                   &A[(size_t)(m0 + ar) * K + ac * 8]);
        cp_async16(sbase + ((64 + br0) * GLD + bc0 * 8) * 2,
                   &B[(size_t)(n0 + br0) * K + bc0 * 8]);
        if (tid < 128)
            cp_async16(sbase + ((64 + br1) * GLD + bc1 * 8) * 2,
                       &B[(size_t)(n0 + br1) * K + bc1 * 8]);
        cp_commit();
    }

    for (int kc = 0; kc < KC; kc++) {
        if (kc + 1 < KC) {
            int k0 = (kc + 1) << 5;
            uint32_t sb = sbase + ((kc + 1) & 1) * STG * 2;
            cp_async16(sb + (ar * GLD + ac * 8) * 2,
                       &A[(size_t)(m0 + ar) * K + k0 + ac * 8]);
            cp_async16(sb + ((64 + br0) * GLD + bc0 * 8) * 2,
                       &B[(size_t)(n0 + br0) * K + k0 + bc0 * 8]);
            if (tid < 128)
                cp_async16(sb + ((64 + br1) * GLD + bc1 * 8) * 2,
                           &B[(size_t)(n0 + br1) * K + k0 + bc1 * 8]);
            cp_commit();
            cp_wait<1>();
        } else {
            cp_wait<0>();
        }
        __syncthreads();

        uint32_t sst = sbase + (kc & 1) * STG * 2;
        const bf16* Bs = sh + (kc & 1) * STG + 64 * GLD;
        uint32_t aA = sst + (warpM * 32 * GLD) * 2 + loff;

        #pragma unroll
        for (int ks = 0; ks < 2; ks++) {
            uint32_t afr[2][4];
            #pragma unroll
            for (int mt = 0; mt < 2; mt++)
                ldsm4(afr[mt], aA + (mt * 16 * GLD + ks * 16) * 2);
            #pragma unroll
            for (int nt = 0; nt < 3; nt++) {
                const uint32_t* bp = (const uint32_t*)
                    (Bs + (warpN * 24 + nt * 8 + g) * GLD + ks * 16 + tg * 2);
                uint32_t b0 = bp[0], b1 = bp[4];
                #pragma unroll
                for (int mt = 0; mt < 2; mt++)
                    mma_bf16(acc[mt][nt], afr[mt], b0, b1);
            }
        }
        __syncthreads();
    }

    #pragma unroll
    for (int mt = 0; mt < 2; mt++) {
        int r0 = m0 + warpM * 32 + mt * 16 + g;
        #pragma unroll
        for (int nt = 0; nt < 3; nt++) {
            int c0 = n0 + warpN * 24 + nt * 8 + tg * 2;
            float bs0 = bias[c0], bs1 = bias[c0 + 1];
            float v0 = acc[mt][nt][0] + bs0;
            float v1 = acc[mt][nt][1] + bs1;
            float v2 = acc[mt][nt][2] + bs0;
            float v3 = acc[mt][nt][3] + bs1;
            if (EPI == 1) {
                v0 = 0.5f * v0 * (1.0f + erff(v0 * 0.70710678118654752f));
                v1 = 0.5f * v1 * (1.0f + erff(v1 * 0.70710678118654752f));
                v2 = 0.5f * v2 * (1.0f + erff(v2 * 0.70710678118654752f));
                v3 = 0.5f * v3 * (1.0f + erff(v3 * 0.70710678118654752f));
            }
            if (EPI == 2) {
                const float* rp0 = &res[(size_t)r0 * N + c0];
                const float* rp1 = &res[(size_t)(r0 + 8) * N + c0];
                v0 += rp0[0]; v1 += rp0[1];
                v2 += rp1[0]; v3 += rp1[1];
            }
            if (OUTB) {
                bf16* C = (bf16*)Cv;
                *(bf162*)&C[(size_t)r0 * N + c0]       = __floats2bfloat162_rn(v0, v1);
                *(bf162*)&C[(size_t)(r0 + 8) * N + c0] = __floats2bfloat162_rn(v2, v3);
            } else {
                float* C = (float*)Cv;
                *(float2*)&C[(size_t)r0 * N + c0]       = make_float2(v0, v1);
                *(float2*)&C[(size_t)(r0 + 8) * N + c0] = make_float2(v2, v3);
            }
        }
    }
}

// ---------------------------------------------------------------------------
// proj GEMM fused with window-reverse residual + LN2 (ldmatrix A-frags).
// ---------------------------------------------------------------------------
__global__ __launch_bounds__(256, 2)
void proj_fused(const bf16* __restrict__ A, const bf16* __restrict__ B,
                const float* __restrict__ bias,
                const float* __restrict__ x,
                const float* __restrict__ g2v, const float* __restrict__ b2v,
                float* __restrict__ xres, bf16* __restrict__ xwh) {
    __shared__ __align__(16) bf16 sh[2 * STG];   // 25.6 KB; reused as S[64][100]
    const int K = 96;

    int tid  = threadIdx.x;
    int w    = tid >> 5;
    int lane = tid & 31;
    int g    = lane >> 2;
    int tg   = lane & 3;
    int warpM = w & 1;
    int warpN = w >> 1;
    int m0 = blockIdx.x * 64;

    int ar = tid >> 2, ac = tid & 3;
    int br0 = tid >> 2, bc0 = tid & 3;
    int bi1 = 256 + tid;
    int br1 = bi1 >> 2, bc1 = bi1 & 3;

    uint32_t sbase = (uint32_t)__cvta_generic_to_shared(sh);
    uint32_t loff = (((lane & 15) * GLD) + ((lane >> 4) * 8)) * 2;

    float acc[2][3][4];
    #pragma unroll
    for (int i = 0; i < 2; i++)
        #pragma unroll
        for (int j = 0; j < 3; j++)
            #pragma unroll
            for (int t = 0; t < 4; t++) acc[i][j][t] = 0.0f;

    {
        cp_async16(sbase + (ar * GLD + ac * 8) * 2,
                   &A[(size_t)(m0 + ar) * K + ac * 8]);
        cp_async16(sbase + ((64 + br0) * GLD + bc0 * 8) * 2,
                   &B[(size_t)br0 * K + bc0 * 8]);
        if (tid < 128)
            cp_async16(sbase + ((64 + br1) * GLD + bc1 * 8) * 2,
                       &B[(size_t)br1 * K + bc1 * 8]);
        cp_commit();
    }

    for (int kc = 0; kc < 3; kc++) {
        if (kc + 1 < 3) {
            int k0 = (kc + 1) << 5;
            uint32_t sb = sbase + ((kc + 1) & 1) * STG * 2;
            cp_async16(sb + (ar * GLD + ac * 8) * 2,
                       &A[(size_t)(m0 + ar) * K + k0 + ac * 8]);
            cp_async16(sb + ((64 + br0) * GLD + bc0 * 8) * 2,
                       &B[(size_t)br0 * K + k0 + bc0 * 8]);
            if (tid < 128)
                cp_async16(sb + ((64 + br1) * GLD + bc1 * 8) * 2,
                           &B[(size_t)br1 * K + k0 + bc1 * 8]);
            cp_commit();
            cp_wait<1>();
        } else {
            cp_wait<0>();
        }
        __syncthreads();

        uint32_t sst = sbase + (kc & 1) * STG * 2;
        const bf16* Bs = sh + (kc & 1) * STG + 64 * GLD;
        uint32_t aA = sst + (warpM * 32 * GLD) * 2 + loff;

        #pragma unroll
        for (int ks = 0; ks < 2; ks++) {
            uint32_t afr[2][4];
            #pragma unroll
            for (int mt = 0; mt < 2; mt++)
                ldsm4(afr[mt], aA + (mt * 16 * GLD + ks * 16) * 2);
            #pragma unroll
            for (int nt = 0; nt < 3; nt++) {
                const uint32_t* bp = (const uint32_t*)
                    (Bs + (warpN * 24 + nt * 8 + g) * GLD + ks * 16 + tg * 2);
                uint32_t b0 = bp[0], b1 = bp[4];
                #pragma unroll
                for (int mt = 0; mt < 2; mt++)
                    mma_bf16(acc[mt][nt], afr[mt], b0, b1);
            }
        }
        __syncthreads();
    }

    float* S = (float*)sh;
    #pragma unroll
    for (int mt = 0; mt < 2; mt++) {
        int rr = warpM * 32 + mt * 16 + g;
        #pragma unroll
        for (int nt = 0; nt < 3; nt++) {
            int c0 = warpN * 24 + nt * 8 + tg * 2;
            float bs0 = bias[c0], bs1 = bias[c0 + 1];
            S[rr * 100 + c0]            = acc[mt][nt][0] + bs0;
            S[rr * 100 + c0 + 1]        = acc[mt][nt][1] + bs1;
            S[(rr + 8) * 100 + c0]      = acc[mt][nt][2] + bs0;
            S[(rr + 8) * 100 + c0 + 1]  = acc[mt][nt][3] + bs1;
        }
    }
    __syncthreads();

    for (int rr = w; rr < 64; rr += 8) {
        int t = m0 + rr;
        int win = t / NTOKW, n = t % NTOKW;
        int bb  = win >> 11;
        int rem = win & 2047;
        int wd = rem >> 8, wh = (rem >> 4) & 15, ww = rem & 15;
        int zd = n / 49, r2 = n % 49, zh = r2 / 7, zw = r2 % 7;
        int sd = (wd * 2 + zd + 1) & 15;
        int shh = wh * 7 + zh + 3; if (shh >= 112) shh -= 112;
        int sww = ww * 7 + zw + 3; if (sww >= 112) sww -= 112;
        size_t sidx = (((size_t)bb * 16 + sd) * 112 + shh) * 112 + sww;
        const float* px = x + sidx * CDIM;
        const float* ps = S + rr * 100;
        float v0 = px[lane]      + ps[lane];
        float v1 = px[lane + 32] + ps[lane + 32];
        float v2 = px[lane + 64] + ps[lane + 64];
        float* pr = xres + sidx * CDIM;
        pr[lane] = v0; pr[lane + 32] = v1; pr[lane + 64] = v2;
        float s  = v0 + v1 + v2;
        float ss = v0 * v0 + v1 * v1 + v2 * v2;
        #pragma unroll
        for (int o = 16; o; o >>= 1) {
            s  += __shfl_xor_sync(0xFFFFFFFFu, s, o);
            ss += __shfl_xor_sync(0xFFFFFFFFu, ss, o);
        }
        float mu   = s * (1.0f / 96.0f);
        float var  = ss * (1.0f / 96.0f) - mu * mu;
        float rstd = rsqrtf(var + 1e-5f);
        bf16* po = xwh + sidx * CDIM;
        po[lane]      = __float2bfloat16((v0 - mu) * rstd * g2v[lane]      + b2v[lane]);
        po[lane + 32] = __float2bfloat16((v1 - mu) * rstd * g2v[lane + 32] + b2v[lane + 32]);
        po[lane + 64] = __float2bfloat16((v2 - mu) * rstd * g2v[lane + 64] + b2v[lane + 64]);
    }
}

// ---------------------------------------------------------------------------
// Tensor-core attention (identical to round 13).
// ---------------------------------------------------------------------------
#define QLD 36
#define KLD 36
#define VLD 116
#define PLD 116
#define SMEM_ATTN_BF 24480
#define SMEM_ATTN_BYTES (SMEM_ATTN_BF * 2 + 112 * 4)

__global__ __launch_bounds__(256)
void attn_kernel() {
    int wh   = blockIdx.x;
    int win  = wh / HEADS, head = wh % HEADS;
    int mw   = win & (NW_PB - 1);
    extern __shared__ bf16 smh[];
    bf16* Qs = smh;
    bf16* Ks = smh + 4032;
    bf16* Vt = smh + 7776;
    bf16* P  = smh + 11488;
    float* sinv = (float*)(smh + SMEM_ATTN_BF);
    int tid  = threadIdx.x;
    int w    = tid >> 5;
    int lane = tid & 31;
    int g    = lane >> 2;
    int tg   = lane & 3;
    uint2 Z2 = make_uint2(0u, 0u);

    const bf16* qkv = g_qkvh + (size_t)win * NTOKW * 288 + head * HDIM;
    for (int idx = tid; idx < 112 * 8; idx += 256) {
        int n = idx >> 3, d4 = (idx & 7) * 4;
        uint2 val = (n < NTOKW) ? *(const uint2*)(qkv + n * 288 + d4) : Z2;
        *(uint2*)(Qs + n * QLD + d4) = val;
    }
    for (int idx = tid; idx < 104 * 8; idx += 256) {
        int n = idx >> 3, d4 = (idx & 7) * 4;
        uint2 val = (n < NTOKW) ? *(const uint2*)(qkv + n * 288 + 96 + d4) : Z2;
        *(uint2*)(Ks + n * KLD + d4) = val;
    }
    for (int idx = tid; idx < 112 * 8; idx += 256) {
        int n = idx >> 3, d4 = (idx & 7) * 4;
        uint2 val = (n < NTOKW) ? *(const uint2*)(qkv + n * 288 + 192 + d4) : Z2;
        bf162 lo = *(bf162*)&val.x;
        bf162 hi = *(bf162*)&val.y;
        Vt[(d4 + 0) * VLD + n] = lo.x;
        Vt[(d4 + 1) * VLD + n] = lo.y;
        Vt[(d4 + 2) * VLD + n] = hi.x;
        Vt[(d4 + 3) * VLD + n] = hi.y;
    }
    {
        const uint32_t* mp = (const uint32_t*)(g_maskh + (size_t)mw * 9604);
        const uint32_t* rp = (const uint32_t*)(g_rpbh + head * 9604);
        uint32_t* Pu = (uint32_t*)P;
        for (int u = tid; u < 4802; u += 256) {
            int i = u / 49, c = u % 49;
            uint32_t mv = mp[u], rv = rp[u];
            bf162 sum = __hadd2(*(bf162*)&mv, *(bf162*)&rv);
            Pu[i * (PLD / 2) + c] = *(uint32_t*)&sum;
        }
        for (int u = tid; u < 98 * 7; u += 256) {
            int i = u / 7, c = 49 + u % 7;
            Pu[i * (PLD / 2) + c] = 0;
        }
    }
    __syncthreads();

    int row0 = w * 16;
    if (w < 7) {
        #pragma unroll
        for (int h2 = 0; h2 < 2; h2++) {
            int ntbase = h2 * 7;
            int NT = h2 ? 6 : 7;
            float acc[7][4];
            #pragma unroll
            for (int t = 0; t < 7; t++)
                #pragma unroll
                for (int q = 0; q < 4; q++) acc[t][q] = 0.0f;
            #pragma unroll
            for (int ks = 0; ks < 2; ks++) {
                uint32_t afr[4];
                const uint32_t* ap = (const uint32_t*)
                    (Qs + (row0 + g) * QLD + ks * 16 + tg * 2);
                afr[0] = ap[0];
                afr[1] = ap[8 * (QLD / 2)];
                afr[2] = ap[4];
                afr[3] = ap[8 * (QLD / 2) + 4];
                for (int t = 0; t < NT; t++) {
                    int n = (ntbase + t) * 8 + g;
                    const uint32_t* bp = (const uint32_t*)
                        (Ks + n * KLD + ks * 16 + tg * 2);
                    mma_bf16(acc[t], afr, bp[0], bp[4]);
                }
            }
            for (int t = 0; t < NT; t++) {
                int c0 = (ntbase + t) * 8 + tg * 2;
                bf162* p0 = (bf162*)(P + (row0 + g) * PLD + c0);
                bf162* p1 = (bf162*)(P + (row0 + g + 8) * PLD + c0);
                float2 f0 = __bfloat1622float2(*p0);
                float2 f1 = __bfloat1622float2(*p1);
                *p0 = __floats2bfloat162_rn(acc[t][0] * SCALE + f0.x,
                                            acc[t][1] * SCALE + f0.y);
                *p1 = __floats2bfloat162_rn(acc[t][2] * SCALE + f1.x,
                                            acc[t][3] * SCALE + f1.y);
            }
        }
    }
    __syncthreads();

    for (int r = w; r < NTOKW; r += 8) {
        uint32_t* prow = (uint32_t*)(P + r * PLD);
        float s = 0.0f;
        for (int jp = lane; jp < 49; jp += 32) {
            uint32_t v = prow[jp];
            bf162 e = h2exp(*(bf162*)&v);
            prow[jp] = *(uint32_t*)&e;
            float2 f = __bfloat1622float2(e);
            s += f.x + f.y;
        }
        #pragma unroll
        for (int o = 16; o; o >>= 1) s += __shfl_xor_sync(0xFFFFFFFFu, s, o);
        if (lane == 0) sinv[r] = 1.0f / s;
    }
    __syncthreads();

    if (w < 7) {
        float acc[4][4];
        #pragma unroll
        for (int t = 0; t < 4; t++)
            #pragma unroll
            for (int q = 0; q < 4; q++) acc[t][q] = 0.0f;
        #pragma unroll
        for (int ks = 0; ks < 7; ks++) {
            uint32_t afr[4];
            const uint32_t* ap = (const uint32_t*)
                (P + (row0 + g) * PLD + ks * 16 + tg * 2);
            afr[0] = ap[0];
            afr[1] = ap[8 * (PLD / 2)];
            afr[2] = ap[4];
            afr[3] = ap[8 * (PLD / 2) + 4];
            #pragma unroll
            for (int nt = 0; nt < 4; nt++) {
                const uint32_t* bp = (const uint32_t*)
                    (Vt + (nt * 8 + g) * VLD + ks * 16 + tg * 2);
                mma_bf16(acc[nt], afr, bp[0], bp[4]);
            }
        }
        int r = row0 + g;
        float i0 = (r < NTOKW)     ? sinv[r]     : 0.0f;
        float i1 = (r + 8 < NTOKW) ? sinv[r + 8] : 0.0f;
        size_t obase = ((size_t)win * NTOKW + r) * CDIM + head * HDIM;
        #pragma unroll
        for (int nt = 0; nt < 4; nt++) {
            int c0 = nt * 8 + tg * 2;
            if (r < NTOKW)
                *(bf162*)&g_attnh[obase + c0] =
                    __floats2bfloat162_rn(acc[nt][0] * i0, acc[nt][1] * i0);
            if (r + 8 < NTOKW)
                *(bf162*)&g_attnh[obase + 8 * CDIM + c0] =
                    __floats2bfloat162_rn(acc[nt][2] * i1, acc[nt][3] * i1);
        }
    }
}

// ---------------------------------------------------------------------------
extern "C" void kernel_launch(void* const* d_in, const int* in_sizes, int n_in,
                              void* d_out, int out_size) {
    const float* x         = (const float*)d_in[0];
    const float* attn_mask = (const float*)d_in[1];
    const float* g1        = (const float*)d_in[2];
    const float* b1        = (const float*)d_in[3];
    const float* qkv_w     = (const float*)d_in[4];
    const float* qkv_b     = (const float*)d_in[5];
    const float* rpb_table = (const float*)d_in[6];
    const float* proj_w    = (const float*)d_in[7];
    const float* proj_b    = (const float*)d_in[8];
    const float* g2        = (const float*)d_in[9];
    const float* b2        = (const float*)d_in[10];
    const float* fc1_w     = (const float*)d_in[11];
    const float* fc1_b     = (const float*)d_in[12];
    const float* fc2_w     = (const float*)d_in[13];
    const float* fc2_b     = (const float*)d_in[14];
    float* out = (float*)d_out;

    bf16 *p_xwh, *p_qkvh, *p_attnh, *p_h, *p_wh;
    float *p_xres;
    cudaGetSymbolAddress((void**)&p_xwh,   g_xwh);
    cudaGetSymbolAddress((void**)&p_qkvh,  g_qkvh);
    cudaGetSymbolAddress((void**)&p_attnh, g_attnh);
    cudaGetSymbolAddress((void**)&p_h,     g_h);
    cudaGetSymbolAddress((void**)&p_wh,    g_wh);
    cudaGetSymbolAddress((void**)&p_xres,  g_xres);

    const int attn_smem = SMEM_ATTN_BYTES;           // 49.4 KB
    cudaFuncSetAttribute(attn_kernel, cudaFuncAttributeMaxDynamicSharedMemorySize, attn_smem);

    conv_weights<<<432, 256>>>(qkv_w, proj_w, fc1_w, fc2_w);
    rpb_expand<<<(HEADS * NTOKW * NTOKW + 255) / 256, 256>>>(rpb_table);
    mask_conv<<<(NW_PB * NTOKW * NTOKW) / (4 * 256), 256>>>(attn_mask);

    ln1_shift_win<<<NTOK / 4, 128>>>(x, g1, b1);

    // QKV gemm (M, 288, 96) -> bf16
    mma_gemm<0,1><<<dim3(288 / 96, NTOK / 64), 256>>>(
        p_xwh, p_wh, qkv_b, nullptr, p_qkvh, NTOK, 288, 96);

    attn_kernel<<<NWIN * HEADS, 256, attn_smem>>>();

    // proj gemm + residual + LN2 (fused)
    proj_fused<<<NTOK / 64, 256>>>(
        p_attnh, p_wh + 27648, proj_b, x, g2, b2, p_xres, p_xwh);

    // fc1 + gelu (M, 384, 96) -> bf16 h
    mma_gemm<1,1><<<dim3(HID / 96, NTOK / 64), 256>>>(
        p_xwh, p_wh + 36864, fc1_b, nullptr, p_h, NTOK, HID, 96);

    // fc2 + residual (M, 96, 384) -> fp32 d_out
    mma_gemm<2,0><<<dim3(1, NTOK / 64), 256>>>(
        p_h, p_wh + 73728, fc2_b, p_xres, out, NTOK, 96, HID);
}

// round 15
// speedup vs baseline: 3.8181x; 1.0008x over previous
#include <cuda_runtime.h>
#include <cuda_bf16.h>
#include <cstdint>
#include <math.h>

// ---------------------------------------------------------------------------
// Swin Transformer 3D block — round 15:
//   attn: Q pre-scaled at load; QK^T acc initialized from global mask+rpb
//         (bias staging phase + RMW epilogue removed)
//   GEMMs: __launch_bounds__(256,3) -> 3 blocks/SM
// ---------------------------------------------------------------------------

#define NTOK   401408
#define CDIM   96
#define NWIN   4096
#define NW_PB  2048
#define NTOKW  98
#define HEADS  3
#define HDIM   32
#define SCALE  0.17677669529663687f
#define HID    384

typedef __nv_bfloat16 bf16;
typedef __nv_bfloat162 bf162;

// -------------------------- device scratch ---------------------------------
__device__ bf16  g_xwh  [(size_t)NTOK * CDIM];
__device__ bf16  g_qkvh [(size_t)NTOK * 288];
__device__ bf16  g_attnh[(size_t)NTOK * CDIM];
__device__ bf16  g_h    [(size_t)NTOK * HID];
__device__ float g_xres [(size_t)NTOK * CDIM];
__device__ bf16  g_rpbh [HEADS * NTOKW * NTOKW];
__device__ bf16  g_maskh[(size_t)NW_PB * NTOKW * NTOKW];
__device__ bf16  g_wh   [110592];

// ---------------------------------------------------------------------------
__global__ void conv_weights(const float* __restrict__ qkv_w,
                             const float* __restrict__ proj_w,
                             const float* __restrict__ fc1_w,
                             const float* __restrict__ fc2_w) {
    int idx = blockIdx.x * 256 + threadIdx.x;       // 110592 total, exact
    const float* src; int off;
    if (idx < 27648)       { src = qkv_w;  off = idx; }
    else if (idx < 36864)  { src = proj_w; off = idx - 27648; }
    else if (idx < 73728)  { src = fc1_w;  off = idx - 36864; }
    else                   { src = fc2_w;  off = idx - 73728; }
    g_wh[idx] = __float2bfloat16(src[off]);
}

// ---------------------------------------------------------------------------
__global__ void rpb_expand(const float* __restrict__ table) {
    int idx = blockIdx.x * 256 + threadIdx.x;
    if (idx >= HEADS * NTOKW * NTOKW) return;
    int head = idx / (NTOKW * NTOKW);
    int r = idx % (NTOKW * NTOKW);
    int i = r / NTOKW, j = r % NTOKW;
    int zdi = i / 49, zhi = (i / 7) % 7, zwi = i % 7;
    int zdj = j / 49, zhj = (j / 7) % 7, zwj = j % 7;
    int ridx = (zdi - zdj + 1) * 169 + (zhi - zhj + 6) * 13 + (zwi - zwj + 6);
    g_rpbh[idx] = __float2bfloat16(table[ridx * 3 + head]);
}

// ---------------------------------------------------------------------------
__global__ void mask_conv(const float* __restrict__ mask) {
    int idx = blockIdx.x * 256 + threadIdx.x;        // 19208 blocks, exact
    float4 m = *(const float4*)&mask[(size_t)idx * 4];
    bf162 lo = __floats2bfloat162_rn(m.x, m.y);
    bf162 hi = __floats2bfloat162_rn(m.z, m.w);
    uint2 pk = make_uint2(*(uint32_t*)&lo, *(uint32_t*)&hi);
    *(uint2*)&g_maskh[(size_t)idx * 4] = pk;
}

// ---------------------------------------------------------------------------
__global__ void ln1_shift_win(const float* __restrict__ x,
                              const float* __restrict__ g,
                              const float* __restrict__ b) {
    int t    = blockIdx.x * 4 + (threadIdx.x >> 5);
    int lane = threadIdx.x & 31;
    int win = t / NTOKW, n = t % NTOKW;
    int bb  = win >> 11;
    int rem = win & 2047;
    int wd = rem >> 8, wh = (rem >> 4) & 15, ww = rem & 15;
    int zd = n / 49, r2 = n % 49, zh = r2 / 7, zw = r2 % 7;
    int sd = (wd * 2 + zd + 1) & 15;
    int sh = wh * 7 + zh + 3; if (sh >= 112) sh -= 112;
    int sw = ww * 7 + zw + 3; if (sw >= 112) sw -= 112;
    const float* px = x + ((((size_t)bb * 16 + sd) * 112 + sh) * 112 + sw) * CDIM;
    float v0 = px[lane], v1 = px[lane + 32], v2 = px[lane + 64];
    float s  = v0 + v1 + v2;
    float ss = v0 * v0 + v1 * v1 + v2 * v2;
    #pragma unroll
    for (int o = 16; o; o >>= 1) {
        s  += __shfl_xor_sync(0xFFFFFFFFu, s, o);
        ss += __shfl_xor_sync(0xFFFFFFFFu, ss, o);
    }
    float mu   = s * (1.0f / 96.0f);
    float var  = ss * (1.0f / 96.0f) - mu * mu;
    float rstd = rsqrtf(var + 1e-5f);
    bf16* po = g_xwh + (size_t)t * CDIM;
    po[lane]      = __float2bfloat16((v0 - mu) * rstd * g[lane]      + b[lane]);
    po[lane + 32] = __float2bfloat16((v1 - mu) * rstd * g[lane + 32] + b[lane + 32]);
    po[lane + 64] = __float2bfloat16((v2 - mu) * rstd * g[lane + 64] + b[lane + 64]);
}

// ---------------------------------------------------------------------------
__device__ __forceinline__ void mma_bf16(float c[4], const uint32_t a[4],
                                         uint32_t b0, uint32_t b1) {
    asm volatile(
        "mma.sync.aligned.m16n8k16.row.col.f32.bf16.bf16.f32 "
        "{%0,%1,%2,%3}, {%4,%5,%6,%7}, {%8,%9}, {%0,%1,%2,%3};"
        : "+f"(c[0]), "+f"(c[1]), "+f"(c[2]), "+f"(c[3])
        : "r"(a[0]), "r"(a[1]), "r"(a[2]), "r"(a[3]), "r"(b0), "r"(b1));
}
__device__ __forceinline__ void ldsm4(uint32_t r[4], uint32_t saddr) {
    asm volatile("ldmatrix.sync.aligned.m8n8.x4.shared.b16 {%0,%1,%2,%3}, [%4];"
        : "=r"(r[0]), "=r"(r[1]), "=r"(r[2]), "=r"(r[3]) : "r"(saddr));
}
__device__ __forceinline__ void cp_async16(uint32_t smem_addr, const void* gptr) {
    asm volatile("cp.async.ca.shared.global [%0], [%1], 16;"
                 :: "r"(smem_addr), "l"(gptr));
}
__device__ __forceinline__ void cp_commit() {
    asm volatile("cp.async.commit_group;" ::: "memory");
}
template<int N>
__device__ __forceinline__ void cp_wait() {
    asm volatile("cp.async.wait_group %0;" :: "n"(N) : "memory");
}

// ---------------------------------------------------------------------------
// GEMM v4: BM=64, BN=96, BK=32, 2-stage cp.async, ldmatrix A-frags,
//   3 blocks/SM.  EPI: 0=bias, 1=bias+gelu, 2=bias+res.  OUTB: bf16/fp32 out.
// ---------------------------------------------------------------------------
#define GLD  40
#define STG  ((64 + 96) * GLD)  // bf16 units per stage = 6400

template<int EPI, int OUTB>
__global__ __launch_bounds__(256, 3)
void mma_gemm(const bf16* __restrict__ A, const bf16* __restrict__ B,
              const float* __restrict__ bias, const float* __restrict__ res,
              void* __restrict__ Cv, int M, int N, int K) {
    __shared__ __align__(16) bf16 sh[2 * STG];          // 25.6 KB

    int tid  = threadIdx.x;
    int w    = tid >> 5;
    int lane = tid & 31;
    int g    = lane >> 2;
    int tg   = lane & 3;
    int warpM = w & 1;
    int warpN = w >> 1;
    int m0 = blockIdx.y * 64;
    int n0 = blockIdx.x * 96;

    int ar = tid >> 2, ac = tid & 3;
    int br0 = tid >> 2, bc0 = tid & 3;
    int bi1 = 256 + tid;
    int br1 = bi1 >> 2, bc1 = bi1 & 3;

    uint32_t sbase = (uint32_t)__cvta_generic_to_shared(sh);
    uint32_t loff = (((lane & 15) * GLD) + ((lane >> 4) * 8)) * 2;

    float acc[2][3][4];
    #pragma unroll
    for (int i = 0; i < 2; i++)
        #pragma unroll
        for (int j = 0; j < 3; j++)
            #pragma unroll
            for (int t = 0; t < 4; t++) acc[i][j][t] = 0.0f;

    int KC = K >> 5;

    {
        cp_async16(sbase + (ar * GLD + ac * 8) * 2,
                   &A[(size_t)(m0 + ar) * K + ac * 8]);
        cp_async16(sbase + ((64 + br0) * GLD + bc0 * 8) * 2,
                   &B[(size_t)(n0 + br0) * K + bc0 * 8]);
        if (tid < 128)
            cp_async16(sbase + ((64 + br1) * GLD + bc1 * 8) * 2,
                       &B[(size_t)(n0 + br1) * K + bc1 * 8]);
        cp_commit();
    }

    for (int kc = 0; kc < KC; kc++) {
        if (kc + 1 < KC) {
            int k0 = (kc + 1) << 5;
            uint32_t sb = sbase + ((kc + 1) & 1) * STG * 2;
            cp_async16(sb + (ar * GLD + ac * 8) * 2,
                       &A[(size_t)(m0 + ar) * K + k0 + ac * 8]);
            cp_async16(sb + ((64 + br0) * GLD + bc0 * 8) * 2,
                       &B[(size_t)(n0 + br0) * K + k0 + bc0 * 8]);
            if (tid < 128)
                cp_async16(sb + ((64 + br1) * GLD + bc1 * 8) * 2,
                           &B[(size_t)(n0 + br1) * K + k0 + bc1 * 8]);
            cp_commit();
            cp_wait<1>();
        } else {
            cp_wait<0>();
        }
        __syncthreads();

        uint32_t sst = sbase + (kc & 1) * STG * 2;
        const bf16* Bs = sh + (kc & 1) * STG + 64 * GLD;
        uint32_t aA = sst + (warpM * 32 * GLD) * 2 + loff;

        #pragma unroll
        for (int ks = 0; ks < 2; ks++) {
            uint32_t afr[2][4];
            #pragma unroll
            for (int mt = 0; mt < 2; mt++)
                ldsm4(afr[mt], aA + (mt * 16 * GLD + ks * 16) * 2);
            #pragma unroll
            for (int nt = 0; nt < 3; nt++) {
                const uint32_t* bp = (const uint32_t*)
                    (Bs + (warpN * 24 + nt * 8 + g) * GLD + ks * 16 + tg * 2);
                uint32_t b0 = bp[0], b1 = bp[4];
                #pragma unroll
                for (int mt = 0; mt < 2; mt++)
                    mma_bf16(acc[mt][nt], afr[mt], b0, b1);
            }
        }
        __syncthreads();
    }

    #pragma unroll
    for (int mt = 0; mt < 2; mt++) {
        int r0 = m0 + warpM * 32 + mt * 16 + g;
        #pragma unroll
        for (int nt = 0; nt < 3; nt++) {
            int c0 = n0 + warpN * 24 + nt * 8 + tg * 2;
            float bs0 = bias[c0], bs1 = bias[c0 + 1];
            float v0 = acc[mt][nt][0] + bs0;
            float v1 = acc[mt][nt][1] + bs1;
            float v2 = acc[mt][nt][2] + bs0;
            float v3 = acc[mt][nt][3] + bs1;
            if (EPI == 1) {
                v0 = 0.5f * v0 * (1.0f + erff(v0 * 0.70710678118654752f));
                v1 = 0.5f * v1 * (1.0f + erff(v1 * 0.70710678118654752f));
                v2 = 0.5f * v2 * (1.0f + erff(v2 * 0.70710678118654752f));
                v3 = 0.5f * v3 * (1.0f + erff(v3 * 0.70710678118654752f));
            }
            if (EPI == 2) {
                const float* rp0 = &res[(size_t)r0 * N + c0];
                const float* rp1 = &res[(size_t)(r0 + 8) * N + c0];
                v0 += rp0[0]; v1 += rp0[1];
                v2 += rp1[0]; v3 += rp1[1];
            }
            if (OUTB) {
                bf16* C = (bf16*)Cv;
                *(bf162*)&C[(size_t)r0 * N + c0]       = __floats2bfloat162_rn(v0, v1);
                *(bf162*)&C[(size_t)(r0 + 8) * N + c0] = __floats2bfloat162_rn(v2, v3);
            } else {
                float* C = (float*)Cv;
                *(float2*)&C[(size_t)r0 * N + c0]       = make_float2(v0, v1);
                *(float2*)&C[(size_t)(r0 + 8) * N + c0] = make_float2(v2, v3);
            }
        }
    }
}

// ---------------------------------------------------------------------------
// proj GEMM fused with window-reverse residual + LN2.
// ---------------------------------------------------------------------------
__global__ __launch_bounds__(256, 3)
void proj_fused(const bf16* __restrict__ A, const bf16* __restrict__ B,
                const float* __restrict__ bias,
                const float* __restrict__ x,
                const float* __restrict__ g2v, const float* __restrict__ b2v,
                float* __restrict__ xres, bf16* __restrict__ xwh) {
    __shared__ __align__(16) bf16 sh[2 * STG];   // 25.6 KB; reused as S[64][100]
    const int K = 96;

    int tid  = threadIdx.x;
    int w    = tid >> 5;
    int lane = tid & 31;
    int g    = lane >> 2;
    int tg   = lane & 3;
    int warpM = w & 1;
    int warpN = w >> 1;
    int m0 = blockIdx.x * 64;

    int ar = tid >> 2, ac = tid & 3;
    int br0 = tid >> 2, bc0 = tid & 3;
    int bi1 = 256 + tid;
    int br1 = bi1 >> 2, bc1 = bi1 & 3;

    uint32_t sbase = (uint32_t)__cvta_generic_to_shared(sh);
    uint32_t loff = (((lane & 15) * GLD) + ((lane >> 4) * 8)) * 2;

    float acc[2][3][4];
    #pragma unroll
    for (int i = 0; i < 2; i++)
        #pragma unroll
        for (int j = 0; j < 3; j++)
            #pragma unroll
            for (int t = 0; t < 4; t++) acc[i][j][t] = 0.0f;

    {
        cp_async16(sbase + (ar * GLD + ac * 8) * 2,
                   &A[(size_t)(m0 + ar) * K + ac * 8]);
        cp_async16(sbase + ((64 + br0) * GLD + bc0 * 8) * 2,
                   &B[(size_t)br0 * K + bc0 * 8]);
        if (tid < 128)
            cp_async16(sbase + ((64 + br1) * GLD + bc1 * 8) * 2,
                       &B[(size_t)br1 * K + bc1 * 8]);
        cp_commit();
    }

    for (int kc = 0; kc < 3; kc++) {
        if (kc + 1 < 3) {
            int k0 = (kc + 1) << 5;
            uint32_t sb = sbase + ((kc + 1) & 1) * STG * 2;
            cp_async16(sb + (ar * GLD + ac * 8) * 2,
                       &A[(size_t)(m0 + ar) * K + k0 + ac * 8]);
            cp_async16(sb + ((64 + br0) * GLD + bc0 * 8) * 2,
                       &B[(size_t)br0 * K + k0 + bc0 * 8]);
            if (tid < 128)
                cp_async16(sb + ((64 + br1) * GLD + bc1 * 8) * 2,
                           &B[(size_t)br1 * K + k0 + bc1 * 8]);
            cp_commit();
            cp_wait<1>();
        } else {
            cp_wait<0>();
        }
        __syncthreads();

        uint32_t sst = sbase + (kc & 1) * STG * 2;
        const bf16* Bs = sh + (kc & 1) * STG + 64 * GLD;
        uint32_t aA = sst + (warpM * 32 * GLD) * 2 + loff;

        #pragma unroll
        for (int ks = 0; ks < 2; ks++) {
            uint32_t afr[2][4];
            #pragma unroll
            for (int mt = 0; mt < 2; mt++)
                ldsm4(afr[mt], aA + (mt * 16 * GLD + ks * 16) * 2);
            #pragma unroll
            for (int nt = 0; nt < 3; nt++) {
                const uint32_t* bp = (const uint32_t*)
                    (Bs + (warpN * 24 + nt * 8 + g) * GLD + ks * 16 + tg * 2);
                uint32_t b0 = bp[0], b1 = bp[4];
                #pragma unroll
                for (int mt = 0; mt < 2; mt++)
                    mma_bf16(acc[mt][nt], afr[mt], b0, b1);
            }
        }
        __syncthreads();
    }

    float* S = (float*)sh;
    #pragma unroll
    for (int mt = 0; mt < 2; mt++) {
        int rr = warpM * 32 + mt * 16 + g;
        #pragma unroll
        for (int nt = 0; nt < 3; nt++) {
            int c0 = warpN * 24 + nt * 8 + tg * 2;
            float bs0 = bias[c0], bs1 = bias[c0 + 1];
            S[rr * 100 + c0]            = acc[mt][nt][0] + bs0;
            S[rr * 100 + c0 + 1]        = acc[mt][nt][1] + bs1;
            S[(rr + 8) * 100 + c0]      = acc[mt][nt][2] + bs0;
            S[(rr + 8) * 100 + c0 + 1]  = acc[mt][nt][3] + bs1;
        }
    }
    __syncthreads();

    for (int rr = w; rr < 64; rr += 8) {
        int t = m0 + rr;
        int win = t / NTOKW, n = t % NTOKW;
        int bb  = win >> 11;
        int rem = win & 2047;
        int wd = rem >> 8, wh = (rem >> 4) & 15, ww = rem & 15;
        int zd = n / 49, r2 = n % 49, zh = r2 / 7, zw = r2 % 7;
        int sd = (wd * 2 + zd + 1) & 15;
        int shh = wh * 7 + zh + 3; if (shh >= 112) shh -= 112;
        int sww = ww * 7 + zw + 3; if (sww >= 112) sww -= 112;
        size_t sidx = (((size_t)bb * 16 + sd) * 112 + shh) * 112 + sww;
        const float* px = x + sidx * CDIM;
        const float* ps = S + rr * 100;
        float v0 = px[lane]      + ps[lane];
        float v1 = px[lane + 32] + ps[lane + 32];
        float v2 = px[lane + 64] + ps[lane + 64];
        float* pr = xres + sidx * CDIM;
        pr[lane] = v0; pr[lane + 32] = v1; pr[lane + 64] = v2;
        float s  = v0 + v1 + v2;
        float ss = v0 * v0 + v1 * v1 + v2 * v2;
        #pragma unroll
        for (int o = 16; o; o >>= 1) {
            s  += __shfl_xor_sync(0xFFFFFFFFu, s, o);
            ss += __shfl_xor_sync(0xFFFFFFFFu, ss, o);
        }
        float mu   = s * (1.0f / 96.0f);
        float var  = ss * (1.0f / 96.0f) - mu * mu;
        float rstd = rsqrtf(var + 1e-5f);
        bf16* po = xwh + sidx * CDIM;
        po[lane]      = __float2bfloat16((v0 - mu) * rstd * g2v[lane]      + b2v[lane]);
        po[lane + 32] = __float2bfloat16((v1 - mu) * rstd * g2v[lane + 32] + b2v[lane + 32]);
        po[lane + 64] = __float2bfloat16((v2 - mu) * rstd * g2v[lane + 64] + b2v[lane + 64]);
    }
}

// ---------------------------------------------------------------------------
// Tensor-core attention: Q pre-scaled; QK^T acc init from global mask+rpb;
// pure-store epilogue.  Softmax/PV as round 13.
// ---------------------------------------------------------------------------
#define QLD 36
#define KLD 36
#define VLD 116
#define PLD 116
#define SMEM_ATTN_BF 24480
#define SMEM_ATTN_BYTES (SMEM_ATTN_BF * 2 + 112 * 4)

__global__ __launch_bounds__(256)
void attn_kernel() {
    int wh   = blockIdx.x;
    int win  = wh / HEADS, head = wh % HEADS;
    int mw   = win & (NW_PB - 1);
    extern __shared__ bf16 smh[];
    bf16* Qs = smh;
    bf16* Ks = smh + 4032;
    bf16* Vt = smh + 7776;
    bf16* P  = smh + 11488;
    float* sinv = (float*)(smh + SMEM_ATTN_BF);
    int tid  = threadIdx.x;
    int w    = tid >> 5;
    int lane = tid & 31;
    int g    = lane >> 2;
    int tg   = lane & 3;
    uint2 Z2 = make_uint2(0u, 0u);
    bf162 sc2 = __float2bfloat162_rn(SCALE);

    const bf16* qkv = g_qkvh + (size_t)win * NTOKW * 288 + head * HDIM;
    // Q: pre-scaled by SCALE
    for (int idx = tid; idx < 112 * 8; idx += 256) {
        int n = idx >> 3, d4 = (idx & 7) * 4;
        uint2 val = (n < NTOKW) ? *(const uint2*)(qkv + n * 288 + d4) : Z2;
        bf162 lo = __hmul2(*(bf162*)&val.x, sc2);
        bf162 hi = __hmul2(*(bf162*)&val.y, sc2);
        val.x = *(uint32_t*)&lo; val.y = *(uint32_t*)&hi;
        *(uint2*)(Qs + n * QLD + d4) = val;
    }
    for (int idx = tid; idx < 104 * 8; idx += 256) {
        int n = idx >> 3, d4 = (idx & 7) * 4;
        uint2 val = (n < NTOKW) ? *(const uint2*)(qkv + n * 288 + 96 + d4) : Z2;
        *(uint2*)(Ks + n * KLD + d4) = val;
    }
    for (int idx = tid; idx < 112 * 8; idx += 256) {
        int n = idx >> 3, d4 = (idx & 7) * 4;
        uint2 val = (n < NTOKW) ? *(const uint2*)(qkv + n * 288 + 192 + d4) : Z2;
        bf162 lo = *(bf162*)&val.x;
        bf162 hi = *(bf162*)&val.y;
        Vt[(d4 + 0) * VLD + n] = lo.x;
        Vt[(d4 + 1) * VLD + n] = lo.y;
        Vt[(d4 + 2) * VLD + n] = hi.x;
        Vt[(d4 + 3) * VLD + n] = hi.y;
    }
    // only pad cols 104..111 of P need zeroing (tiles write cols 0..103)
    {
        uint32_t* Pu = (uint32_t*)P;
        for (int u = tid; u < 112 * 4; u += 256) {
            int i = u >> 2, c = 52 + (u & 3);
            Pu[i * (PLD / 2) + c] = 0;
        }
    }
    __syncthreads();

    int row0 = w * 16;
    if (w < 7) {
        const bf16* mrow = g_maskh + (size_t)mw * 9604;
        const bf16* rrow = g_rpbh + head * 9604;
        int i0 = row0 + g, i1 = row0 + g + 8;
        #pragma unroll
        for (int h2 = 0; h2 < 2; h2++) {
            int ntbase = h2 * 7;
            int NT = h2 ? 6 : 7;
            float acc[7][4];
            // acc init = mask + rpb (0 outside the 98x98 region)
            for (int t = 0; t < NT; t++) {
                int c0 = (ntbase + t) * 8 + tg * 2;
                float2 b0 = make_float2(0.0f, 0.0f);
                float2 b1 = make_float2(0.0f, 0.0f);
                if (c0 < 98) {
                    if (i0 < NTOKW) {
                        bf162 m = *(const bf162*)(mrow + i0 * 98 + c0);
                        bf162 r = *(const bf162*)(rrow + i0 * 98 + c0);
                        b0 = __bfloat1622float2(__hadd2(m, r));
                    }
                    if (i1 < NTOKW) {
                        bf162 m = *(const bf162*)(mrow + i1 * 98 + c0);
                        bf162 r = *(const bf162*)(rrow + i1 * 98 + c0);
                        b1 = __bfloat1622float2(__hadd2(m, r));
                    }
                }
                acc[t][0] = b0.x; acc[t][1] = b0.y;
                acc[t][2] = b1.x; acc[t][3] = b1.y;
            }
            #pragma unroll
            for (int ks = 0; ks < 2; ks++) {
                uint32_t afr[4];
                const uint32_t* ap = (const uint32_t*)
                    (Qs + (row0 + g) * QLD + ks * 16 + tg * 2);
                afr[0] = ap[0];
                afr[1] = ap[8 * (QLD / 2)];
                afr[2] = ap[4];
                afr[3] = ap[8 * (QLD / 2) + 4];
                for (int t = 0; t < NT; t++) {
                    int n = (ntbase + t) * 8 + g;
                    const uint32_t* bp = (const uint32_t*)
                        (Ks + n * KLD + ks * 16 + tg * 2);
                    mma_bf16(acc[t], afr, bp[0], bp[4]);
                }
            }
            // pure-store epilogue
            for (int t = 0; t < NT; t++) {
                int c0 = (ntbase + t) * 8 + tg * 2;
                *(bf162*)(P + (row0 + g) * PLD + c0) =
                    __floats2bfloat162_rn(acc[t][0], acc[t][1]);
                *(bf162*)(P + (row0 + g + 8) * PLD + c0) =
                    __floats2bfloat162_rn(acc[t][2], acc[t][3]);
            }
        }
    }
    __syncthreads();

    for (int r = w; r < NTOKW; r += 8) {
        uint32_t* prow = (uint32_t*)(P + r * PLD);
        float s = 0.0f;
        for (int jp = lane; jp < 49; jp += 32) {
            uint32_t v = prow[jp];
            bf162 e = h2exp(*(bf162*)&v);
            prow[jp] = *(uint32_t*)&e;
            float2 f = __bfloat1622float2(e);
            s += f.x + f.y;
        }
        #pragma unroll
        for (int o = 16; o; o >>= 1) s += __shfl_xor_sync(0xFFFFFFFFu, s, o);
        if (lane == 0) sinv[r] = 1.0f / s;
    }
    __syncthreads();

    if (w < 7) {
        float acc[4][4];
        #pragma unroll
        for (int t = 0; t < 4; t++)
            #pragma unroll
            for (int q = 0; q < 4; q++) acc[t][q] = 0.0f;
        #pragma unroll
        for (int ks = 0; ks < 7; ks++) {
            uint32_t afr[4];
            const uint32_t* ap = (const uint32_t*)
                (P + (row0 + g) * PLD + ks * 16 + tg * 2);
            afr[0] = ap[0];
            afr[1] = ap[8 * (PLD / 2)];
            afr[2] = ap[4];
            afr[3] = ap[8 * (PLD / 2) + 4];
            #pragma unroll
            for (int nt = 0; nt < 4; nt++) {
                const uint32_t* bp = (const uint32_t*)
                    (Vt + (nt * 8 + g) * VLD + ks * 16 + tg * 2);
                mma_bf16(acc[nt], afr, bp[0], bp[4]);
            }
        }
        int r = row0 + g;
        float i0 = (r < NTOKW)     ? sinv[r]     : 0.0f;
        float i1 = (r + 8 < NTOKW) ? sinv[r + 8] : 0.0f;
        size_t obase = ((size_t)win * NTOKW + r) * CDIM + head * HDIM;
        #pragma unroll
        for (int nt = 0; nt < 4; nt++) {
            int c0 = nt * 8 + tg * 2;
            if (r < NTOKW)
                *(bf162*)&g_attnh[obase + c0] =
                    __floats2bfloat162_rn(acc[nt][0] * i0, acc[nt][1] * i0);
            if (r + 8 < NTOKW)
                *(bf162*)&g_attnh[obase + 8 * CDIM + c0] =
                    __floats2bfloat162_rn(acc[nt][2] * i1, acc[nt][3] * i1);
        }
    }
}

// ---------------------------------------------------------------------------
extern "C" void kernel_launch(void* const* d_in, const int* in_sizes, int n_in,
                              void* d_out, int out_size) {
    const float* x         = (const float*)d_in[0];
    const float* attn_mask = (const float*)d_in[1];
    const float* g1        = (const float*)d_in[2];
    const float* b1        = (const float*)d_in[3];
    const float* qkv_w     = (const float*)d_in[4];
    const float* qkv_b     = (const float*)d_in[5];
    const float* rpb_table = (const float*)d_in[6];
    const float* proj_w    = (const float*)d_in[7];
    const float* proj_b    = (const float*)d_in[8];
    const float* g2        = (const float*)d_in[9];
    const float* b2        = (const float*)d_in[10];
    const float* fc1_w     = (const float*)d_in[11];
    const float* fc1_b     = (const float*)d_in[12];
    const float* fc2_w     = (const float*)d_in[13];
    const float* fc2_b     = (const float*)d_in[14];
    float* out = (float*)d_out;

    bf16 *p_xwh, *p_qkvh, *p_attnh, *p_h, *p_wh;
    float *p_xres;
    cudaGetSymbolAddress((void**)&p_xwh,   g_xwh);
    cudaGetSymbolAddress((void**)&p_qkvh,  g_qkvh);
    cudaGetSymbolAddress((void**)&p_attnh, g_attnh);
    cudaGetSymbolAddress((void**)&p_h,     g_h);
    cudaGetSymbolAddress((void**)&p_wh,    g_wh);
    cudaGetSymbolAddress((void**)&p_xres,  g_xres);

    const int attn_smem = SMEM_ATTN_BYTES;           // 49.4 KB
    cudaFuncSetAttribute(attn_kernel, cudaFuncAttributeMaxDynamicSharedMemorySize, attn_smem);

    conv_weights<<<432, 256>>>(qkv_w, proj_w, fc1_w, fc2_w);
    rpb_expand<<<(HEADS * NTOKW * NTOKW + 255) / 256, 256>>>(rpb_table);
    mask_conv<<<(NW_PB * NTOKW * NTOKW) / (4 * 256), 256>>>(attn_mask);

    ln1_shift_win<<<NTOK / 4, 128>>>(x, g1, b1);

    // QKV gemm (M, 288, 96) -> bf16
    mma_gemm<0,1><<<dim3(288 / 96, NTOK / 64), 256>>>(
        p_xwh, p_wh, qkv_b, nullptr, p_qkvh, NTOK, 288, 96);

    attn_kernel<<<NWIN * HEADS, 256, attn_smem>>>();

    // proj gemm + residual + LN2 (fused)
    proj_fused<<<NTOK / 64, 256>>>(
        p_attnh, p_wh + 27648, proj_b, x, g2, b2, p_xres, p_xwh);

    // fc1 + gelu (M, 384, 96) -> bf16 h
    mma_gemm<1,1><<<dim3(HID / 96, NTOK / 64), 256>>>(
        p_xwh, p_wh + 36864, fc1_b, nullptr, p_h, NTOK, HID, 96);

    // fc2 + residual (M, 96, 384) -> fp32 d_out
    mma_gemm<2,0><<<dim3(1, NTOK / 64), 256>>>(
        p_h, p_wh + 73728, fc2_b, p_xres, out, NTOK, 96, HID);
}

// round 16
// speedup vs baseline: 4.1926x; 1.0981x over previous
#include <cuda_runtime.h>
#include <cuda_bf16.h>
#include <cstdint>
#include <math.h>

// ---------------------------------------------------------------------------
// Swin Transformer 3D block — round 16: dataflow surgery.
//   - fused MLP (fc1+gelu+fc2+residual) with h resident in smem (616 MB saved)
//   - QKV multi-N-tile GEMM (A loaded once, 154 MB saved)
//   proj_fused / attention / elementwise identical to round 15.
// ---------------------------------------------------------------------------

#define NTOK   401408
#define CDIM   96
#define NWIN   4096
#define NW_PB  2048
#define NTOKW  98
#define HEADS  3
#define HDIM   32
#define SCALE  0.17677669529663687f
#define HID    384

typedef __nv_bfloat16 bf16;
typedef __nv_bfloat162 bf162;

// -------------------------- device scratch ---------------------------------
__device__ bf16  g_xwh  [(size_t)NTOK * CDIM];
__device__ bf16  g_qkvh [(size_t)NTOK * 288];
__device__ bf16  g_attnh[(size_t)NTOK * CDIM];
__device__ float g_xres [(size_t)NTOK * CDIM];
__device__ bf16  g_rpbh [HEADS * NTOKW * NTOKW];
__device__ bf16  g_maskh[(size_t)NW_PB * NTOKW * NTOKW];
__device__ bf16  g_wh   [110592];

// ---------------------------------------------------------------------------
__global__ void conv_weights(const float* __restrict__ qkv_w,
                             const float* __restrict__ proj_w,
                             const float* __restrict__ fc1_w,
                             const float* __restrict__ fc2_w) {
    int idx = blockIdx.x * 256 + threadIdx.x;       // 110592 total, exact
    const float* src; int off;
    if (idx < 27648)       { src = qkv_w;  off = idx; }
    else if (idx < 36864)  { src = proj_w; off = idx - 27648; }
    else if (idx < 73728)  { src = fc1_w;  off = idx - 36864; }
    else                   { src = fc2_w;  off = idx - 73728; }
    g_wh[idx] = __float2bfloat16(src[off]);
}

// ---------------------------------------------------------------------------
__global__ void rpb_expand(const float* __restrict__ table) {
    int idx = blockIdx.x * 256 + threadIdx.x;
    if (idx >= HEADS * NTOKW * NTOKW) return;
    int head = idx / (NTOKW * NTOKW);
    int r = idx % (NTOKW * NTOKW);
    int i = r / NTOKW, j = r % NTOKW;
    int zdi = i / 49, zhi = (i / 7) % 7, zwi = i % 7;
    int zdj = j / 49, zhj = (j / 7) % 7, zwj = j % 7;
    int ridx = (zdi - zdj + 1) * 169 + (zhi - zhj + 6) * 13 + (zwi - zwj + 6);
    g_rpbh[idx] = __float2bfloat16(table[ridx * 3 + head]);
}

// ---------------------------------------------------------------------------
__global__ void mask_conv(const float* __restrict__ mask) {
    int idx = blockIdx.x * 256 + threadIdx.x;        // 19208 blocks, exact
    float4 m = *(const float4*)&mask[(size_t)idx * 4];
    bf162 lo = __floats2bfloat162_rn(m.x, m.y);
    bf162 hi = __floats2bfloat162_rn(m.z, m.w);
    uint2 pk = make_uint2(*(uint32_t*)&lo, *(uint32_t*)&hi);
    *(uint2*)&g_maskh[(size_t)idx * 4] = pk;
}

// ---------------------------------------------------------------------------
__global__ void ln1_shift_win(const float* __restrict__ x,
                              const float* __restrict__ g,
                              const float* __restrict__ b) {
    int t    = blockIdx.x * 4 + (threadIdx.x >> 5);
    int lane = threadIdx.x & 31;
    int win = t / NTOKW, n = t % NTOKW;
    int bb  = win >> 11;
    int rem = win & 2047;
    int wd = rem >> 8, wh = (rem >> 4) & 15, ww = rem & 15;
    int zd = n / 49, r2 = n % 49, zh = r2 / 7, zw = r2 % 7;
    int sd = (wd * 2 + zd + 1) & 15;
    int sh = wh * 7 + zh + 3; if (sh >= 112) sh -= 112;
    int sw = ww * 7 + zw + 3; if (sw >= 112) sw -= 112;
    const float* px = x + ((((size_t)bb * 16 + sd) * 112 + sh) * 112 + sw) * CDIM;
    float v0 = px[lane], v1 = px[lane + 32], v2 = px[lane + 64];
    float s  = v0 + v1 + v2;
    float ss = v0 * v0 + v1 * v1 + v2 * v2;
    #pragma unroll
    for (int o = 16; o; o >>= 1) {
        s  += __shfl_xor_sync(0xFFFFFFFFu, s, o);
        ss += __shfl_xor_sync(0xFFFFFFFFu, ss, o);
    }
    float mu   = s * (1.0f / 96.0f);
    float var  = ss * (1.0f / 96.0f) - mu * mu;
    float rstd = rsqrtf(var + 1e-5f);
    bf16* po = g_xwh + (size_t)t * CDIM;
    po[lane]      = __float2bfloat16((v0 - mu) * rstd * g[lane]      + b[lane]);
    po[lane + 32] = __float2bfloat16((v1 - mu) * rstd * g[lane + 32] + b[lane + 32]);
    po[lane + 64] = __float2bfloat16((v2 - mu) * rstd * g[lane + 64] + b[lane + 64]);
}

// ---------------------------------------------------------------------------
__device__ __forceinline__ void mma_bf16(float c[4], const uint32_t a[4],
                                         uint32_t b0, uint32_t b1) {
    asm volatile(
        "mma.sync.aligned.m16n8k16.row.col.f32.bf16.bf16.f32 "
        "{%0,%1,%2,%3}, {%4,%5,%6,%7}, {%8,%9}, {%0,%1,%2,%3};"
        : "+f"(c[0]), "+f"(c[1]), "+f"(c[2]), "+f"(c[3])
        : "r"(a[0]), "r"(a[1]), "r"(a[2]), "r"(a[3]), "r"(b0), "r"(b1));
}
__device__ __forceinline__ void ldsm4(uint32_t r[4], uint32_t saddr) {
    asm volatile("ldmatrix.sync.aligned.m8n8.x4.shared.b16 {%0,%1,%2,%3}, [%4];"
        : "=r"(r[0]), "=r"(r[1]), "=r"(r[2]), "=r"(r[3]) : "r"(saddr));
}
__device__ __forceinline__ void cp_async16(uint32_t smem_addr, const void* gptr) {
    asm volatile("cp.async.ca.shared.global [%0], [%1], 16;"
                 :: "r"(smem_addr), "l"(gptr));
}
__device__ __forceinline__ void cp_commit() {
    asm volatile("cp.async.commit_group;" ::: "memory");
}
template<int N>
__device__ __forceinline__ void cp_wait() {
    asm volatile("cp.async.wait_group %0;" :: "n"(N) : "memory");
}

// ---------------------------------------------------------------------------
// QKV GEMM, multi-N-tile: A(64x96) loaded once, 3 N-chunks of 96 streamed.
//   smem (bf16 units): As[0,6656) Bs0[6656,16640) Bs1[16640,26624)
//   ALD=104 (208B row stride, LDSM-legal, conflict-free).
// ---------------------------------------------------------------------------
#define ALD   104
#define AS_SZ (64 * ALD)          // 6656
#define BS_SZ (96 * ALD)          // 9984
#define QKV_SMEM_BYTES ((AS_SZ + 2 * BS_SZ) * 2)   // 53248

__global__ __launch_bounds__(256, 2)
void qkv_gemm(const bf16* __restrict__ A, const bf16* __restrict__ W,
              const float* __restrict__ bias, bf16* __restrict__ C) {
    extern __shared__ __align__(16) bf16 sm[];
    int tid  = threadIdx.x;
    int w    = tid >> 5;
    int lane = tid & 31;
    int g    = lane >> 2;
    int tg   = lane & 3;
    int warpM = w & 1;
    int warpN = w >> 1;
    int m0 = blockIdx.x * 64;

    uint32_t sbase = (uint32_t)__cvta_generic_to_shared(sm);
    uint32_t loff  = (((lane & 15) * ALD) + ((lane >> 4) * 8)) * 2;

    // A: 64 x 12 chunks = 768, 3/thread
    #pragma unroll
    for (int t = 0; t < 3; t++) {
        int idx = tid + t * 256;
        int r = idx / 12, c = idx % 12;
        cp_async16(sbase + (r * ALD + c * 8) * 2,
                   &A[(size_t)(m0 + r) * 96 + c * 8]);
    }
    // W chunk 0: 96 x 12 = 1152
    #pragma unroll
    for (int t = 0; t < 5; t++) {
        int idx = tid + t * 256;
        if (idx < 1152) {
            int r = idx / 12, c = idx % 12;
            cp_async16(sbase + (AS_SZ + r * ALD + c * 8) * 2,
                       &W[(size_t)r * 96 + c * 8]);
        }
    }
    cp_commit();

    for (int nc = 0; nc < 3; nc++) {
        if (nc + 1 < 3) {
            uint32_t sb = sbase + (AS_SZ + ((nc + 1) & 1) * BS_SZ) * 2;
            const bf16* Wn = W + (size_t)(nc + 1) * 96 * 96;
            #pragma unroll
            for (int t = 0; t < 5; t++) {
                int idx = tid + t * 256;
                if (idx < 1152) {
                    int r = idx / 12, c = idx % 12;
                    cp_async16(sb + (r * ALD + c * 8) * 2,
                               &Wn[(size_t)r * 96 + c * 8]);
                }
            }
            cp_commit(); cp_wait<1>();
        } else {
            cp_wait<0>();
        }
        __syncthreads();

        const bf16* Bs = sm + AS_SZ + (nc & 1) * BS_SZ;
        float acc[2][3][4];
        #pragma unroll
        for (int i = 0; i < 2; i++)
            #pragma unroll
            for (int j = 0; j < 3; j++)
                #pragma unroll
                for (int t = 0; t < 4; t++) acc[i][j][t] = 0.0f;

        uint32_t aA = sbase + (warpM * 32 * ALD) * 2 + loff;
        #pragma unroll
        for (int ks = 0; ks < 6; ks++) {
            uint32_t afr[2][4];
            #pragma unroll
            for (int mt = 0; mt < 2; mt++)
                ldsm4(afr[mt], aA + (mt * 16 * ALD + ks * 16) * 2);
            #pragma unroll
            for (int nt = 0; nt < 3; nt++) {
                const uint32_t* bp = (const uint32_t*)
                    (Bs + (warpN * 24 + nt * 8 + g) * ALD + ks * 16 + tg * 2);
                uint32_t b0 = bp[0], b1 = bp[4];
                #pragma unroll
                for (int mt = 0; mt < 2; mt++)
                    mma_bf16(acc[mt][nt], afr[mt], b0, b1);
            }
        }

        #pragma unroll
        for (int mt = 0; mt < 2; mt++) {
            int r0 = m0 + warpM * 32 + mt * 16 + g;
            #pragma unroll
            for (int nt = 0; nt < 3; nt++) {
                int c0 = nc * 96 + warpN * 24 + nt * 8 + tg * 2;
                float bs0 = bias[c0], bs1 = bias[c0 + 1];
                *(bf162*)&C[(size_t)r0 * 288 + c0] =
                    __floats2bfloat162_rn(acc[mt][nt][0] + bs0, acc[mt][nt][1] + bs1);
                *(bf162*)&C[(size_t)(r0 + 8) * 288 + c0] =
                    __floats2bfloat162_rn(acc[mt][nt][2] + bs0, acc[mt][nt][3] + bs1);
            }
        }
        __syncthreads();
    }
}

// ---------------------------------------------------------------------------
// Fused MLP: fc1 + gelu (h in smem) + fc2 + residual -> fp32 out.
//   smem: As[0,6656) Bs0[6656,16640) Bs1[16640,26624) Hs[26624,51712)
//   HLD=392 (784B row stride, LDSM-legal, conflict-free).
// ---------------------------------------------------------------------------
#define HLD   392
#define HS_OFF (AS_SZ + 2 * BS_SZ)       // 26624
#define MLP_SMEM_BYTES ((HS_OFF + 64 * HLD) * 2)   // 103424

__global__ __launch_bounds__(256, 2)
void mlp_fused(const bf16* __restrict__ A, const bf16* __restrict__ W1,
               const float* __restrict__ b1v, const bf16* __restrict__ W2,
               const float* __restrict__ b2v, const float* __restrict__ res,
               float* __restrict__ out) {
    extern __shared__ __align__(16) bf16 sm[];
    bf16* Hs = sm + HS_OFF;
    int tid  = threadIdx.x;
    int w    = tid >> 5;
    int lane = tid & 31;
    int g    = lane >> 2;
    int tg   = lane & 3;
    int warpM = w & 1;
    int warpN = w >> 1;
    int m0 = blockIdx.x * 64;

    uint32_t sbase = (uint32_t)__cvta_generic_to_shared(sm);
    uint32_t loff  = (((lane & 15) * ALD) + ((lane >> 4) * 8)) * 2;
    uint32_t loffH = (((lane & 15) * HLD) + ((lane >> 4) * 8)) * 2;

    // A: 64 x 12 = 768 chunks
    #pragma unroll
    for (int t = 0; t < 3; t++) {
        int idx = tid + t * 256;
        int r = idx / 12, c = idx % 12;
        cp_async16(sbase + (r * ALD + c * 8) * 2,
                   &A[(size_t)(m0 + r) * 96 + c * 8]);
    }
    // W1 chunk 0
    #pragma unroll
    for (int t = 0; t < 5; t++) {
        int idx = tid + t * 256;
        if (idx < 1152) {
            int r = idx / 12, c = idx % 12;
            cp_async16(sbase + (AS_SZ + r * ALD + c * 8) * 2,
                       &W1[(size_t)r * 96 + c * 8]);
        }
    }
    cp_commit();

    // ---------------- phase 1: fc1 + gelu -> Hs ----------------
    for (int nc = 0; nc < 4; nc++) {
        // prefetch: nc<3 -> W1 chunk nc+1 ; nc==3 -> W2 K-chunk 0
        {
            uint32_t sb = sbase + (AS_SZ + ((nc + 1) & 1) * BS_SZ) * 2;
            #pragma unroll
            for (int t = 0; t < 5; t++) {
                int idx = tid + t * 256;
                if (idx < 1152) {
                    int r = idx / 12, c = idx % 12;
                    const bf16* src = (nc < 3)
                        ? &W1[(size_t)(nc + 1) * 96 * 96 + (size_t)r * 96 + c * 8]
                        : &W2[(size_t)r * HID + c * 8];
                    cp_async16(sb + (r * ALD + c * 8) * 2, src);
                }
            }
            cp_commit(); cp_wait<1>();
        }
        __syncthreads();

        const bf16* Bs = sm + AS_SZ + (nc & 1) * BS_SZ;
        float acc[2][3][4];
        #pragma unroll
        for (int i = 0; i < 2; i++)
            #pragma unroll
            for (int j = 0; j < 3; j++)
                #pragma unroll
                for (int t = 0; t < 4; t++) acc[i][j][t] = 0.0f;

        uint32_t aA = sbase + (warpM * 32 * ALD) * 2 + loff;
        #pragma unroll
        for (int ks = 0; ks < 6; ks++) {
            uint32_t afr[2][4];
            #pragma unroll
            for (int mt = 0; mt < 2; mt++)
                ldsm4(afr[mt], aA + (mt * 16 * ALD + ks * 16) * 2);
            #pragma unroll
            for (int nt = 0; nt < 3; nt++) {
                const uint32_t* bp = (const uint32_t*)
                    (Bs + (warpN * 24 + nt * 8 + g) * ALD + ks * 16 + tg * 2);
                uint32_t b0 = bp[0], b1 = bp[4];
                #pragma unroll
                for (int mt = 0; mt < 2; mt++)
                    mma_bf16(acc[mt][nt], afr[mt], b0, b1);
            }
        }
        // gelu -> Hs (cols nc*96 + ...)
        #pragma unroll
        for (int mt = 0; mt < 2; mt++) {
            int rr = warpM * 32 + mt * 16 + g;
            #pragma unroll
            for (int nt = 0; nt < 3; nt++) {
                int c0 = warpN * 24 + nt * 8 + tg * 2;
                float bs0 = b1v[nc * 96 + c0], bs1 = b1v[nc * 96 + c0 + 1];
                float v0 = acc[mt][nt][0] + bs0;
                float v1 = acc[mt][nt][1] + bs1;
                float v2 = acc[mt][nt][2] + bs0;
                float v3 = acc[mt][nt][3] + bs1;
                v0 = 0.5f * v0 * (1.0f + erff(v0 * 0.70710678118654752f));
                v1 = 0.5f * v1 * (1.0f + erff(v1 * 0.70710678118654752f));
                v2 = 0.5f * v2 * (1.0f + erff(v2 * 0.70710678118654752f));
                v3 = 0.5f * v3 * (1.0f + erff(v3 * 0.70710678118654752f));
                *(bf162*)(Hs + rr * HLD + nc * 96 + c0) =
                    __floats2bfloat162_rn(v0, v1);
                *(bf162*)(Hs + (rr + 8) * HLD + nc * 96 + c0) =
                    __floats2bfloat162_rn(v2, v3);
            }
        }
        __syncthreads();
    }

    // ---------------- phase 2: fc2 over K=384 from Hs ----------------
    float acc[2][3][4];
    #pragma unroll
    for (int i = 0; i < 2; i++)
        #pragma unroll
        for (int j = 0; j < 3; j++)
            #pragma unroll
            for (int t = 0; t < 4; t++) acc[i][j][t] = 0.0f;

    for (int kc = 0; kc < 4; kc++) {
        if (kc + 1 < 4) {
            uint32_t sb = sbase + (AS_SZ + ((kc + 1) & 1) * BS_SZ) * 2;
            #pragma unroll
            for (int t = 0; t < 5; t++) {
                int idx = tid + t * 256;
                if (idx < 1152) {
                    int r = idx / 12, c = idx % 12;
                    cp_async16(sb + (r * ALD + c * 8) * 2,
                               &W2[(size_t)r * HID + (kc + 1) * 96 + c * 8]);
                }
            }
            cp_commit(); cp_wait<1>();
        } else {
            cp_wait<0>();
        }
        __syncthreads();

        const bf16* Bs = sm + AS_SZ + (kc & 1) * BS_SZ;
        uint32_t aH = sbase + (HS_OFF + warpM * 32 * HLD) * 2 + loffH;
        #pragma unroll
        for (int ks = 0; ks < 6; ks++) {
            uint32_t afr[2][4];
            #pragma unroll
            for (int mt = 0; mt < 2; mt++)
                ldsm4(afr[mt], aH + (mt * 16 * HLD + kc * 96 + ks * 16) * 2);
            #pragma unroll
            for (int nt = 0; nt < 3; nt++) {
                const uint32_t* bp = (const uint32_t*)
                    (Bs + (warpN * 24 + nt * 8 + g) * ALD + ks * 16 + tg * 2);
                uint32_t b0 = bp[0], b1 = bp[4];
                #pragma unroll
                for (int mt = 0; mt < 2; mt++)
                    mma_bf16(acc[mt][nt], afr[mt], b0, b1);
            }
        }
        __syncthreads();
    }

    // epilogue: bias + residual -> fp32 out
    #pragma unroll
    for (int mt = 0; mt < 2; mt++) {
        int r0 = m0 + warpM * 32 + mt * 16 + g;
        #pragma unroll
        for (int nt = 0; nt < 3; nt++) {
            int c0 = warpN * 24 + nt * 8 + tg * 2;
            float bs0 = b2v[c0], bs1 = b2v[c0 + 1];
            const float* rp0 = &res[(size_t)r0 * 96 + c0];
            const float* rp1 = &res[(size_t)(r0 + 8) * 96 + c0];
            *(float2*)&out[(size_t)r0 * 96 + c0] =
                make_float2(acc[mt][nt][0] + bs0 + rp0[0],
                            acc[mt][nt][1] + bs1 + rp0[1]);
            *(float2*)&out[(size_t)(r0 + 8) * 96 + c0] =
                make_float2(acc[mt][nt][2] + bs0 + rp1[0],
                            acc[mt][nt][3] + bs1 + rp1[1]);
        }
    }
}

// ---------------------------------------------------------------------------
// proj GEMM fused with window-reverse residual + LN2 (as round 15).
// ---------------------------------------------------------------------------
#define GLD  40
#define STG  ((64 + 96) * GLD)

__global__ __launch_bounds__(256, 3)
void proj_fused(const bf16* __restrict__ A, const bf16* __restrict__ B,
                const float* __restrict__ bias,
                const float* __restrict__ x,
                const float* __restrict__ g2v, const float* __restrict__ b2v,
                float* __restrict__ xres, bf16* __restrict__ xwh) {
    __shared__ __align__(16) bf16 sh[2 * STG];
    const int K = 96;

    int tid  = threadIdx.x;
    int w    = tid >> 5;
    int lane = tid & 31;
    int g    = lane >> 2;
    int tg   = lane & 3;
    int warpM = w & 1;
    int warpN = w >> 1;
    int m0 = blockIdx.x * 64;

    int ar = tid >> 2, ac = tid & 3;
    int br0 = tid >> 2, bc0 = tid & 3;
    int bi1 = 256 + tid;
    int br1 = bi1 >> 2, bc1 = bi1 & 3;

    uint32_t sbase = (uint32_t)__cvta_generic_to_shared(sh);
    uint32_t loff = (((lane & 15) * GLD) + ((lane >> 4) * 8)) * 2;

    float acc[2][3][4];
    #pragma unroll
    for (int i = 0; i < 2; i++)
        #pragma unroll
        for (int j = 0; j < 3; j++)
            #pragma unroll
            for (int t = 0; t < 4; t++) acc[i][j][t] = 0.0f;

    {
        cp_async16(sbase + (ar * GLD + ac * 8) * 2,
                   &A[(size_t)(m0 + ar) * K + ac * 8]);
        cp_async16(sbase + ((64 + br0) * GLD + bc0 * 8) * 2,
                   &B[(size_t)br0 * K + bc0 * 8]);
        if (tid < 128)
            cp_async16(sbase + ((64 + br1) * GLD + bc1 * 8) * 2,
                       &B[(size_t)br1 * K + bc1 * 8]);
        cp_commit();
    }

    for (int kc = 0; kc < 3; kc++) {
        if (kc + 1 < 3) {
            int k0 = (kc + 1) << 5;
            uint32_t sb = sbase + ((kc + 1) & 1) * STG * 2;
            cp_async16(sb + (ar * GLD + ac * 8) * 2,
                       &A[(size_t)(m0 + ar) * K + k0 + ac * 8]);
            cp_async16(sb + ((64 + br0) * GLD + bc0 * 8) * 2,
                       &B[(size_t)br0 * K + k0 + bc0 * 8]);
            if (tid < 128)
                cp_async16(sb + ((64 + br1) * GLD + bc1 * 8) * 2,
                           &B[(size_t)br1 * K + k0 + bc1 * 8]);
            cp_commit();
            cp_wait<1>();
        } else {
            cp_wait<0>();
        }
        __syncthreads();

        uint32_t sst = sbase + (kc & 1) * STG * 2;
        const bf16* Bs = sh + (kc & 1) * STG + 64 * GLD;
        uint32_t aA = sst + (warpM * 32 * GLD) * 2 + loff;

        #pragma unroll
        for (int ks = 0; ks < 2; ks++) {
            uint32_t afr[2][4];
            #pragma unroll
            for (int mt = 0; mt < 2; mt++)
                ldsm4(afr[mt], aA + (mt * 16 * GLD + ks * 16) * 2);
            #pragma unroll
            for (int nt = 0; nt < 3; nt++) {
                const uint32_t* bp = (const uint32_t*)
                    (Bs + (warpN * 24 + nt * 8 + g) * GLD + ks * 16 + tg * 2);
                uint32_t b0 = bp[0], b1 = bp[4];
                #pragma unroll
                for (int mt = 0; mt < 2; mt++)
                    mma_bf16(acc[mt][nt], afr[mt], b0, b1);
            }
        }
        __syncthreads();
    }

    float* S = (float*)sh;
    #pragma unroll
    for (int mt = 0; mt < 2; mt++) {
        int rr = warpM * 32 + mt * 16 + g;
        #pragma unroll
        for (int nt = 0; nt < 3; nt++) {
            int c0 = warpN * 24 + nt * 8 + tg * 2;
            float bs0 = bias[c0], bs1 = bias[c0 + 1];
            S[rr * 100 + c0]            = acc[mt][nt][0] + bs0;
            S[rr * 100 + c0 + 1]        = acc[mt][nt][1] + bs1;
            S[(rr + 8) * 100 + c0]      = acc[mt][nt][2] + bs0;
            S[(rr + 8) * 100 + c0 + 1]  = acc[mt][nt][3] + bs1;
        }
    }
    __syncthreads();

    for (int rr = w; rr < 64; rr += 8) {
        int t = m0 + rr;
        int win = t / NTOKW, n = t % NTOKW;
        int bb  = win >> 11;
        int rem = win & 2047;
        int wd = rem >> 8, wh = (rem >> 4) & 15, ww = rem & 15;
        int zd = n / 49, r2 = n % 49, zh = r2 / 7, zw = r2 % 7;
        int sd = (wd * 2 + zd + 1) & 15;
        int shh = wh * 7 + zh + 3; if (shh >= 112) shh -= 112;
        int sww = ww * 7 + zw + 3; if (sww >= 112) sww -= 112;
        size_t sidx = (((size_t)bb * 16 + sd) * 112 + shh) * 112 + sww;
        const float* px = x + sidx * CDIM;
        const float* ps = S + rr * 100;
        float v0 = px[lane]      + ps[lane];
        float v1 = px[lane + 32] + ps[lane + 32];
        float v2 = px[lane + 64] + ps[lane + 64];
        float* pr = xres + sidx * CDIM;
        pr[lane] = v0; pr[lane + 32] = v1; pr[lane + 64] = v2;
        float s  = v0 + v1 + v2;
        float ss = v0 * v0 + v1 * v1 + v2 * v2;
        #pragma unroll
        for (int o = 16; o; o >>= 1) {
            s  += __shfl_xor_sync(0xFFFFFFFFu, s, o);
            ss += __shfl_xor_sync(0xFFFFFFFFu, ss, o);
        }
        float mu   = s * (1.0f / 96.0f);
        float var  = ss * (1.0f / 96.0f) - mu * mu;
        float rstd = rsqrtf(var + 1e-5f);
        bf16* po = xwh + sidx * CDIM;
        po[lane]      = __float2bfloat16((v0 - mu) * rstd * g2v[lane]      + b2v[lane]);
        po[lane + 32] = __float2bfloat16((v1 - mu) * rstd * g2v[lane + 32] + b2v[lane + 32]);
        po[lane + 64] = __float2bfloat16((v2 - mu) * rstd * g2v[lane + 64] + b2v[lane + 64]);
    }
}

// ---------------------------------------------------------------------------
// Tensor-core attention (identical to round 15).
// ---------------------------------------------------------------------------
#define QLD 36
#define KLD 36
#define VLD 116
#define PLD 116
#define SMEM_ATTN_BF 24480
#define SMEM_ATTN_BYTES (SMEM_ATTN_BF * 2 + 112 * 4)

__global__ __launch_bounds__(256)
void attn_kernel() {
    int wh   = blockIdx.x;
    int win  = wh / HEADS, head = wh % HEADS;
    int mw   = win & (NW_PB - 1);
    extern __shared__ bf16 smh[];
    bf16* Qs = smh;
    bf16* Ks = smh + 4032;
    bf16* Vt = smh + 7776;
    bf16* P  = smh + 11488;
    float* sinv = (float*)(smh + SMEM_ATTN_BF);
    int tid  = threadIdx.x;
    int w    = tid >> 5;
    int lane = tid & 31;
    int g    = lane >> 2;
    int tg   = lane & 3;
    uint2 Z2 = make_uint2(0u, 0u);
    bf162 sc2 = __float2bfloat162_rn(SCALE);

    const bf16* qkv = g_qkvh + (size_t)win * NTOKW * 288 + head * HDIM;
    for (int idx = tid; idx < 112 * 8; idx += 256) {
        int n = idx >> 3, d4 = (idx & 7) * 4;
        uint2 val = (n < NTOKW) ? *(const uint2*)(qkv + n * 288 + d4) : Z2;
        bf162 lo = __hmul2(*(bf162*)&val.x, sc2);
        bf162 hi = __hmul2(*(bf162*)&val.y, sc2);
        val.x = *(uint32_t*)&lo; val.y = *(uint32_t*)&hi;
        *(uint2*)(Qs + n * QLD + d4) = val;
    }
    for (int idx = tid; idx < 104 * 8; idx += 256) {
        int n = idx >> 3, d4 = (idx & 7) * 4;
        uint2 val = (n < NTOKW) ? *(const uint2*)(qkv + n * 288 + 96 + d4) : Z2;
        *(uint2*)(Ks + n * KLD + d4) = val;
    }
    for (int idx = tid; idx < 112 * 8; idx += 256) {
        int n = idx >> 3, d4 = (idx & 7) * 4;
        uint2 val = (n < NTOKW) ? *(const uint2*)(qkv + n * 288 + 192 + d4) : Z2;
        bf162 lo = *(bf162*)&val.x;
        bf162 hi = *(bf162*)&val.y;
        Vt[(d4 + 0) * VLD + n] = lo.x;
        Vt[(d4 + 1) * VLD + n] = lo.y;
        Vt[(d4 + 2) * VLD + n] = hi.x;
        Vt[(d4 + 3) * VLD + n] = hi.y;
    }
    {
        uint32_t* Pu = (uint32_t*)P;
        for (int u = tid; u < 112 * 4; u += 256) {
            int i = u >> 2, c = 52 + (u & 3);
            Pu[i * (PLD / 2) + c] = 0;
        }
    }
    __syncthreads();

    int row0 = w * 16;
    if (w < 7) {
        const bf16* mrow = g_maskh + (size_t)mw * 9604;
        const bf16* rrow = g_rpbh + head * 9604;
        int i0 = row0 + g, i1 = row0 + g + 8;
        #pragma unroll
        for (int h2 = 0; h2 < 2; h2++) {
            int ntbase = h2 * 7;
            int NT = h2 ? 6 : 7;
            float acc[7][4];
            for (int t = 0; t < NT; t++) {
                int c0 = (ntbase + t) * 8 + tg * 2;
                float2 b0 = make_float2(0.0f, 0.0f);
                float2 b1 = make_float2(0.0f, 0.0f);
                if (c0 < 98) {
                    if (i0 < NTOKW) {
                        bf162 m = *(const bf162*)(mrow + i0 * 98 + c0);
                        bf162 r = *(const bf162*)(rrow + i0 * 98 + c0);
                        b0 = __bfloat1622float2(__hadd2(m, r));
                    }
                    if (i1 < NTOKW) {
                        bf162 m = *(const bf162*)(mrow + i1 * 98 + c0);
                        bf162 r = *(const bf162*)(rrow + i1 * 98 + c0);
                        b1 = __bfloat1622float2(__hadd2(m, r));
                    }
                }
                acc[t][0] = b0.x; acc[t][1] = b0.y;
                acc[t][2] = b1.x; acc[t][3] = b1.y;
            }
            #pragma unroll
            for (int ks = 0; ks < 2; ks++) {
                uint32_t afr[4];
                const uint32_t* ap = (const uint32_t*)
                    (Qs + (row0 + g) * QLD + ks * 16 + tg * 2);
                afr[0] = ap[0];
                afr[1] = ap[8 * (QLD / 2)];
                afr[2] = ap[4];
                afr[3] = ap[8 * (QLD / 2) + 4];
                for (int t = 0; t < NT; t++) {
                    int n = (ntbase + t) * 8 + g;
                    const uint32_t* bp = (const uint32_t*)
                        (Ks + n * KLD + ks * 16 + tg * 2);
                    mma_bf16(acc[t], afr, bp[0], bp[4]);
                }
            }
            for (int t = 0; t < NT; t++) {
                int c0 = (ntbase + t) * 8 + tg * 2;
                *(bf162*)(P + (row0 + g) * PLD + c0) =
                    __floats2bfloat162_rn(acc[t][0], acc[t][1]);
                *(bf162*)(P + (row0 + g + 8) * PLD + c0) =
                    __floats2bfloat162_rn(acc[t][2], acc[t][3]);
            }
        }
    }
    __syncthreads();

    for (int r = w; r < NTOKW; r += 8) {
        uint32_t* prow = (uint32_t*)(P + r * PLD);
        float s = 0.0f;
        for (int jp = lane; jp < 49; jp += 32) {
            uint32_t v = prow[jp];
            bf162 e = h2exp(*(bf162*)&v);
            prow[jp] = *(uint32_t*)&e;
            float2 f = __bfloat1622float2(e);
            s += f.x + f.y;
        }
        #pragma unroll
        for (int o = 16; o; o >>= 1) s += __shfl_xor_sync(0xFFFFFFFFu, s, o);
        if (lane == 0) sinv[r] = 1.0f / s;
    }
    __syncthreads();

    if (w < 7) {
        float acc[4][4];
        #pragma unroll
        for (int t = 0; t < 4; t++)
            #pragma unroll
            for (int q = 0; q < 4; q++) acc[t][q] = 0.0f;
        #pragma unroll
        for (int ks = 0; ks < 7; ks++) {
            uint32_t afr[4];
            const uint32_t* ap = (const uint32_t*)
                (P + (row0 + g) * PLD + ks * 16 + tg * 2);
            afr[0] = ap[0];
            afr[1] = ap[8 * (PLD / 2)];
            afr[2] = ap[4];
            afr[3] = ap[8 * (PLD / 2) + 4];
            #pragma unroll
            for (int nt = 0; nt < 4; nt++) {
                const uint32_t* bp = (const uint32_t*)
                    (Vt + (nt * 8 + g) * VLD + ks * 16 + tg * 2);
                mma_bf16(acc[nt], afr, bp[0], bp[4]);
            }
        }
        int r = row0 + g;
        float i0 = (r < NTOKW)     ? sinv[r]     : 0.0f;
        float i1 = (r + 8 < NTOKW) ? sinv[r + 8] : 0.0f;
        size_t obase = ((size_t)win * NTOKW + r) * CDIM + head * HDIM;
        #pragma unroll
        for (int nt = 0; nt < 4; nt++) {
            int c0 = nt * 8 + tg * 2;
            if (r < NTOKW)
                *(bf162*)&g_attnh[obase + c0] =
                    __floats2bfloat162_rn(acc[nt][0] * i0, acc[nt][1] * i0);
            if (r + 8 < NTOKW)
                *(bf162*)&g_attnh[obase + 8 * CDIM + c0] =
                    __floats2bfloat162_rn(acc[nt][2] * i1, acc[nt][3] * i1);
        }
    }
}

// ---------------------------------------------------------------------------
extern "C" void kernel_launch(void* const* d_in, const int* in_sizes, int n_in,
                              void* d_out, int out_size) {
    const float* x         = (const float*)d_in[0];
    const float* attn_mask = (const float*)d_in[1];
    const float* g1        = (const float*)d_in[2];
    const float* b1        = (const float*)d_in[3];
    const float* qkv_w     = (const float*)d_in[4];
    const float* qkv_b     = (const float*)d_in[5];
    const float* rpb_table = (const float*)d_in[6];
    const float* proj_w    = (const float*)d_in[7];
    const float* proj_b    = (const float*)d_in[8];
    const float* g2        = (const float*)d_in[9];
    const float* b2        = (const float*)d_in[10];
    const float* fc1_w     = (const float*)d_in[11];
    const float* fc1_b     = (const float*)d_in[12];
    const float* fc2_w     = (const float*)d_in[13];
    const float* fc2_b     = (const float*)d_in[14];
    float* out = (float*)d_out;

    bf16 *p_xwh, *p_qkvh, *p_attnh, *p_wh;
    float *p_xres;
    cudaGetSymbolAddress((void**)&p_xwh,   g_xwh);
    cudaGetSymbolAddress((void**)&p_qkvh,  g_qkvh);
    cudaGetSymbolAddress((void**)&p_attnh, g_attnh);
    cudaGetSymbolAddress((void**)&p_wh,    g_wh);
    cudaGetSymbolAddress((void**)&p_xres,  g_xres);

    cudaFuncSetAttribute(attn_kernel, cudaFuncAttributeMaxDynamicSharedMemorySize,
                         SMEM_ATTN_BYTES);
    cudaFuncSetAttribute(qkv_gemm, cudaFuncAttributeMaxDynamicSharedMemorySize,
                         QKV_SMEM_BYTES);
    cudaFuncSetAttribute(mlp_fused, cudaFuncAttributeMaxDynamicSharedMemorySize,
                         MLP_SMEM_BYTES);

    conv_weights<<<432, 256>>>(qkv_w, proj_w, fc1_w, fc2_w);
    rpb_expand<<<(HEADS * NTOKW * NTOKW + 255) / 256, 256>>>(rpb_table);
    mask_conv<<<(NW_PB * NTOKW * NTOKW) / (4 * 256), 256>>>(attn_mask);

    ln1_shift_win<<<NTOK / 4, 128>>>(x, g1, b1);

    // QKV gemm (A loaded once, 3 N-chunks)
    qkv_gemm<<<NTOK / 64, 256, QKV_SMEM_BYTES>>>(
        p_xwh, p_wh, qkv_b, p_qkvh);

    attn_kernel<<<NWIN * HEADS, 256, SMEM_ATTN_BYTES>>>();

    // proj gemm + residual + LN2 (fused)
    proj_fused<<<NTOK / 64, 256>>>(
        p_attnh, p_wh + 27648, proj_b, x, g2, b2, p_xres, p_xwh);

    // fused MLP: fc1 + gelu + fc2 + residual -> out
    mlp_fused<<<NTOK / 64, 256, MLP_SMEM_BYTES>>>(
        p_xwh, p_wh + 36864, fc1_b, p_wh + 73728, fc2_b, p_xres, out);
}